// round 5
// baseline (speedup 1.0000x reference)
#include <cuda_runtime.h>
#include <cuda_bf16.h>
#include <math.h>
#include <stdint.h>

#define D_DIM 2048
#define N_TOK 4096

// ---------------- device scratch (allocation-free rule) ----------------
__device__ __align__(128) __nv_bfloat16 g_xT_hi[(size_t)D_DIM * N_TOK];
__device__ __align__(128) __nv_bfloat16 g_xT_lo[(size_t)D_DIM * N_TOK];
__device__ __align__(128) __nv_bfloat16 g_x_hi [(size_t)N_TOK * D_DIM];
__device__ __align__(128) __nv_bfloat16 g_x_lo [(size_t)N_TOK * D_DIM];
__device__ __align__(128) __nv_bfloat16 g_wqT_hi[(size_t)D_DIM * D_DIM];
__device__ __align__(128) __nv_bfloat16 g_wqT_lo[(size_t)D_DIM * D_DIM];
__device__ __align__(128) __nv_bfloat16 g_wkT_hi[(size_t)D_DIM * D_DIM];
__device__ __align__(128) __nv_bfloat16 g_wkT_lo[(size_t)D_DIM * D_DIM];
__device__ __align__(128) __nv_bfloat16 g_wv_hi[(size_t)D_DIM * D_DIM];
__device__ __align__(128) __nv_bfloat16 g_wv_lo[(size_t)D_DIM * D_DIM];
__device__ __align__(128) __nv_bfloat16 g_g_hi [(size_t)D_DIM * D_DIM];
__device__ __align__(128) __nv_bfloat16 g_g_lo [(size_t)D_DIM * D_DIM];
__device__ __align__(128) __nv_bfloat16 g_t1_hi[(size_t)D_DIM * D_DIM];
__device__ __align__(128) __nv_bfloat16 g_t1_lo[(size_t)D_DIM * D_DIM];
__device__ __align__(128) __nv_bfloat16 g_t2_hi[(size_t)D_DIM * D_DIM];
__device__ __align__(128) __nv_bfloat16 g_t2_lo[(size_t)D_DIM * D_DIM];
__device__ __align__(128) __nv_bfloat16 g_pT_hi[(size_t)D_DIM * D_DIM];
__device__ __align__(128) __nv_bfloat16 g_pT_lo[(size_t)D_DIM * D_DIM];
__device__ float g_part[16 * D_DIM];
__device__ float g_u[D_DIM], g_w1[D_DIM], g_w2[D_DIM];
__device__ float g_v1[D_DIM], g_v2[D_DIM], g_v3[D_DIM], g_r[D_DIM];
__device__ float g_sc[2];

// ---------------- helpers ----------------
__device__ __forceinline__ uint32_t s2u(const void* p) {
    uint32_t a;
    asm("{ .reg .u64 t; cvta.to.shared.u64 t, %1; cvt.u32.u64 %0, t; }" : "=r"(a) : "l"(p));
    return a;
}
__device__ __forceinline__ void cp16(uint32_t dst, const void* src) {
    asm volatile("cp.async.cg.shared.global [%0], [%1], 16;" :: "r"(dst), "l"(src) : "memory");
}
__device__ __forceinline__ void cp_commit() {
    asm volatile("cp.async.commit_group;" ::: "memory");
}
template<int N>
__device__ __forceinline__ void cp_wait() {
    asm volatile("cp.async.wait_group %0;" :: "n"(N) : "memory");
}
__device__ __forceinline__ void ldsm4(uint32_t* r, uint32_t addr) {
    asm volatile("ldmatrix.sync.aligned.m8n8.x4.shared.b16 {%0,%1,%2,%3}, [%4];"
                 : "=r"(r[0]), "=r"(r[1]), "=r"(r[2]), "=r"(r[3]) : "r"(addr));
}
__device__ __forceinline__ void mma16816(float* d, const uint32_t* a, uint32_t b0, uint32_t b1) {
    asm volatile(
        "mma.sync.aligned.m16n8k16.row.col.f32.bf16.bf16.f32 "
        "{%0,%1,%2,%3}, {%4,%5,%6,%7}, {%8,%9}, {%0,%1,%2,%3};"
        : "+f"(d[0]), "+f"(d[1]), "+f"(d[2]), "+f"(d[3])
        : "r"(a[0]), "r"(a[1]), "r"(a[2]), "r"(a[3]), "r"(b0), "r"(b1));
}

// ---------------- split-bf16 HMMA GEMM body ----------------
// C[m,n] = alpha * sum_k (Ah+Al)[m,k]*(Bh+Bl)[n,k]  (drops lo*lo)
// MODE 0 NORM : Ch/Cl[m*Ntot+n] = split(val)
// MODE 1 SYM  : NORM + mirror Ch/Cl[n*Ntot+m]
// MODE 2 TRANS: Ch/Cl[n*Mtot+m] = split(val + cA[m]cB[n] + cC[m]cD[n])
// MODE 3 FINAL: Cf[m*Ntot+n]    = val*alpha + biascol[n]   (fp32)
#define PLANE_B 10240
#define STAGE_B 40960
static const int SMEM_DYN = 2 * STAGE_B;

template<int MODE>
__device__ __forceinline__ void gemm_body(
    const __nv_bfloat16* __restrict__ Ah, const __nv_bfloat16* __restrict__ Al,
    const __nv_bfloat16* __restrict__ Bh, const __nv_bfloat16* __restrict__ Bl,
    __nv_bfloat16* __restrict__ Ch, __nv_bfloat16* __restrict__ Cl,
    float* __restrict__ Cf,
    const float* __restrict__ cA, const float* __restrict__ cB,
    const float* __restrict__ cC, const float* __restrict__ cD,
    const float* __restrict__ biascol,
    int bm0, int bn0, int Mtot, int Ntot, int Kd, float alpha,
    char* dyn)
{
    const uint32_t su = s2u(dyn);
    const int tid  = threadIdx.x;
    const int wid  = tid >> 5, lane = tid & 31;
    const int wm0  = (wid & 1) * 64;
    const int wn0  = (wid >> 1) * 32;

    // cp.async schedule: 2048 16B transfers / 256 threads = 8 each
    const __nv_bfloat16* gsrc[8];
    uint32_t doff[8];
    #pragma unroll
    for (int i = 0; i < 8; ++i) {
        int idx   = i * 256 + tid;
        int plane = idx >> 9;
        int row   = (idx >> 2) & 127;
        int seg   = idx & 3;
        const __nv_bfloat16* base =
            (plane == 0) ? Ah : (plane == 1) ? Al : (plane == 2) ? Bh : Bl;
        int grow = (plane < 2 ? bm0 : bn0) + row;
        gsrc[i] = base + (size_t)grow * Kd + seg * 8;
        doff[i] = (uint32_t)(plane * PLANE_B + row * 80 + seg * 16);
    }

    const int NC = Kd / 32;
    #pragma unroll
    for (int i = 0; i < 8; ++i) cp16(su + doff[i], gsrc[i]);
    cp_commit();

    float acc[4][4][4];
    #pragma unroll
    for (int im = 0; im < 4; ++im)
        #pragma unroll
        for (int in = 0; in < 4; ++in)
            #pragma unroll
            for (int j = 0; j < 4; ++j) acc[im][in][j] = 0.0f;

    const int a_rl = ((lane >> 3) & 1) * 8 + (lane & 7);
    const int a_ch = ((lane >> 4) & 1) * 16;
    const int b_rl = lane;

    for (int c = 0; c < NC; ++c) {
        cp_wait<0>();
        __syncthreads();
        if (c + 1 < NC) {
            const uint32_t sd = su + ((c + 1) & 1) * STAGE_B;
            const size_t koff = (size_t)(c + 1) * 32;
            #pragma unroll
            for (int i = 0; i < 8; ++i) cp16(sd + doff[i], gsrc[i] + koff);
            cp_commit();
        }
        const uint32_t sb = su + (c & 1) * STAGE_B;
        const uint32_t aBase = sb + (wm0 + a_rl) * 80 + a_ch;
        const uint32_t bBase = sb + (wn0 + b_rl) * 80;

        #pragma unroll
        for (int kk = 0; kk < 2; ++kk) {
            const uint32_t kO = kk * 32;
            uint32_t a[4][4], b0[4], b1[4];
            #pragma unroll
            for (int im = 0; im < 4; ++im)
                ldsm4(a[im], aBase + 0 * PLANE_B + im * (16 * 80) + kO);
            ldsm4(b0, bBase + 3 * PLANE_B + kO);
            ldsm4(b1, bBase + 3 * PLANE_B + kO + 16);
            #pragma unroll
            for (int im = 0; im < 4; ++im)
                #pragma unroll
                for (int in = 0; in < 4; ++in)
                    mma16816(acc[im][in], a[im], b0[in], b1[in]);
            ldsm4(b0, bBase + 2 * PLANE_B + kO);
            ldsm4(b1, bBase + 2 * PLANE_B + kO + 16);
            #pragma unroll
            for (int im = 0; im < 4; ++im)
                #pragma unroll
                for (int in = 0; in < 4; ++in)
                    mma16816(acc[im][in], a[im], b0[in], b1[in]);
            #pragma unroll
            for (int im = 0; im < 4; ++im)
                ldsm4(a[im], aBase + 1 * PLANE_B + im * (16 * 80) + kO);
            #pragma unroll
            for (int im = 0; im < 4; ++im)
                #pragma unroll
                for (int in = 0; in < 4; ++in)
                    mma16816(acc[im][in], a[im], b0[in], b1[in]);
        }
    }

    // ---- epilogue ----
    const int mbase = bm0 + wm0 + (lane >> 2);
    const int nbase = bn0 + wn0 + (lane & 3) * 2;
    #pragma unroll
    for (int im = 0; im < 4; ++im) {
        #pragma unroll
        for (int in = 0; in < 4; ++in) {
            const float* d = acc[im][in];
            const int n0 = nbase + in * 8;
            if (MODE == 3) {
                const int m0 = mbase + im * 16;
                float2 v0, v1;
                v0.x = d[0] * alpha + biascol[n0];
                v0.y = d[1] * alpha + biascol[n0 + 1];
                v1.x = d[2] * alpha + biascol[n0];
                v1.y = d[3] * alpha + biascol[n0 + 1];
                *(float2*)(Cf + (size_t)m0 * Ntot + n0)       = v0;
                *(float2*)(Cf + (size_t)(m0 + 8) * Ntot + n0) = v1;
            } else {
                #pragma unroll
                for (int j = 0; j < 4; ++j) {
                    const int m = mbase + im * 16 + (j >> 1) * 8;
                    const int n = n0 + (j & 1);
                    float v = d[j] * alpha;
                    if (MODE == 2) v += cA[m] * cB[n] + cC[m] * cD[n];
                    __nv_bfloat16 h = __float2bfloat16(v);
                    __nv_bfloat16 l = __float2bfloat16(v - __bfloat162float(h));
                    if (MODE == 0) {
                        size_t o = (size_t)m * Ntot + n;
                        Ch[o] = h; Cl[o] = l;
                    } else if (MODE == 1) {
                        size_t o1 = (size_t)m * Ntot + n;
                        size_t o2 = (size_t)n * Ntot + m;
                        Ch[o1] = h; Cl[o1] = l;
                        Ch[o2] = h; Cl[o2] = l;
                    } else { // TRANS
                        size_t o = (size_t)n * Mtot + m;
                        Ch[o] = h; Cl[o] = l;
                    }
                }
            }
        }
    }
}

template<int MODE>
__global__ void __launch_bounds__(256, 2) gemm_mma(
    const __nv_bfloat16* __restrict__ Ah, const __nv_bfloat16* __restrict__ Al,
    const __nv_bfloat16* __restrict__ Bh, const __nv_bfloat16* __restrict__ Bl,
    __nv_bfloat16* __restrict__ Ch, __nv_bfloat16* __restrict__ Cl,
    float* __restrict__ Cf,
    const float* __restrict__ cA, const float* __restrict__ cB,
    const float* __restrict__ cC, const float* __restrict__ cD,
    const float* __restrict__ biascol,
    int Mtot, int Ntot, int Kd, float alpha)
{
    extern __shared__ char dyn[];
    gemm_body<MODE>(Ah, Al, Bh, Bl, Ch, Cl, Cf, cA, cB, cC, cD, biascol,
                    blockIdx.y * 128, blockIdx.x * 128, Mtot, Ntot, Kd, alpha, dyn);
}

// Fused: blocks [0,136) -> G = xT xT^T (symmetric, upper-tri tiles, K=N_TOK)
//        blocks [136,392) -> T1 = wqT wkT^T (K=D_DIM)
// G blocks come first so the long tiles occupy wave 1; T1 fills idle SMs.
__global__ void __launch_bounds__(256, 2) fused_g_t1(
    const __nv_bfloat16* __restrict__ xTh, const __nv_bfloat16* __restrict__ xTl,
    __nv_bfloat16* __restrict__ gh, __nv_bfloat16* __restrict__ gl,
    const __nv_bfloat16* __restrict__ wqTh, const __nv_bfloat16* __restrict__ wqTl,
    const __nv_bfloat16* __restrict__ wkTh, const __nv_bfloat16* __restrict__ wkTl,
    __nv_bfloat16* __restrict__ t1h, __nv_bfloat16* __restrict__ t1l)
{
    extern __shared__ char dyn[];
    if (blockIdx.x < 136) {
        int idx = blockIdx.x, by = 0;
        while (idx >= 16 - by) { idx -= 16 - by; ++by; }
        const int bxt = by + idx;
        gemm_body<1>(xTh, xTl, xTh, xTl, gh, gl, nullptr,
                     nullptr, nullptr, nullptr, nullptr, nullptr,
                     by * 128, bxt * 128, D_DIM, D_DIM, N_TOK, 1.0f, dyn);
    } else {
        const int idx = blockIdx.x - 136;
        gemm_body<0>(wqTh, wqTl, wkTh, wkTl, t1h, t1l, nullptr,
                     nullptr, nullptr, nullptr, nullptr, nullptr,
                     (idx >> 4) * 128, (idx & 15) * 128, D_DIM, D_DIM, D_DIM, 1.0f, dyn);
    }
}

// ---------------- preprocessing ----------------
// One pass over x: straight split AND transposed split.
__global__ void prep_x(const float* __restrict__ in,
                       __nv_bfloat16* __restrict__ hi, __nv_bfloat16* __restrict__ lo,
                       __nv_bfloat16* __restrict__ thi, __nv_bfloat16* __restrict__ tlo)
{
    __shared__ float t[32][33];
    int bx = blockIdx.x * 32, by = blockIdx.y * 32;
    int tx = threadIdx.x, ty = threadIdx.y;  // 32 x 8
    #pragma unroll
    for (int j = 0; j < 32; j += 8) {
        size_t gi = (size_t)(by + ty + j) * D_DIM + bx + tx;
        float v = in[gi];
        t[ty + j][tx] = v;
        __nv_bfloat16 h = __float2bfloat16(v);
        hi[gi] = h;
        lo[gi] = __float2bfloat16(v - __bfloat162float(h));
    }
    __syncthreads();
    #pragma unroll
    for (int j = 0; j < 32; j += 8) {
        float v = t[tx][ty + j];
        size_t o = (size_t)(bx + ty + j) * N_TOK + by + tx;
        __nv_bfloat16 h = __float2bfloat16(v);
        thi[o] = h;
        tlo[o] = __float2bfloat16(v - __bfloat162float(h));
    }
}

// Batched weight prep: z=0 transpose-split Wq, z=1 transpose-split Wk, z=2 split Wv.
__global__ void prep_w(const float* __restrict__ Wq, __nv_bfloat16* __restrict__ wqTh, __nv_bfloat16* __restrict__ wqTl,
                       const float* __restrict__ Wk, __nv_bfloat16* __restrict__ wkTh, __nv_bfloat16* __restrict__ wkTl,
                       const float* __restrict__ Wv, __nv_bfloat16* __restrict__ wvh,  __nv_bfloat16* __restrict__ wvl)
{
    __shared__ float t[32][33];
    int bx = blockIdx.x * 32, by = blockIdx.y * 32;
    int tx = threadIdx.x, ty = threadIdx.y;
    const int z = blockIdx.z;
    const float* in = (z == 0) ? Wq : (z == 1) ? Wk : Wv;
    if (z == 2) {
        #pragma unroll
        for (int j = 0; j < 32; j += 8) {
            size_t gi = (size_t)(by + ty + j) * D_DIM + bx + tx;
            float v = in[gi];
            __nv_bfloat16 h = __float2bfloat16(v);
            wvh[gi] = h;
            wvl[gi] = __float2bfloat16(v - __bfloat162float(h));
        }
        return;
    }
    __nv_bfloat16* hi = (z == 0) ? wqTh : wkTh;
    __nv_bfloat16* lo = (z == 0) ? wqTl : wkTl;
    #pragma unroll
    for (int j = 0; j < 32; j += 8)
        t[ty + j][tx] = in[(size_t)(by + ty + j) * D_DIM + bx + tx];
    __syncthreads();
    #pragma unroll
    for (int j = 0; j < 32; j += 8) {
        float v = t[tx][ty + j];
        size_t o = (size_t)(bx + ty + j) * D_DIM + by + tx;
        __nv_bfloat16 h = __float2bfloat16(v);
        hi[o] = h;
        lo[o] = __float2bfloat16(v - __bfloat162float(h));
    }
}

// ---------------- small vector ops (bias corrections, exact fp32) ----------------
__global__ void wpart_kernel(const float* __restrict__ W, const float* __restrict__ vec,
                             float* __restrict__ part, int R)
{
    int d = blockIdx.x * blockDim.x + threadIdx.x;
    int c = blockIdx.y;
    int chunk = R / 16;
    float s = 0.0f;
    for (int r = c * chunk; r < (c + 1) * chunk; ++r)
        s = fmaf(vec ? vec[r] : 1.0f, W[(size_t)r * D_DIM + d], s);
    part[c * D_DIM + d] = s;
}
__global__ void wreduce_kernel(const float* __restrict__ part, float* __restrict__ y, float alpha)
{
    int d = blockIdx.x * blockDim.x + threadIdx.x;
    float s = 0.0f;
    #pragma unroll
    for (int c = 0; c < 16; ++c) s += part[c * D_DIM + d];
    y[d] = s * alpha;
}
__global__ void rowmv_kernel(const float* __restrict__ W, const float* __restrict__ v,
                             const float* __restrict__ add, float addscale,
                             float* __restrict__ y)
{
    int i = (blockIdx.x * blockDim.x + threadIdx.x) >> 5;
    int lane = threadIdx.x & 31;
    if (i >= D_DIM) return;
    float s = 0.0f;
    for (int j = lane; j < D_DIM; j += 32) s = fmaf(W[(size_t)i * D_DIM + j], v[j], s);
    #pragma unroll
    for (int o = 16; o; o >>= 1) s += __shfl_xor_sync(0xFFFFFFFFu, s, o);
    if (lane == 0) y[i] = s + (add ? addscale * add[i] : 0.0f);
}
__global__ void splitmv_kernel(const __nv_bfloat16* __restrict__ hi,
                               const __nv_bfloat16* __restrict__ lo,
                               const float* __restrict__ v,
                               float* __restrict__ y, float alpha)
{
    int i = (blockIdx.x * blockDim.x + threadIdx.x) >> 5;
    int lane = threadIdx.x & 31;
    if (i >= D_DIM) return;
    float s = 0.0f;
    for (int j = lane; j < D_DIM; j += 32)
        s = fmaf(__bfloat162float(hi[(size_t)i * D_DIM + j]) +
                 __bfloat162float(lo[(size_t)i * D_DIM + j]), v[j], s);
    #pragma unroll
    for (int o = 16; o; o >>= 1) s += __shfl_xor_sync(0xFFFFFFFFu, s, o);
    if (lane == 0) y[i] = s * alpha;
}
__global__ void dot2_kernel(const float* a, const float* b,
                            const float* c, const float* d, float* sc)
{
    __shared__ float red[256];
    int tid = threadIdx.x;
    float s = 0.0f;
    if (blockIdx.x == 0)
        for (int i = tid; i < D_DIM; i += 256) s = fmaf(a[i], b[i], s);
    else
        for (int i = tid; i < D_DIM; i += 256) s = fmaf(c[i], d[i], s);
    red[tid] = s;
    __syncthreads();
    for (int o = 128; o; o >>= 1) { if (tid < o) red[tid] += red[tid + o]; __syncthreads(); }
    if (tid == 0) sc[blockIdx.x] = red[0];
}
__global__ void r_kernel(const float* __restrict__ Wv, const float* __restrict__ w2,
                         const float* __restrict__ bv, const float* __restrict__ v3,
                         const float* __restrict__ sc, float* __restrict__ r, float s)
{
    int i = (blockIdx.x * blockDim.x + threadIdx.x) >> 5;
    int lane = threadIdx.x & 31;
    if (i >= D_DIM) return;
    float acc = 0.0f;
    for (int j = lane; j < D_DIM; j += 32) acc = fmaf(Wv[(size_t)i * D_DIM + j], w2[j], acc);
    #pragma unroll
    for (int o = 16; o; o >>= 1) acc += __shfl_xor_sync(0xFFFFFFFFu, acc, o);
    if (lane == 0) r[i] = s * (acc + bv[i] * sc[0] + v3[i] * sc[1]);
}

// ---------------- launcher ----------------
extern "C" void kernel_launch(void* const* d_in, const int* in_sizes, int n_in,
                              void* d_out, int out_size)
{
    const float* x  = (const float*)d_in[0];
    const float* Wq = (const float*)d_in[1];
    const float* bq = (const float*)d_in[2];
    const float* Wk = (const float*)d_in[3];
    const float* bk = (const float*)d_in[4];
    const float* Wv = (const float*)d_in[5];
    const float* bv = (const float*)d_in[6];
    float* out = (float*)d_out;

    __nv_bfloat16 *xT_hi, *xT_lo, *x_hi, *x_lo, *wqT_hi, *wqT_lo, *wkT_hi, *wkT_lo;
    __nv_bfloat16 *wv_hi, *wv_lo, *gh, *gl, *t1h, *t1l, *t2h, *t2l, *pTh, *pTl;
    float *part, *u, *w1, *w2, *v1, *v2, *v3, *r, *sc;
    cudaGetSymbolAddress((void**)&xT_hi, g_xT_hi);  cudaGetSymbolAddress((void**)&xT_lo, g_xT_lo);
    cudaGetSymbolAddress((void**)&x_hi, g_x_hi);    cudaGetSymbolAddress((void**)&x_lo, g_x_lo);
    cudaGetSymbolAddress((void**)&wqT_hi, g_wqT_hi);cudaGetSymbolAddress((void**)&wqT_lo, g_wqT_lo);
    cudaGetSymbolAddress((void**)&wkT_hi, g_wkT_hi);cudaGetSymbolAddress((void**)&wkT_lo, g_wkT_lo);
    cudaGetSymbolAddress((void**)&wv_hi, g_wv_hi);  cudaGetSymbolAddress((void**)&wv_lo, g_wv_lo);
    cudaGetSymbolAddress((void**)&gh, g_g_hi);      cudaGetSymbolAddress((void**)&gl, g_g_lo);
    cudaGetSymbolAddress((void**)&t1h, g_t1_hi);    cudaGetSymbolAddress((void**)&t1l, g_t1_lo);
    cudaGetSymbolAddress((void**)&t2h, g_t2_hi);    cudaGetSymbolAddress((void**)&t2l, g_t2_lo);
    cudaGetSymbolAddress((void**)&pTh, g_pT_hi);    cudaGetSymbolAddress((void**)&pTl, g_pT_lo);
    cudaGetSymbolAddress((void**)&part, g_part);
    cudaGetSymbolAddress((void**)&u, g_u);   cudaGetSymbolAddress((void**)&w1, g_w1);
    cudaGetSymbolAddress((void**)&w2, g_w2); cudaGetSymbolAddress((void**)&v1, g_v1);
    cudaGetSymbolAddress((void**)&v2, g_v2); cudaGetSymbolAddress((void**)&v3, g_v3);
    cudaGetSymbolAddress((void**)&r, g_r);   cudaGetSymbolAddress((void**)&sc, g_sc);

    cudaFuncSetAttribute(gemm_mma<0>, cudaFuncAttributeMaxDynamicSharedMemorySize, SMEM_DYN);
    cudaFuncSetAttribute(gemm_mma<2>, cudaFuncAttributeMaxDynamicSharedMemorySize, SMEM_DYN);
    cudaFuncSetAttribute(gemm_mma<3>, cudaFuncAttributeMaxDynamicSharedMemorySize, SMEM_DYN);
    cudaFuncSetAttribute(fused_g_t1,  cudaFuncAttributeMaxDynamicSharedMemorySize, SMEM_DYN);

    const float s = 1.0f / sqrtf((float)D_DIM);
    dim3 blk(256);
    dim3 tblk(32, 8);

    // ---- operand preparation ----
    prep_x<<<dim3(D_DIM / 32, N_TOK / 32), tblk>>>(x, x_hi, x_lo, xT_hi, xT_lo);
    prep_w<<<dim3(D_DIM / 32, D_DIM / 32, 3), tblk>>>(Wq, wqT_hi, wqT_lo,
                                                      Wk, wkT_hi, wkT_lo,
                                                      Wv, wv_hi, wv_lo);

    // ---- bias-correction vectors (exact fp32; zeros in this dataset) ----
    wpart_kernel<<<dim3(D_DIM / 256, 16), 256>>>(x, nullptr, part, N_TOK);
    wreduce_kernel<<<D_DIM / 256, 256>>>(part, u, 1.0f);                      // u = x^T 1
    wpart_kernel<<<dim3(D_DIM / 256, 16), 256>>>(Wk, bq, part, D_DIM);
    wreduce_kernel<<<D_DIM / 256, 256>>>(part, w1, 1.0f);                     // w1 = Wk^T bq
    dot2_kernel<<<2, 256>>>(u, w1, bk, bq, sc);                               // sc0=u.w1 sc1=bk.bq
    wpart_kernel<<<dim3(D_DIM / 256, 16), 256>>>(Wq, bk, part, D_DIM);
    wreduce_kernel<<<D_DIM / 256, 256>>>(part, v2, s);                        // v2 = s*Wq^T bk
    rowmv_kernel<<<D_DIM / 8, 256>>>(Wv, u, bv, (float)N_TOK, v3);            // v3 = Wv u + N bv

    // ---- GEMM chain ----
    // G = x^T x (136 symmetric tiles)  ||  T1 = Wq^T Wk (256 tiles), one launch
    fused_g_t1<<<392, blk, SMEM_DYN>>>(xT_hi, xT_lo, gh, gl,
                                       wqT_hi, wqT_lo, wkT_hi, wkT_lo, t1h, t1l);
    splitmv_kernel<<<D_DIM / 8, 256>>>(gh, gl, w1, w2, 1.0f);                 // w2 = G w1
    splitmv_kernel<<<D_DIM / 8, 256>>>(t1h, t1l, u, v1, s);                   // v1 = s*T1 u
    r_kernel<<<D_DIM / 8, 256>>>(Wv, w2, bv, v3, sc, r, s);                   // r
    // T2 = T1 G  (G symmetric -> K-major rows of G)
    gemm_mma<0><<<dim3(16, 16), blk, SMEM_DYN>>>(t1h, t1l, gh, gl,
        t2h, t2l, nullptr, nullptr, nullptr, nullptr, nullptr, nullptr,
        D_DIM, D_DIM, D_DIM, 1.0f);
    // P = s*T2 Wv^T + v1 bv^T + v2 v3^T  (store transposed-split pT)
    gemm_mma<2><<<dim3(16, 16), blk, SMEM_DYN>>>(t2h, t2l, wv_hi, wv_lo,
        pTh, pTl, nullptr, v1, bv, v2, v3, nullptr,
        D_DIM, D_DIM, D_DIM, s);
    // out = x P + 1 r^T
    gemm_mma<3><<<dim3(16, 32), blk, SMEM_DYN>>>(x_hi, x_lo, pTh, pTl,
        nullptr, nullptr, out, nullptr, nullptr, nullptr, nullptr, r,
        N_TOK, D_DIM, D_DIM, 1.0f);
}

// round 6
// speedup vs baseline: 1.0618x; 1.0618x over previous
#include <cuda_runtime.h>
#include <cuda_bf16.h>
#include <math.h>
#include <stdint.h>

#define D_DIM 2048
#define N_TOK 4096

// ---------------- device scratch (allocation-free rule) ----------------
__device__ __align__(128) __nv_bfloat16 g_xT_hi[(size_t)D_DIM * N_TOK];
__device__ __align__(128) __nv_bfloat16 g_xT_lo[(size_t)D_DIM * N_TOK];
__device__ __align__(128) __nv_bfloat16 g_x_hi [(size_t)N_TOK * D_DIM];
__device__ __align__(128) __nv_bfloat16 g_x_lo [(size_t)N_TOK * D_DIM];
__device__ __align__(128) __nv_bfloat16 g_wqT_hi[(size_t)D_DIM * D_DIM];
__device__ __align__(128) __nv_bfloat16 g_wqT_lo[(size_t)D_DIM * D_DIM];
__device__ __align__(128) __nv_bfloat16 g_wkT_hi[(size_t)D_DIM * D_DIM];
__device__ __align__(128) __nv_bfloat16 g_wkT_lo[(size_t)D_DIM * D_DIM];
__device__ __align__(128) __nv_bfloat16 g_wv_hi[(size_t)D_DIM * D_DIM];
__device__ __align__(128) __nv_bfloat16 g_wv_lo[(size_t)D_DIM * D_DIM];
__device__ __align__(128) __nv_bfloat16 g_g_hi [(size_t)D_DIM * D_DIM];
__device__ __align__(128) __nv_bfloat16 g_g_lo [(size_t)D_DIM * D_DIM];
__device__ __align__(128) __nv_bfloat16 g_t1_hi[(size_t)D_DIM * D_DIM];
__device__ __align__(128) __nv_bfloat16 g_t1_lo[(size_t)D_DIM * D_DIM];
__device__ __align__(128) __nv_bfloat16 g_t2_hi[(size_t)D_DIM * D_DIM];
__device__ __align__(128) __nv_bfloat16 g_t2_lo[(size_t)D_DIM * D_DIM];
__device__ __align__(128) __nv_bfloat16 g_pT_hi[(size_t)D_DIM * D_DIM];
__device__ __align__(128) __nv_bfloat16 g_pT_lo[(size_t)D_DIM * D_DIM];
__device__ float g_part[48 * D_DIM];
__device__ float g_u[D_DIM], g_w1[D_DIM], g_w2[D_DIM];
__device__ float g_v1[D_DIM], g_v2[D_DIM], g_v3[D_DIM], g_r[D_DIM];
__device__ float g_sc[2];

// ---------------- helpers ----------------
__device__ __forceinline__ uint32_t s2u(const void* p) {
    uint32_t a;
    asm("{ .reg .u64 t; cvta.to.shared.u64 t, %1; cvt.u32.u64 %0, t; }" : "=r"(a) : "l"(p));
    return a;
}
__device__ __forceinline__ void cp16(uint32_t dst, const void* src) {
    asm volatile("cp.async.cg.shared.global [%0], [%1], 16;" :: "r"(dst), "l"(src) : "memory");
}
__device__ __forceinline__ void cp_commit() {
    asm volatile("cp.async.commit_group;" ::: "memory");
}
template<int N>
__device__ __forceinline__ void cp_wait() {
    asm volatile("cp.async.wait_group %0;" :: "n"(N) : "memory");
}
__device__ __forceinline__ void ldsm4(uint32_t* r, uint32_t addr) {
    asm volatile("ldmatrix.sync.aligned.m8n8.x4.shared.b16 {%0,%1,%2,%3}, [%4];"
                 : "=r"(r[0]), "=r"(r[1]), "=r"(r[2]), "=r"(r[3]) : "r"(addr));
}
__device__ __forceinline__ void mma16816(float* d, const uint32_t* a, uint32_t b0, uint32_t b1) {
    asm volatile(
        "mma.sync.aligned.m16n8k16.row.col.f32.bf16.bf16.f32 "
        "{%0,%1,%2,%3}, {%4,%5,%6,%7}, {%8,%9}, {%0,%1,%2,%3};"
        : "+f"(d[0]), "+f"(d[1]), "+f"(d[2]), "+f"(d[3])
        : "r"(a[0]), "r"(a[1]), "r"(a[2]), "r"(a[3]), "r"(b0), "r"(b1));
}

// ---------------- split-bf16 HMMA GEMM body ----------------
// C[m,n] = alpha * sum_k (Ah+Al)[m,k]*(Bh+Bl)[n,k]  (drops lo*lo)
// MODE 0 NORM : Ch/Cl[m*Ntot+n] = split(val)
// MODE 1 SYM  : NORM + mirror Ch/Cl[n*Ntot+m]
// MODE 2 TRANS: Ch/Cl[n*Mtot+m] = split(val + cA[m]cB[n] + cC[m]cD[n])
// MODE 3 FINAL: Cf[m*Ntot+n]    = val*alpha + biascol[n]   (fp32)
#define PLANE_B 10240
#define STAGE_B 40960
static const int SMEM_DYN = 2 * STAGE_B;

template<int MODE>
__device__ __forceinline__ void gemm_body(
    const __nv_bfloat16* __restrict__ Ah, const __nv_bfloat16* __restrict__ Al,
    const __nv_bfloat16* __restrict__ Bh, const __nv_bfloat16* __restrict__ Bl,
    __nv_bfloat16* __restrict__ Ch, __nv_bfloat16* __restrict__ Cl,
    float* __restrict__ Cf,
    const float* __restrict__ cA, const float* __restrict__ cB,
    const float* __restrict__ cC, const float* __restrict__ cD,
    const float* __restrict__ biascol,
    int bm0, int bn0, int Mtot, int Ntot, int Kd, float alpha,
    char* dyn)
{
    const uint32_t su = s2u(dyn);
    const int tid  = threadIdx.x;
    const int wid  = tid >> 5, lane = tid & 31;
    const int wm0  = (wid & 1) * 64;
    const int wn0  = (wid >> 1) * 32;

    // cp.async schedule: 2048 16B transfers / 256 threads = 8 each
    const __nv_bfloat16* gsrc[8];
    uint32_t doff[8];
    #pragma unroll
    for (int i = 0; i < 8; ++i) {
        int idx   = i * 256 + tid;
        int plane = idx >> 9;
        int row   = (idx >> 2) & 127;
        int seg   = idx & 3;
        const __nv_bfloat16* base =
            (plane == 0) ? Ah : (plane == 1) ? Al : (plane == 2) ? Bh : Bl;
        int grow = (plane < 2 ? bm0 : bn0) + row;
        gsrc[i] = base + (size_t)grow * Kd + seg * 8;
        doff[i] = (uint32_t)(plane * PLANE_B + row * 80 + seg * 16);
    }

    const int NC = Kd / 32;
    #pragma unroll
    for (int i = 0; i < 8; ++i) cp16(su + doff[i], gsrc[i]);
    cp_commit();

    float acc[4][4][4];
    #pragma unroll
    for (int im = 0; im < 4; ++im)
        #pragma unroll
        for (int in = 0; in < 4; ++in)
            #pragma unroll
            for (int j = 0; j < 4; ++j) acc[im][in][j] = 0.0f;

    const int a_rl = ((lane >> 3) & 1) * 8 + (lane & 7);
    const int a_ch = ((lane >> 4) & 1) * 16;
    const int b_rl = lane;

    for (int c = 0; c < NC; ++c) {
        cp_wait<0>();
        __syncthreads();
        if (c + 1 < NC) {
            const uint32_t sd = su + ((c + 1) & 1) * STAGE_B;
            const size_t koff = (size_t)(c + 1) * 32;
            #pragma unroll
            for (int i = 0; i < 8; ++i) cp16(sd + doff[i], gsrc[i] + koff);
            cp_commit();
        }
        const uint32_t sb = su + (c & 1) * STAGE_B;
        const uint32_t aBase = sb + (wm0 + a_rl) * 80 + a_ch;
        const uint32_t bBase = sb + (wn0 + b_rl) * 80;

        #pragma unroll
        for (int kk = 0; kk < 2; ++kk) {
            const uint32_t kO = kk * 32;
            uint32_t a[4][4], b0[4], b1[4];
            #pragma unroll
            for (int im = 0; im < 4; ++im)
                ldsm4(a[im], aBase + 0 * PLANE_B + im * (16 * 80) + kO);
            ldsm4(b0, bBase + 3 * PLANE_B + kO);
            ldsm4(b1, bBase + 3 * PLANE_B + kO + 16);
            #pragma unroll
            for (int im = 0; im < 4; ++im)
                #pragma unroll
                for (int in = 0; in < 4; ++in)
                    mma16816(acc[im][in], a[im], b0[in], b1[in]);
            ldsm4(b0, bBase + 2 * PLANE_B + kO);
            ldsm4(b1, bBase + 2 * PLANE_B + kO + 16);
            #pragma unroll
            for (int im = 0; im < 4; ++im)
                #pragma unroll
                for (int in = 0; in < 4; ++in)
                    mma16816(acc[im][in], a[im], b0[in], b1[in]);
            #pragma unroll
            for (int im = 0; im < 4; ++im)
                ldsm4(a[im], aBase + 1 * PLANE_B + im * (16 * 80) + kO);
            #pragma unroll
            for (int im = 0; im < 4; ++im)
                #pragma unroll
                for (int in = 0; in < 4; ++in)
                    mma16816(acc[im][in], a[im], b0[in], b1[in]);
        }
    }

    // ---- epilogue ----
    const int mbase = bm0 + wm0 + (lane >> 2);
    const int nbase = bn0 + wn0 + (lane & 3) * 2;
    #pragma unroll
    for (int im = 0; im < 4; ++im) {
        #pragma unroll
        for (int in = 0; in < 4; ++in) {
            const float* d = acc[im][in];
            const int n0 = nbase + in * 8;
            if (MODE == 3) {
                const int m0 = mbase + im * 16;
                float2 v0, v1;
                v0.x = d[0] * alpha + biascol[n0];
                v0.y = d[1] * alpha + biascol[n0 + 1];
                v1.x = d[2] * alpha + biascol[n0];
                v1.y = d[3] * alpha + biascol[n0 + 1];
                *(float2*)(Cf + (size_t)m0 * Ntot + n0)       = v0;
                *(float2*)(Cf + (size_t)(m0 + 8) * Ntot + n0) = v1;
            } else {
                #pragma unroll
                for (int j = 0; j < 4; ++j) {
                    const int m = mbase + im * 16 + (j >> 1) * 8;
                    const int n = n0 + (j & 1);
                    float v = d[j] * alpha;
                    if (MODE == 2) v += cA[m] * cB[n] + cC[m] * cD[n];
                    __nv_bfloat16 h = __float2bfloat16(v);
                    __nv_bfloat16 l = __float2bfloat16(v - __bfloat162float(h));
                    if (MODE == 0) {
                        size_t o = (size_t)m * Ntot + n;
                        Ch[o] = h; Cl[o] = l;
                    } else if (MODE == 1) {
                        size_t o1 = (size_t)m * Ntot + n;
                        size_t o2 = (size_t)n * Ntot + m;
                        Ch[o1] = h; Cl[o1] = l;
                        Ch[o2] = h; Cl[o2] = l;
                    } else { // TRANS
                        size_t o = (size_t)n * Mtot + m;
                        Ch[o] = h; Cl[o] = l;
                    }
                }
            }
        }
    }
}

template<int MODE>
__global__ void __launch_bounds__(256, 2) gemm_mma(
    const __nv_bfloat16* __restrict__ Ah, const __nv_bfloat16* __restrict__ Al,
    const __nv_bfloat16* __restrict__ Bh, const __nv_bfloat16* __restrict__ Bl,
    __nv_bfloat16* __restrict__ Ch, __nv_bfloat16* __restrict__ Cl,
    float* __restrict__ Cf,
    const float* __restrict__ cA, const float* __restrict__ cB,
    const float* __restrict__ cC, const float* __restrict__ cD,
    const float* __restrict__ biascol,
    int Mtot, int Ntot, int Kd, float alpha)
{
    extern __shared__ char dyn[];
    gemm_body<MODE>(Ah, Al, Bh, Bl, Ch, Cl, Cf, cA, cB, cC, cD, biascol,
                    blockIdx.y * 128, blockIdx.x * 128, Mtot, Ntot, Kd, alpha, dyn);
}

// Symmetric GEMM: 1D grid of 136 upper-triangular tiles, mirror store.
__global__ void __launch_bounds__(256, 2) gemm_sym(
    const __nv_bfloat16* __restrict__ Ah, const __nv_bfloat16* __restrict__ Al,
    __nv_bfloat16* __restrict__ Ch, __nv_bfloat16* __restrict__ Cl,
    int Ntot, int Kd)
{
    extern __shared__ char dyn[];
    int idx = blockIdx.x, by = 0;
    while (idx >= 16 - by) { idx -= 16 - by; ++by; }
    const int bxt = by + idx;
    gemm_body<1>(Ah, Al, Ah, Al, Ch, Cl, nullptr,
                 nullptr, nullptr, nullptr, nullptr, nullptr,
                 by * 128, bxt * 128, Ntot, Ntot, Kd, 1.0f, dyn);
}

// ---------------- preprocessing ----------------
// One pass over x: straight split AND transposed split.
__global__ void prep_x(const float* __restrict__ in,
                       __nv_bfloat16* __restrict__ hi, __nv_bfloat16* __restrict__ lo,
                       __nv_bfloat16* __restrict__ thi, __nv_bfloat16* __restrict__ tlo)
{
    __shared__ float t[32][33];
    int bx = blockIdx.x * 32, by = blockIdx.y * 32;
    int tx = threadIdx.x, ty = threadIdx.y;  // 32 x 8
    #pragma unroll
    for (int j = 0; j < 32; j += 8) {
        size_t gi = (size_t)(by + ty + j) * D_DIM + bx + tx;
        float v = in[gi];
        t[ty + j][tx] = v;
        __nv_bfloat16 h = __float2bfloat16(v);
        hi[gi] = h;
        lo[gi] = __float2bfloat16(v - __bfloat162float(h));
    }
    __syncthreads();
    #pragma unroll
    for (int j = 0; j < 32; j += 8) {
        float v = t[tx][ty + j];
        size_t o = (size_t)(bx + ty + j) * N_TOK + by + tx;
        __nv_bfloat16 h = __float2bfloat16(v);
        thi[o] = h;
        tlo[o] = __float2bfloat16(v - __bfloat162float(h));
    }
}

// Batched weight prep: z=0 transpose-split Wq, z=1 transpose-split Wk, z=2 split Wv.
__global__ void prep_w(const float* __restrict__ Wq, __nv_bfloat16* __restrict__ wqTh, __nv_bfloat16* __restrict__ wqTl,
                       const float* __restrict__ Wk, __nv_bfloat16* __restrict__ wkTh, __nv_bfloat16* __restrict__ wkTl,
                       const float* __restrict__ Wv, __nv_bfloat16* __restrict__ wvh,  __nv_bfloat16* __restrict__ wvl)
{
    __shared__ float t[32][33];
    int bx = blockIdx.x * 32, by = blockIdx.y * 32;
    int tx = threadIdx.x, ty = threadIdx.y;
    const int z = blockIdx.z;
    const float* in = (z == 0) ? Wq : (z == 1) ? Wk : Wv;
    if (z == 2) {
        #pragma unroll
        for (int j = 0; j < 32; j += 8) {
            size_t gi = (size_t)(by + ty + j) * D_DIM + bx + tx;
            float v = in[gi];
            __nv_bfloat16 h = __float2bfloat16(v);
            wvh[gi] = h;
            wvl[gi] = __float2bfloat16(v - __bfloat162float(h));
        }
        return;
    }
    __nv_bfloat16* hi = (z == 0) ? wqTh : wkTh;
    __nv_bfloat16* lo = (z == 0) ? wqTl : wkTl;
    #pragma unroll
    for (int j = 0; j < 32; j += 8)
        t[ty + j][tx] = in[(size_t)(by + ty + j) * D_DIM + bx + tx];
    __syncthreads();
    #pragma unroll
    for (int j = 0; j < 32; j += 8) {
        float v = t[tx][ty + j];
        size_t o = (size_t)(bx + ty + j) * D_DIM + by + tx;
        __nv_bfloat16 h = __float2bfloat16(v);
        hi[o] = h;
        lo[o] = __float2bfloat16(v - __bfloat162float(h));
    }
}

// ---------------- fused small vector ops (exact fp32) ----------------
// partials: z=0: u partials over x (vec=1, R=N_TOK); z=1: w1 over Wk (vec=bq);
//           z=2: v2 over Wq (vec=bk). part layout: [z*16 + c][D]
__global__ void vec_part(const float* __restrict__ x,
                         const float* __restrict__ Wk, const float* __restrict__ bq,
                         const float* __restrict__ Wq, const float* __restrict__ bk,
                         float* __restrict__ part)
{
    const int d = blockIdx.x * 256 + threadIdx.x;
    const int c = blockIdx.y, z = blockIdx.z;
    const float* W = (z == 0) ? x : (z == 1) ? Wk : Wq;
    const float* v = (z == 0) ? nullptr : (z == 1) ? bq : bk;
    const int R = (z == 0) ? N_TOK : D_DIM;
    const int chunk = R / 16;
    float s = 0.0f;
    for (int r = c * chunk; r < (c + 1) * chunk; ++r)
        s = fmaf(v ? v[r] : 1.0f, W[(size_t)r * D_DIM + d], s);
    part[(size_t)(z * 16 + c) * D_DIM + d] = s;
}
// reduce: z=0 -> u, z=1 -> w1, z=2 -> v2 (scaled)
__global__ void vec_reduce(const float* __restrict__ part,
                           float* __restrict__ u, float* __restrict__ w1,
                           float* __restrict__ v2, float sscale)
{
    const int d = blockIdx.x * 256 + threadIdx.x;
    const int z = blockIdx.y;
    float s = 0.0f;
    #pragma unroll
    for (int c = 0; c < 16; ++c) s += part[(size_t)(z * 16 + c) * D_DIM + d];
    if (z == 0) u[d] = s;
    else if (z == 1) w1[d] = s;
    else v2[d] = s * sscale;
}
// blocks 0-1: sc[0]=dot(u,w1), sc[1]=dot(bk,bq); blocks 2..257: v3 = Wv u + N bv
__global__ void vec_dot_rowmv(const float* __restrict__ u, const float* __restrict__ w1,
                              const float* __restrict__ bk, const float* __restrict__ bq,
                              float* __restrict__ sc,
                              const float* __restrict__ Wv, const float* __restrict__ bv,
                              float* __restrict__ v3)
{
    if (blockIdx.x < 2) {
        __shared__ float red[256];
        int tid = threadIdx.x;
        float s = 0.0f;
        if (blockIdx.x == 0)
            for (int i = tid; i < D_DIM; i += 256) s = fmaf(u[i], w1[i], s);
        else
            for (int i = tid; i < D_DIM; i += 256) s = fmaf(bk[i], bq[i], s);
        red[tid] = s;
        __syncthreads();
        for (int o = 128; o; o >>= 1) { if (tid < o) red[tid] += red[tid + o]; __syncthreads(); }
        if (tid == 0) sc[blockIdx.x] = red[0];
        return;
    }
    const int i = ((blockIdx.x - 2) * 256 + threadIdx.x) >> 5;
    const int lane = threadIdx.x & 31;
    if (i >= D_DIM) return;
    float s = 0.0f;
    for (int j = lane; j < D_DIM; j += 32) s = fmaf(Wv[(size_t)i * D_DIM + j], u[j], s);
    #pragma unroll
    for (int o = 16; o; o >>= 1) s += __shfl_xor_sync(0xFFFFFFFFu, s, o);
    if (lane == 0) v3[i] = s + (float)N_TOK * bv[i];
}
// batched split matvec: z=0: w2 = G w1; z=1: v1 = s*T1 u
__global__ void vec_splitmv2(const __nv_bfloat16* __restrict__ gh, const __nv_bfloat16* __restrict__ gl,
                             const float* __restrict__ w1, float* __restrict__ w2,
                             const __nv_bfloat16* __restrict__ t1h, const __nv_bfloat16* __restrict__ t1l,
                             const float* __restrict__ u, float* __restrict__ v1, float sscale)
{
    const __nv_bfloat16* hi = blockIdx.y ? t1h : gh;
    const __nv_bfloat16* lo = blockIdx.y ? t1l : gl;
    const float* v = blockIdx.y ? u : w1;
    float* y = blockIdx.y ? v1 : w2;
    const float alpha = blockIdx.y ? sscale : 1.0f;
    const int i = (blockIdx.x * 256 + threadIdx.x) >> 5;
    const int lane = threadIdx.x & 31;
    if (i >= D_DIM) return;
    float s = 0.0f;
    for (int j = lane; j < D_DIM; j += 32)
        s = fmaf(__bfloat162float(hi[(size_t)i * D_DIM + j]) +
                 __bfloat162float(lo[(size_t)i * D_DIM + j]), v[j], s);
    #pragma unroll
    for (int o = 16; o; o >>= 1) s += __shfl_xor_sync(0xFFFFFFFFu, s, o);
    if (lane == 0) y[i] = s * alpha;
}
// r = s*(Wv w2 + bv*sc0 + v3*sc1)
__global__ void r_kernel(const float* __restrict__ Wv, const float* __restrict__ w2,
                         const float* __restrict__ bv, const float* __restrict__ v3,
                         const float* __restrict__ sc, float* __restrict__ r, float s)
{
    const int i = (blockIdx.x * 256 + threadIdx.x) >> 5;
    const int lane = threadIdx.x & 31;
    if (i >= D_DIM) return;
    float acc = 0.0f;
    for (int j = lane; j < D_DIM; j += 32) acc = fmaf(Wv[(size_t)i * D_DIM + j], w2[j], acc);
    #pragma unroll
    for (int o = 16; o; o >>= 1) acc += __shfl_xor_sync(0xFFFFFFFFu, acc, o);
    if (lane == 0) r[i] = s * (acc + bv[i] * sc[0] + v3[i] * sc[1]);
}

// ---------------- launcher ----------------
extern "C" void kernel_launch(void* const* d_in, const int* in_sizes, int n_in,
                              void* d_out, int out_size)
{
    const float* x  = (const float*)d_in[0];
    const float* Wq = (const float*)d_in[1];
    const float* bq = (const float*)d_in[2];
    const float* Wk = (const float*)d_in[3];
    const float* bk = (const float*)d_in[4];
    const float* Wv = (const float*)d_in[5];
    const float* bv = (const float*)d_in[6];
    float* out = (float*)d_out;

    __nv_bfloat16 *xT_hi, *xT_lo, *x_hi, *x_lo, *wqT_hi, *wqT_lo, *wkT_hi, *wkT_lo;
    __nv_bfloat16 *wv_hi, *wv_lo, *gh, *gl, *t1h, *t1l, *t2h, *t2l, *pTh, *pTl;
    float *part, *u, *w1, *w2, *v1, *v2, *v3, *r, *sc;
    cudaGetSymbolAddress((void**)&xT_hi, g_xT_hi);  cudaGetSymbolAddress((void**)&xT_lo, g_xT_lo);
    cudaGetSymbolAddress((void**)&x_hi, g_x_hi);    cudaGetSymbolAddress((void**)&x_lo, g_x_lo);
    cudaGetSymbolAddress((void**)&wqT_hi, g_wqT_hi);cudaGetSymbolAddress((void**)&wqT_lo, g_wqT_lo);
    cudaGetSymbolAddress((void**)&wkT_hi, g_wkT_hi);cudaGetSymbolAddress((void**)&wkT_lo, g_wkT_lo);
    cudaGetSymbolAddress((void**)&wv_hi, g_wv_hi);  cudaGetSymbolAddress((void**)&wv_lo, g_wv_lo);
    cudaGetSymbolAddress((void**)&gh, g_g_hi);      cudaGetSymbolAddress((void**)&gl, g_g_lo);
    cudaGetSymbolAddress((void**)&t1h, g_t1_hi);    cudaGetSymbolAddress((void**)&t1l, g_t1_lo);
    cudaGetSymbolAddress((void**)&t2h, g_t2_hi);    cudaGetSymbolAddress((void**)&t2l, g_t2_lo);
    cudaGetSymbolAddress((void**)&pTh, g_pT_hi);    cudaGetSymbolAddress((void**)&pTl, g_pT_lo);
    cudaGetSymbolAddress((void**)&part, g_part);
    cudaGetSymbolAddress((void**)&u, g_u);   cudaGetSymbolAddress((void**)&w1, g_w1);
    cudaGetSymbolAddress((void**)&w2, g_w2); cudaGetSymbolAddress((void**)&v1, g_v1);
    cudaGetSymbolAddress((void**)&v2, g_v2); cudaGetSymbolAddress((void**)&v3, g_v3);
    cudaGetSymbolAddress((void**)&r, g_r);   cudaGetSymbolAddress((void**)&sc, g_sc);

    cudaFuncSetAttribute(gemm_mma<0>, cudaFuncAttributeMaxDynamicSharedMemorySize, SMEM_DYN);
    cudaFuncSetAttribute(gemm_mma<2>, cudaFuncAttributeMaxDynamicSharedMemorySize, SMEM_DYN);
    cudaFuncSetAttribute(gemm_mma<3>, cudaFuncAttributeMaxDynamicSharedMemorySize, SMEM_DYN);
    cudaFuncSetAttribute(gemm_sym,    cudaFuncAttributeMaxDynamicSharedMemorySize, SMEM_DYN);

    const float s = 1.0f / sqrtf((float)D_DIM);
    dim3 blk(256);
    dim3 tblk(32, 8);

    // ---- operand preparation ----
    prep_x<<<dim3(D_DIM / 32, N_TOK / 32), tblk>>>(x, x_hi, x_lo, xT_hi, xT_lo);
    prep_w<<<dim3(D_DIM / 32, D_DIM / 32, 3), tblk>>>(Wq, wqT_hi, wqT_lo,
                                                      Wk, wkT_hi, wkT_lo,
                                                      Wv, wv_hi, wv_lo);

    // ---- bias-correction vectors (exact fp32; zeros in this dataset) ----
    vec_part<<<dim3(D_DIM / 256, 16, 3), 256>>>(x, Wk, bq, Wq, bk, part);
    vec_reduce<<<dim3(D_DIM / 256, 3), 256>>>(part, u, w1, v2, s);
    vec_dot_rowmv<<<2 + D_DIM / 8, 256>>>(u, w1, bk, bq, sc, Wv, bv, v3);

    // ---- GEMM chain ----
    // G = x^T x (136 symmetric tiles)
    gemm_sym<<<136, blk, SMEM_DYN>>>(xT_hi, xT_lo, gh, gl, D_DIM, N_TOK);
    // T1 = Wq^T Wk
    gemm_mma<0><<<dim3(16, 16), blk, SMEM_DYN>>>(wqT_hi, wqT_lo, wkT_hi, wkT_lo,
        t1h, t1l, nullptr, nullptr, nullptr, nullptr, nullptr, nullptr,
        D_DIM, D_DIM, D_DIM, 1.0f);
    // w2 = G w1 ; v1 = s*T1 u
    vec_splitmv2<<<dim3(D_DIM / 8, 2), 256>>>(gh, gl, w1, w2, t1h, t1l, u, v1, s);
    // T2 = T1 G (G symmetric -> K-major rows of G)
    gemm_mma<0><<<dim3(16, 16), blk, SMEM_DYN>>>(t1h, t1l, gh, gl,
        t2h, t2l, nullptr, nullptr, nullptr, nullptr, nullptr, nullptr,
        D_DIM, D_DIM, D_DIM, 1.0f);
    // r = s*(Wv w2 + bv*sc0 + v3*sc1)
    r_kernel<<<D_DIM / 8, 256>>>(Wv, w2, bv, v3, sc, r, s);
    // P = s*T2 Wv^T + v1 bv^T + v2 v3^T (store transposed-split pT)
    gemm_mma<2><<<dim3(16, 16), blk, SMEM_DYN>>>(t2h, t2l, wv_hi, wv_lo,
        pTh, pTl, nullptr, v1, bv, v2, v3, nullptr,
        D_DIM, D_DIM, D_DIM, s);
    // out = x P + 1 r^T
    gemm_mma<3><<<dim3(16, 32), blk, SMEM_DYN>>>(x_hi, x_lo, pTh, pTl,
        nullptr, nullptr, out, nullptr, nullptr, nullptr, nullptr, r,
        N_TOK, D_DIM, D_DIM, 1.0f);
}

// round 7
// speedup vs baseline: 1.0650x; 1.0029x over previous
#include <cuda_runtime.h>
#include <cuda_bf16.h>
#include <math.h>
#include <stdint.h>

#define D_DIM 2048
#define N_TOK 4096

// ---------------- device scratch (allocation-free rule) ----------------
__device__ __align__(128) __nv_bfloat16 g_xT_hi[(size_t)D_DIM * N_TOK];
__device__ __align__(128) __nv_bfloat16 g_xT_lo[(size_t)D_DIM * N_TOK];
__device__ __align__(128) __nv_bfloat16 g_x_hi [(size_t)N_TOK * D_DIM];
__device__ __align__(128) __nv_bfloat16 g_x_lo [(size_t)N_TOK * D_DIM];
__device__ __align__(128) __nv_bfloat16 g_wqT_hi[(size_t)D_DIM * D_DIM];
__device__ __align__(128) __nv_bfloat16 g_wqT_lo[(size_t)D_DIM * D_DIM];
__device__ __align__(128) __nv_bfloat16 g_wkT_hi[(size_t)D_DIM * D_DIM];
__device__ __align__(128) __nv_bfloat16 g_wkT_lo[(size_t)D_DIM * D_DIM];
__device__ __align__(128) __nv_bfloat16 g_wv_hi[(size_t)D_DIM * D_DIM];
__device__ __align__(128) __nv_bfloat16 g_wv_lo[(size_t)D_DIM * D_DIM];
__device__ __align__(128) __nv_bfloat16 g_g_hi [(size_t)D_DIM * D_DIM];
__device__ __align__(128) __nv_bfloat16 g_g_lo [(size_t)D_DIM * D_DIM];
__device__ __align__(128) __nv_bfloat16 g_t1_hi[(size_t)D_DIM * D_DIM];
__device__ __align__(128) __nv_bfloat16 g_t1_lo[(size_t)D_DIM * D_DIM];
__device__ __align__(128) __nv_bfloat16 g_t2_hi[(size_t)D_DIM * D_DIM];
__device__ __align__(128) __nv_bfloat16 g_t2_lo[(size_t)D_DIM * D_DIM];
__device__ __align__(128) __nv_bfloat16 g_pT_hi[(size_t)D_DIM * D_DIM];
__device__ __align__(128) __nv_bfloat16 g_pT_lo[(size_t)D_DIM * D_DIM];
__device__ float g_part[48 * D_DIM];
__device__ float g_u[D_DIM], g_w1[D_DIM], g_w2[D_DIM];
__device__ float g_v1[D_DIM], g_v2[D_DIM], g_v3[D_DIM], g_r[D_DIM];
__device__ float g_sc[2];
// tile flags: [0..255] G, [256..511] T1, [512..767] P
__device__ int g_flags[768];

// ---------------- helpers ----------------
__device__ __forceinline__ uint32_t s2u(const void* p) {
    uint32_t a;
    asm("{ .reg .u64 t; cvta.to.shared.u64 t, %1; cvt.u32.u64 %0, t; }" : "=r"(a) : "l"(p));
    return a;
}
__device__ __forceinline__ void cp16(uint32_t dst, const void* src) {
    asm volatile("cp.async.cg.shared.global [%0], [%1], 16;" :: "r"(dst), "l"(src) : "memory");
}
__device__ __forceinline__ void cp_commit() {
    asm volatile("cp.async.commit_group;" ::: "memory");
}
template<int N>
__device__ __forceinline__ void cp_wait() {
    asm volatile("cp.async.wait_group %0;" :: "n"(N) : "memory");
}
__device__ __forceinline__ void ldsm4(uint32_t* r, uint32_t addr) {
    asm volatile("ldmatrix.sync.aligned.m8n8.x4.shared.b16 {%0,%1,%2,%3}, [%4];"
                 : "=r"(r[0]), "=r"(r[1]), "=r"(r[2]), "=r"(r[3]) : "r"(addr));
}
__device__ __forceinline__ void mma16816(float* d, const uint32_t* a, uint32_t b0, uint32_t b1) {
    asm volatile(
        "mma.sync.aligned.m16n8k16.row.col.f32.bf16.bf16.f32 "
        "{%0,%1,%2,%3}, {%4,%5,%6,%7}, {%8,%9}, {%0,%1,%2,%3};"
        : "+f"(d[0]), "+f"(d[1]), "+f"(d[2]), "+f"(d[3])
        : "r"(a[0]), "r"(a[1]), "r"(a[2]), "r"(a[3]), "r"(b0), "r"(b1));
}
// progressive tile wait: tid0 polls, then CTA-wide sync
__device__ __forceinline__ void wait_kblk(volatile int* wA, volatile int* wB, int sB,
                                          int kb, int tid) {
    if (tid == 0) {
        if (wA) while (wA[kb] == 0) __nanosleep(128);
        while (wB[kb * sB] == 0) __nanosleep(128);
        __threadfence();
    }
    __syncthreads();
}

// ---------------- split-bf16 HMMA GEMM body (runtime mode) ----------------
// C[m,n] = alpha * sum_k (Ah+Al)[m,k]*(Bh+Bl)[n,k]  (drops lo*lo)
// mode 0 NORM : Ch/Cl[m*Ntot+n] = split(val)
// mode 1 SYM  : NORM + mirror Ch/Cl[n*Ntot+m]
// mode 2 TRANS: Ch/Cl[n*Mtot+m] = split(val + cA[m]cB[n] + cC[m]cD[n])
// mode 3 FINAL: Cf[m*Ntot+n]    = val*alpha + biascol[n]   (fp32)
// wB != null => progressive waits per 128-wide K-block (wA optional, stride 1).
#define PLANE_B 10240
#define STAGE_B 40960
static const int SMEM_DYN = 2 * STAGE_B;

__device__ __forceinline__ void gemm_body(
    const __nv_bfloat16* __restrict__ Ah, const __nv_bfloat16* __restrict__ Al,
    const __nv_bfloat16* __restrict__ Bh, const __nv_bfloat16* __restrict__ Bl,
    __nv_bfloat16* Ch, __nv_bfloat16* Cl, float* Cf,
    const float* cA, const float* cB, const float* cC, const float* cD,
    const float* biascol,
    int bm0, int bn0, int Mtot, int Ntot, int Kd, float alpha, int mode,
    volatile int* wA, volatile int* wB, int sB,
    char* dyn)
{
    const uint32_t su = s2u(dyn);
    const int tid  = threadIdx.x;
    const int wid  = tid >> 5, lane = tid & 31;
    const int wm0  = (wid & 1) * 64;
    const int wn0  = (wid >> 1) * 32;

    // cp.async schedule: 2048 16B transfers / 256 threads = 8 each
    const __nv_bfloat16* gsrc[8];
    uint32_t doff[8];
    #pragma unroll
    for (int i = 0; i < 8; ++i) {
        int idx   = i * 256 + tid;
        int plane = idx >> 9;
        int row   = (idx >> 2) & 127;
        int seg   = idx & 3;
        const __nv_bfloat16* base =
            (plane == 0) ? Ah : (plane == 1) ? Al : (plane == 2) ? Bh : Bl;
        int grow = (plane < 2 ? bm0 : bn0) + row;
        gsrc[i] = base + (size_t)grow * Kd + seg * 8;
        doff[i] = (uint32_t)(plane * PLANE_B + row * 80 + seg * 16);
    }

    const int NC = Kd / 32;
    if (wB) wait_kblk(wA, wB, sB, 0, tid);
    #pragma unroll
    for (int i = 0; i < 8; ++i) cp16(su + doff[i], gsrc[i]);
    cp_commit();

    float acc[4][4][4];
    #pragma unroll
    for (int im = 0; im < 4; ++im)
        #pragma unroll
        for (int in = 0; in < 4; ++in)
            #pragma unroll
            for (int j = 0; j < 4; ++j) acc[im][in][j] = 0.0f;

    const int a_rl = ((lane >> 3) & 1) * 8 + (lane & 7);
    const int a_ch = ((lane >> 4) & 1) * 16;
    const int b_rl = lane;

    for (int c = 0; c < NC; ++c) {
        cp_wait<0>();
        __syncthreads();
        if (c + 1 < NC) {
            if (wB && (((c + 1) & 3) == 0))
                wait_kblk(wA, wB, sB, (c + 1) >> 2, tid);
            const uint32_t sd = su + ((c + 1) & 1) * STAGE_B;
            const size_t koff = (size_t)(c + 1) * 32;
            #pragma unroll
            for (int i = 0; i < 8; ++i) cp16(sd + doff[i], gsrc[i] + koff);
            cp_commit();
        }
        const uint32_t sb = su + (c & 1) * STAGE_B;
        const uint32_t aBase = sb + (wm0 + a_rl) * 80 + a_ch;
        const uint32_t bBase = sb + (wn0 + b_rl) * 80;

        #pragma unroll
        for (int kk = 0; kk < 2; ++kk) {
            const uint32_t kO = kk * 32;
            uint32_t a[4][4], b0[4], b1[4];
            #pragma unroll
            for (int im = 0; im < 4; ++im)
                ldsm4(a[im], aBase + 0 * PLANE_B + im * (16 * 80) + kO);
            ldsm4(b0, bBase + 3 * PLANE_B + kO);
            ldsm4(b1, bBase + 3 * PLANE_B + kO + 16);
            #pragma unroll
            for (int im = 0; im < 4; ++im)
                #pragma unroll
                for (int in = 0; in < 4; ++in)
                    mma16816(acc[im][in], a[im], b0[in], b1[in]);
            ldsm4(b0, bBase + 2 * PLANE_B + kO);
            ldsm4(b1, bBase + 2 * PLANE_B + kO + 16);
            #pragma unroll
            for (int im = 0; im < 4; ++im)
                #pragma unroll
                for (int in = 0; in < 4; ++in)
                    mma16816(acc[im][in], a[im], b0[in], b1[in]);
            #pragma unroll
            for (int im = 0; im < 4; ++im)
                ldsm4(a[im], aBase + 1 * PLANE_B + im * (16 * 80) + kO);
            #pragma unroll
            for (int im = 0; im < 4; ++im)
                #pragma unroll
                for (int in = 0; in < 4; ++in)
                    mma16816(acc[im][in], a[im], b0[in], b1[in]);
        }
    }

    // ---- epilogue ----
    const int mbase = bm0 + wm0 + (lane >> 2);
    const int nbase = bn0 + wn0 + (lane & 3) * 2;
    #pragma unroll
    for (int im = 0; im < 4; ++im) {
        #pragma unroll
        for (int in = 0; in < 4; ++in) {
            const float* d = acc[im][in];
            const int n0 = nbase + in * 8;
            if (mode == 3) {
                const int m0 = mbase + im * 16;
                float2 v0, v1;
                v0.x = d[0] * alpha + biascol[n0];
                v0.y = d[1] * alpha + biascol[n0 + 1];
                v1.x = d[2] * alpha + biascol[n0];
                v1.y = d[3] * alpha + biascol[n0 + 1];
                *(float2*)(Cf + (size_t)m0 * Ntot + n0)       = v0;
                *(float2*)(Cf + (size_t)(m0 + 8) * Ntot + n0) = v1;
            } else {
                #pragma unroll
                for (int j = 0; j < 4; ++j) {
                    const int m = mbase + im * 16 + (j >> 1) * 8;
                    const int n = n0 + (j & 1);
                    float v = d[j] * alpha;
                    if (mode == 2) v += cA[m] * cB[n] + cC[m] * cD[n];
                    __nv_bfloat16 h = __float2bfloat16(v);
                    __nv_bfloat16 l = __float2bfloat16(v - __bfloat162float(h));
                    if (mode == 0) {
                        size_t o = (size_t)m * Ntot + n;
                        Ch[o] = h; Cl[o] = l;
                    } else if (mode == 1) {
                        size_t o1 = (size_t)m * Ntot + n;
                        size_t o2 = (size_t)n * Ntot + m;
                        Ch[o1] = h; Cl[o1] = l;
                        Ch[o2] = h; Cl[o2] = l;
                    } else { // TRANS
                        size_t o = (size_t)n * Mtot + m;
                        Ch[o] = h; Cl[o] = l;
                    }
                }
            }
        }
    }
}

// release flags after body stores (per-thread fence -> barrier -> tid0 atomics)
__device__ __forceinline__ void set_flags(int f0, int f1) {
    __threadfence();
    __syncthreads();
    if (threadIdx.x == 0) {
        atomicExch(g_flags + f0, 1);
        if (f1 >= 0) atomicExch(g_flags + f1, 1);
    }
}

// ---------------- FUSED1: G (sym) + T1 + T2(progressive) ----------------
__global__ void __launch_bounds__(256, 2) fused1(
    const __nv_bfloat16* __restrict__ xTh, const __nv_bfloat16* __restrict__ xTl,
    __nv_bfloat16* __restrict__ gh, __nv_bfloat16* __restrict__ gl,
    const __nv_bfloat16* __restrict__ wqTh, const __nv_bfloat16* __restrict__ wqTl,
    const __nv_bfloat16* __restrict__ wkTh, const __nv_bfloat16* __restrict__ wkTl,
    __nv_bfloat16* __restrict__ t1h, __nv_bfloat16* __restrict__ t1l,
    __nv_bfloat16* __restrict__ t2h, __nv_bfloat16* __restrict__ t2l)
{
    extern __shared__ char dyn[];
    const int bid = blockIdx.x;
    const __nv_bfloat16 *Ah, *Al, *Bh, *Bl;
    __nv_bfloat16 *Ch, *Cl;
    int bm0, bn0, Kd, mode;
    volatile int *wA = nullptr, *wB = nullptr;

    if (bid < 136) {                       // G = xT xT^T (sym)
        int idx = bid, by = 0;
        while (idx >= 16 - by) { idx -= 16 - by; ++by; }
        int bx = by + idx;
        Ah = xTh; Al = xTl; Bh = xTh; Bl = xTl; Ch = gh; Cl = gl;
        bm0 = by * 128; bn0 = bx * 128; Kd = N_TOK; mode = 1;
    } else if (bid < 392) {                // T1 = Wq^T Wk
        int idx = bid - 136;
        Ah = wqTh; Al = wqTl; Bh = wkTh; Bl = wkTl; Ch = t1h; Cl = t1l;
        bm0 = (idx >> 4) * 128; bn0 = (idx & 15) * 128; Kd = D_DIM; mode = 0;
    } else {                               // T2 = T1 G (waits on T1 rows + G rows)
        int idx = bid - 392;
        int m = idx >> 4, n = idx & 15;
        Ah = t1h; Al = t1l; Bh = gh; Bl = gl; Ch = t2h; Cl = t2l;
        bm0 = m * 128; bn0 = n * 128; Kd = D_DIM; mode = 0;
        wA = g_flags + 256 + m * 16;       // T1 tile (m, kb)
        wB = g_flags + n * 16;             // G  tile (n, kb)
    }

    gemm_body(Ah, Al, Bh, Bl, Ch, Cl, nullptr,
              nullptr, nullptr, nullptr, nullptr, nullptr,
              bm0, bn0, D_DIM, D_DIM, Kd, 1.0f, mode, wA, wB, 1, dyn);

    if (bid < 136) {
        int idx = bid, by = 0;
        while (idx >= 16 - by) { idx -= 16 - by; ++by; }
        int bx = by + idx;
        set_flags(by * 16 + bx, bx * 16 + by);
    } else if (bid < 392) {
        int idx = bid - 136;
        set_flags(256 + idx, -1);
    }
}

// ---------------- FUSED2: P + out(progressive) ----------------
__global__ void __launch_bounds__(256, 2) fused2(
    const __nv_bfloat16* __restrict__ t2h, const __nv_bfloat16* __restrict__ t2l,
    const __nv_bfloat16* __restrict__ wvh, const __nv_bfloat16* __restrict__ wvl,
    __nv_bfloat16* __restrict__ pTh, __nv_bfloat16* __restrict__ pTl,
    const float* __restrict__ v1, const float* __restrict__ bv,
    const float* __restrict__ v2, const float* __restrict__ v3,
    const __nv_bfloat16* __restrict__ xh, const __nv_bfloat16* __restrict__ xl,
    float* __restrict__ outp, const float* __restrict__ r, float s)
{
    extern __shared__ char dyn[];
    const int bid = blockIdx.x;
    if (bid < 256) {                       // P = s*T2 Wv^T + rank2, transposed-split store
        int a = bid >> 4, j = bid & 15;
        gemm_body(t2h, t2l, wvh, wvl, pTh, pTl, nullptr,
                  v1, bv, v2, v3, nullptr,
                  a * 128, j * 128, D_DIM, D_DIM, D_DIM, s, 2,
                  nullptr, nullptr, 1, dyn);
        set_flags(512 + bid, -1);
    } else {                               // out = x P + 1 r^T (waits on P tiles (kb, j))
        int idx = bid - 256;
        int t = idx >> 4, j = idx & 15;
        gemm_body(xh, xl, pTh, pTl, nullptr, nullptr, outp,
                  nullptr, nullptr, nullptr, nullptr, r,
                  t * 128, j * 128, N_TOK, D_DIM, D_DIM, 1.0f, 3,
                  nullptr, g_flags + 512 + j, 16, dyn);
    }
}

// ---------------- flag reset (graph-replay safe) ----------------
__global__ void zero_flags() {
    for (int i = threadIdx.x; i < 768; i += 256) g_flags[i] = 0;
}

// ---------------- preprocessing (one launch) ----------------
// bid < 8192: x tiles (split + transposed split). else: z=0 Wq^T, z=1 Wk^T, z=2 Wv split.
__global__ void prep_all(const float* __restrict__ x,
                         __nv_bfloat16* __restrict__ xh, __nv_bfloat16* __restrict__ xlo,
                         __nv_bfloat16* __restrict__ xth, __nv_bfloat16* __restrict__ xtl,
                         const float* __restrict__ Wq, __nv_bfloat16* __restrict__ wqTh, __nv_bfloat16* __restrict__ wqTl,
                         const float* __restrict__ Wk, __nv_bfloat16* __restrict__ wkTh, __nv_bfloat16* __restrict__ wkTl,
                         const float* __restrict__ Wv, __nv_bfloat16* __restrict__ wvh,  __nv_bfloat16* __restrict__ wvl)
{
    __shared__ float t[32][33];
    const int tx = threadIdx.x, ty = threadIdx.y;  // 32 x 8
    const int bid = blockIdx.x;
    if (bid < 8192) {                      // x: 4096x2048, tiles 128 x 64
        int bx = (bid & 63) * 32, by = (bid >> 6) * 32;
        #pragma unroll
        for (int j = 0; j < 32; j += 8) {
            size_t gi = (size_t)(by + ty + j) * D_DIM + bx + tx;
            float v = x[gi];
            t[ty + j][tx] = v;
            __nv_bfloat16 h = __float2bfloat16(v);
            xh[gi] = h;
            xlo[gi] = __float2bfloat16(v - __bfloat162float(h));
        }
        __syncthreads();
        #pragma unroll
        for (int j = 0; j < 32; j += 8) {
            float v = t[tx][ty + j];
            size_t o = (size_t)(bx + ty + j) * N_TOK + by + tx;
            __nv_bfloat16 h = __float2bfloat16(v);
            xth[o] = h;
            xtl[o] = __float2bfloat16(v - __bfloat162float(h));
        }
        return;
    }
    const int w = bid - 8192;
    const int z = w >> 12;                 // 4096 tiles per weight
    const int rem = w & 4095;
    const int bx = (rem & 63) * 32, by = (rem >> 6) * 32;
    const float* in = (z == 0) ? Wq : (z == 1) ? Wk : Wv;
    if (z == 2) {
        #pragma unroll
        for (int j = 0; j < 32; j += 8) {
            size_t gi = (size_t)(by + ty + j) * D_DIM + bx + tx;
            float v = in[gi];
            __nv_bfloat16 h = __float2bfloat16(v);
            wvh[gi] = h;
            wvl[gi] = __float2bfloat16(v - __bfloat162float(h));
        }
        return;
    }
    __nv_bfloat16* hi = (z == 0) ? wqTh : wkTh;
    __nv_bfloat16* lo = (z == 0) ? wqTl : wkTl;
    #pragma unroll
    for (int j = 0; j < 32; j += 8)
        t[ty + j][tx] = in[(size_t)(by + ty + j) * D_DIM + bx + tx];
    __syncthreads();
    #pragma unroll
    for (int j = 0; j < 32; j += 8) {
        float v = t[tx][ty + j];
        size_t o = (size_t)(bx + ty + j) * D_DIM + by + tx;
        __nv_bfloat16 h = __float2bfloat16(v);
        hi[o] = h;
        lo[o] = __float2bfloat16(v - __bfloat162float(h));
    }
}

// ---------------- fused small vector ops (exact fp32; deterministic) ----------------
__global__ void vec_part(const float* __restrict__ x,
                         const float* __restrict__ Wk, const float* __restrict__ bq,
                         const float* __restrict__ Wq, const float* __restrict__ bk,
                         float* __restrict__ part)
{
    const int d = blockIdx.x * 256 + threadIdx.x;
    const int c = blockIdx.y, z = blockIdx.z;
    const float* W = (z == 0) ? x : (z == 1) ? Wk : Wq;
    const float* v = (z == 0) ? nullptr : (z == 1) ? bq : bk;
    const int R = (z == 0) ? N_TOK : D_DIM;
    const int chunk = R / 16;
    float s = 0.0f;
    for (int r = c * chunk; r < (c + 1) * chunk; ++r)
        s = fmaf(v ? v[r] : 1.0f, W[(size_t)r * D_DIM + d], s);
    part[(size_t)(z * 16 + c) * D_DIM + d] = s;
}
__global__ void vec_reduce(const float* __restrict__ part,
                           float* __restrict__ u, float* __restrict__ w1,
                           float* __restrict__ v2, float sscale)
{
    const int d = blockIdx.x * 256 + threadIdx.x;
    const int z = blockIdx.y;
    float s = 0.0f;
    #pragma unroll
    for (int c = 0; c < 16; ++c) s += part[(size_t)(z * 16 + c) * D_DIM + d];
    if (z == 0) u[d] = s;
    else if (z == 1) w1[d] = s;
    else v2[d] = s * sscale;
}
__global__ void vec_dot_rowmv(const float* __restrict__ u, const float* __restrict__ w1,
                              const float* __restrict__ bk, const float* __restrict__ bq,
                              float* __restrict__ sc,
                              const float* __restrict__ Wv, const float* __restrict__ bv,
                              float* __restrict__ v3)
{
    if (blockIdx.x < 2) {
        __shared__ float red[256];
        int tid = threadIdx.x;
        float s = 0.0f;
        if (blockIdx.x == 0)
            for (int i = tid; i < D_DIM; i += 256) s = fmaf(u[i], w1[i], s);
        else
            for (int i = tid; i < D_DIM; i += 256) s = fmaf(bk[i], bq[i], s);
        red[tid] = s;
        __syncthreads();
        for (int o = 128; o; o >>= 1) { if (tid < o) red[tid] += red[tid + o]; __syncthreads(); }
        if (tid == 0) sc[blockIdx.x] = red[0];
        return;
    }
    const int i = ((blockIdx.x - 2) * 256 + threadIdx.x) >> 5;
    const int lane = threadIdx.x & 31;
    if (i >= D_DIM) return;
    float s = 0.0f;
    for (int j = lane; j < D_DIM; j += 32) s = fmaf(Wv[(size_t)i * D_DIM + j], u[j], s);
    #pragma unroll
    for (int o = 16; o; o >>= 1) s += __shfl_xor_sync(0xFFFFFFFFu, s, o);
    if (lane == 0) v3[i] = s + (float)N_TOK * bv[i];
}
__global__ void vec_splitmv2(const __nv_bfloat16* __restrict__ gh, const __nv_bfloat16* __restrict__ gl,
                             const float* __restrict__ w1, float* __restrict__ w2,
                             const __nv_bfloat16* __restrict__ t1h, const __nv_bfloat16* __restrict__ t1l,
                             const float* __restrict__ u, float* __restrict__ v1, float sscale)
{
    const __nv_bfloat16* hi = blockIdx.y ? t1h : gh;
    const __nv_bfloat16* lo = blockIdx.y ? t1l : gl;
    const float* v = blockIdx.y ? u : w1;
    float* y = blockIdx.y ? v1 : w2;
    const float alpha = blockIdx.y ? sscale : 1.0f;
    const int i = (blockIdx.x * 256 + threadIdx.x) >> 5;
    const int lane = threadIdx.x & 31;
    if (i >= D_DIM) return;
    float s = 0.0f;
    for (int j = lane; j < D_DIM; j += 32)
        s = fmaf(__bfloat162float(hi[(size_t)i * D_DIM + j]) +
                 __bfloat162float(lo[(size_t)i * D_DIM + j]), v[j], s);
    #pragma unroll
    for (int o = 16; o; o >>= 1) s += __shfl_xor_sync(0xFFFFFFFFu, s, o);
    if (lane == 0) y[i] = s * alpha;
}
__global__ void r_kernel(const float* __restrict__ Wv, const float* __restrict__ w2,
                         const float* __restrict__ bv, const float* __restrict__ v3,
                         const float* __restrict__ sc, float* __restrict__ r, float s)
{
    const int i = (blockIdx.x * 256 + threadIdx.x) >> 5;
    const int lane = threadIdx.x & 31;
    if (i >= D_DIM) return;
    float acc = 0.0f;
    for (int j = lane; j < D_DIM; j += 32) acc = fmaf(Wv[(size_t)i * D_DIM + j], w2[j], acc);
    #pragma unroll
    for (int o = 16; o; o >>= 1) acc += __shfl_xor_sync(0xFFFFFFFFu, acc, o);
    if (lane == 0) r[i] = s * (acc + bv[i] * sc[0] + v3[i] * sc[1]);
}

// ---------------- launcher ----------------
extern "C" void kernel_launch(void* const* d_in, const int* in_sizes, int n_in,
                              void* d_out, int out_size)
{
    const float* x  = (const float*)d_in[0];
    const float* Wq = (const float*)d_in[1];
    const float* bq = (const float*)d_in[2];
    const float* Wk = (const float*)d_in[3];
    const float* bk = (const float*)d_in[4];
    const float* Wv = (const float*)d_in[5];
    const float* bv = (const float*)d_in[6];
    float* out = (float*)d_out;

    __nv_bfloat16 *xT_hi, *xT_lo, *x_hi, *x_lo, *wqT_hi, *wqT_lo, *wkT_hi, *wkT_lo;
    __nv_bfloat16 *wv_hi, *wv_lo, *gh, *gl, *t1h, *t1l, *t2h, *t2l, *pTh, *pTl;
    float *part, *u, *w1, *w2, *v1, *v2, *v3, *r, *sc;
    cudaGetSymbolAddress((void**)&xT_hi, g_xT_hi);  cudaGetSymbolAddress((void**)&xT_lo, g_xT_lo);
    cudaGetSymbolAddress((void**)&x_hi, g_x_hi);    cudaGetSymbolAddress((void**)&x_lo, g_x_lo);
    cudaGetSymbolAddress((void**)&wqT_hi, g_wqT_hi);cudaGetSymbolAddress((void**)&wqT_lo, g_wqT_lo);
    cudaGetSymbolAddress((void**)&wkT_hi, g_wkT_hi);cudaGetSymbolAddress((void**)&wkT_lo, g_wkT_lo);
    cudaGetSymbolAddress((void**)&wv_hi, g_wv_hi);  cudaGetSymbolAddress((void**)&wv_lo, g_wv_lo);
    cudaGetSymbolAddress((void**)&gh, g_g_hi);      cudaGetSymbolAddress((void**)&gl, g_g_lo);
    cudaGetSymbolAddress((void**)&t1h, g_t1_hi);    cudaGetSymbolAddress((void**)&t1l, g_t1_lo);
    cudaGetSymbolAddress((void**)&t2h, g_t2_hi);    cudaGetSymbolAddress((void**)&t2l, g_t2_lo);
    cudaGetSymbolAddress((void**)&pTh, g_pT_hi);    cudaGetSymbolAddress((void**)&pTl, g_pT_lo);
    cudaGetSymbolAddress((void**)&part, g_part);
    cudaGetSymbolAddress((void**)&u, g_u);   cudaGetSymbolAddress((void**)&w1, g_w1);
    cudaGetSymbolAddress((void**)&w2, g_w2); cudaGetSymbolAddress((void**)&v1, g_v1);
    cudaGetSymbolAddress((void**)&v2, g_v2); cudaGetSymbolAddress((void**)&v3, g_v3);
    cudaGetSymbolAddress((void**)&r, g_r);   cudaGetSymbolAddress((void**)&sc, g_sc);

    cudaFuncSetAttribute(fused1, cudaFuncAttributeMaxDynamicSharedMemorySize, SMEM_DYN);
    cudaFuncSetAttribute(fused2, cudaFuncAttributeMaxDynamicSharedMemorySize, SMEM_DYN);

    const float s = 1.0f / sqrtf((float)D_DIM);

    // flags must be zero every replay
    zero_flags<<<1, 256>>>();
    // operand prep (one launch)
    prep_all<<<8192 + 3 * 4096, dim3(32, 8)>>>(x, x_hi, x_lo, xT_hi, xT_lo,
                                               Wq, wqT_hi, wqT_lo,
                                               Wk, wkT_hi, wkT_lo,
                                               Wv, wv_hi, wv_lo);
    // bias-correction vectors (exact fp32)
    vec_part<<<dim3(D_DIM / 256, 16, 3), 256>>>(x, Wk, bq, Wq, bk, part);
    vec_reduce<<<dim3(D_DIM / 256, 3), 256>>>(part, u, w1, v2, s);
    vec_dot_rowmv<<<2 + D_DIM / 8, 256>>>(u, w1, bk, bq, sc, Wv, bv, v3);

    // FUSED1: G + T1 + T2 (progressive)
    fused1<<<648, 256, SMEM_DYN>>>(xT_hi, xT_lo, gh, gl,
                                   wqT_hi, wqT_lo, wkT_hi, wkT_lo,
                                   t1h, t1l, t2h, t2l);
    // w2 = G w1 ; v1 = s*T1 u ; r = s*(Wv w2 + bv*sc0 + v3*sc1)
    vec_splitmv2<<<dim3(D_DIM / 8, 2), 256>>>(gh, gl, w1, w2, t1h, t1l, u, v1, s);
    r_kernel<<<D_DIM / 8, 256>>>(Wv, w2, bv, v3, sc, r, s);

    // FUSED2: P + out (progressive)
    fused2<<<768, 256, SMEM_DYN>>>(t2h, t2l, wv_hi, wv_lo, pTh, pTl,
                                   v1, bv, v2, v3,
                                   x_hi, x_lo, out, r, s);
}

// round 8
// speedup vs baseline: 1.1166x; 1.0485x over previous
#include <cuda_runtime.h>
#include <cuda_bf16.h>
#include <math.h>
#include <stdint.h>

#define D_DIM 2048
#define N_TOK 4096

// ---------------- device scratch (allocation-free rule) ----------------
__device__ __align__(128) __nv_bfloat16 g_xT_hi[(size_t)D_DIM * N_TOK];
__device__ __align__(128) __nv_bfloat16 g_xT_lo[(size_t)D_DIM * N_TOK];
__device__ __align__(128) __nv_bfloat16 g_x_hi [(size_t)N_TOK * D_DIM];
__device__ __align__(128) __nv_bfloat16 g_x_lo [(size_t)N_TOK * D_DIM];
__device__ __align__(128) __nv_bfloat16 g_wqT_hi[(size_t)D_DIM * D_DIM];
__device__ __align__(128) __nv_bfloat16 g_wqT_lo[(size_t)D_DIM * D_DIM];
__device__ __align__(128) __nv_bfloat16 g_wkT_hi[(size_t)D_DIM * D_DIM];
__device__ __align__(128) __nv_bfloat16 g_wkT_lo[(size_t)D_DIM * D_DIM];
__device__ __align__(128) __nv_bfloat16 g_wv_hi[(size_t)D_DIM * D_DIM];
__device__ __align__(128) __nv_bfloat16 g_wv_lo[(size_t)D_DIM * D_DIM];
__device__ __align__(128) __nv_bfloat16 g_g_hi [(size_t)D_DIM * D_DIM];
__device__ __align__(128) __nv_bfloat16 g_g_lo [(size_t)D_DIM * D_DIM];
__device__ __align__(128) __nv_bfloat16 g_t1_hi[(size_t)D_DIM * D_DIM];
__device__ __align__(128) __nv_bfloat16 g_t1_lo[(size_t)D_DIM * D_DIM];
__device__ __align__(128) __nv_bfloat16 g_t2_hi[(size_t)D_DIM * D_DIM];
__device__ __align__(128) __nv_bfloat16 g_t2_lo[(size_t)D_DIM * D_DIM];
__device__ __align__(128) __nv_bfloat16 g_pT_hi[(size_t)D_DIM * D_DIM];
__device__ __align__(128) __nv_bfloat16 g_pT_lo[(size_t)D_DIM * D_DIM];
__device__ float g_part[48 * D_DIM];
__device__ float g_u[D_DIM], g_w1[D_DIM], g_w2[D_DIM];
__device__ float g_v1[D_DIM], g_v2[D_DIM], g_v3[D_DIM], g_r[D_DIM];
__device__ float g_t[N_TOK], g_y[D_DIM];
__device__ float g_sc[2];
// tile flags: [0,256) G, [256,512) T1, [512,768) T2, [768,1024) P
__device__ int g_flags[1024];

// ---------------- helpers ----------------
__device__ __forceinline__ uint32_t s2u(const void* p) {
    uint32_t a;
    asm("{ .reg .u64 t; cvta.to.shared.u64 t, %1; cvt.u32.u64 %0, t; }" : "=r"(a) : "l"(p));
    return a;
}
__device__ __forceinline__ void cp16(uint32_t dst, const void* src) {
    asm volatile("cp.async.cg.shared.global [%0], [%1], 16;" :: "r"(dst), "l"(src) : "memory");
}
__device__ __forceinline__ void cp_commit() {
    asm volatile("cp.async.commit_group;" ::: "memory");
}
template<int N>
__device__ __forceinline__ void cp_wait() {
    asm volatile("cp.async.wait_group %0;" :: "n"(N) : "memory");
}
__device__ __forceinline__ void ldsm4(uint32_t* r, uint32_t addr) {
    asm volatile("ldmatrix.sync.aligned.m8n8.x4.shared.b16 {%0,%1,%2,%3}, [%4];"
                 : "=r"(r[0]), "=r"(r[1]), "=r"(r[2]), "=r"(r[3]) : "r"(addr));
}
__device__ __forceinline__ void mma16816(float* d, const uint32_t* a, uint32_t b0, uint32_t b1) {
    asm volatile(
        "mma.sync.aligned.m16n8k16.row.col.f32.bf16.bf16.f32 "
        "{%0,%1,%2,%3}, {%4,%5,%6,%7}, {%8,%9}, {%0,%1,%2,%3};"
        : "+f"(d[0]), "+f"(d[1]), "+f"(d[2]), "+f"(d[3])
        : "r"(a[0]), "r"(a[1]), "r"(a[2]), "r"(a[3]), "r"(b0), "r"(b1));
}
__device__ __forceinline__ void wait_kblk(volatile int* wA, volatile int* wB, int sB,
                                          int kb, int tid) {
    if (tid == 0) {
        if (wA) while (wA[kb] == 0) __nanosleep(128);
        while (wB[kb * sB] == 0) __nanosleep(128);
        __threadfence();
    }
    __syncthreads();
}

// ---------------- split-bf16 HMMA GEMM body (runtime mode) ----------------
// C[m,n] = alpha * sum_k (Ah+Al)[m,k]*(Bh+Bl)[n,k]  (drops lo*lo)
// mode 0 NORM : Ch/Cl[m*Ntot+n] = split(val)
// mode 1 SYM  : NORM + mirror Ch/Cl[n*Ntot+m]
// mode 2 TRANS: Ch/Cl[n*Mtot+m] = split(val + cA[m]cB[n] + cC[m]cD[n])
// mode 3 FINAL: Cf[m*Ntot+n]    = val*alpha + biascol[n]   (fp32)
// wB != null => progressive waits per 128-wide K-block (wA optional, stride 1).
#define PLANE_B 10240
#define STAGE_B 40960
static const int SMEM_DYN = 2 * STAGE_B;

__device__ __forceinline__ void gemm_body(
    const __nv_bfloat16* __restrict__ Ah, const __nv_bfloat16* __restrict__ Al,
    const __nv_bfloat16* __restrict__ Bh, const __nv_bfloat16* __restrict__ Bl,
    __nv_bfloat16* Ch, __nv_bfloat16* Cl, float* Cf,
    const float* cA, const float* cB, const float* cC, const float* cD,
    const float* biascol,
    int bm0, int bn0, int Mtot, int Ntot, int Kd, float alpha, int mode,
    volatile int* wA, volatile int* wB, int sB,
    char* dyn)
{
    const uint32_t su = s2u(dyn);
    const int tid  = threadIdx.x;
    const int wid  = tid >> 5, lane = tid & 31;
    const int wm0  = (wid & 1) * 64;
    const int wn0  = (wid >> 1) * 32;

    const __nv_bfloat16* gsrc[8];
    uint32_t doff[8];
    #pragma unroll
    for (int i = 0; i < 8; ++i) {
        int idx   = i * 256 + tid;
        int plane = idx >> 9;
        int row   = (idx >> 2) & 127;
        int seg   = idx & 3;
        const __nv_bfloat16* base =
            (plane == 0) ? Ah : (plane == 1) ? Al : (plane == 2) ? Bh : Bl;
        int grow = (plane < 2 ? bm0 : bn0) + row;
        gsrc[i] = base + (size_t)grow * Kd + seg * 8;
        doff[i] = (uint32_t)(plane * PLANE_B + row * 80 + seg * 16);
    }

    const int NC = Kd / 32;
    if (wB) wait_kblk(wA, wB, sB, 0, tid);
    #pragma unroll
    for (int i = 0; i < 8; ++i) cp16(su + doff[i], gsrc[i]);
    cp_commit();

    float acc[4][4][4];
    #pragma unroll
    for (int im = 0; im < 4; ++im)
        #pragma unroll
        for (int in = 0; in < 4; ++in)
            #pragma unroll
            for (int j = 0; j < 4; ++j) acc[im][in][j] = 0.0f;

    const int a_rl = ((lane >> 3) & 1) * 8 + (lane & 7);
    const int a_ch = ((lane >> 4) & 1) * 16;
    const int b_rl = lane;

    for (int c = 0; c < NC; ++c) {
        cp_wait<0>();
        __syncthreads();
        if (c + 1 < NC) {
            if (wB && (((c + 1) & 3) == 0))
                wait_kblk(wA, wB, sB, (c + 1) >> 2, tid);
            const uint32_t sd = su + ((c + 1) & 1) * STAGE_B;
            const size_t koff = (size_t)(c + 1) * 32;
            #pragma unroll
            for (int i = 0; i < 8; ++i) cp16(sd + doff[i], gsrc[i] + koff);
            cp_commit();
        }
        const uint32_t sb = su + (c & 1) * STAGE_B;
        const uint32_t aBase = sb + (wm0 + a_rl) * 80 + a_ch;
        const uint32_t bBase = sb + (wn0 + b_rl) * 80;

        #pragma unroll
        for (int kk = 0; kk < 2; ++kk) {
            const uint32_t kO = kk * 32;
            uint32_t a[4][4], b0[4], b1[4];
            #pragma unroll
            for (int im = 0; im < 4; ++im)
                ldsm4(a[im], aBase + 0 * PLANE_B + im * (16 * 80) + kO);
            ldsm4(b0, bBase + 3 * PLANE_B + kO);
            ldsm4(b1, bBase + 3 * PLANE_B + kO + 16);
            #pragma unroll
            for (int im = 0; im < 4; ++im)
                #pragma unroll
                for (int in = 0; in < 4; ++in)
                    mma16816(acc[im][in], a[im], b0[in], b1[in]);
            ldsm4(b0, bBase + 2 * PLANE_B + kO);
            ldsm4(b1, bBase + 2 * PLANE_B + kO + 16);
            #pragma unroll
            for (int im = 0; im < 4; ++im)
                #pragma unroll
                for (int in = 0; in < 4; ++in)
                    mma16816(acc[im][in], a[im], b0[in], b1[in]);
            #pragma unroll
            for (int im = 0; im < 4; ++im)
                ldsm4(a[im], aBase + 1 * PLANE_B + im * (16 * 80) + kO);
            #pragma unroll
            for (int im = 0; im < 4; ++im)
                #pragma unroll
                for (int in = 0; in < 4; ++in)
                    mma16816(acc[im][in], a[im], b0[in], b1[in]);
        }
    }

    // ---- epilogue ----
    const int mbase = bm0 + wm0 + (lane >> 2);
    const int nbase = bn0 + wn0 + (lane & 3) * 2;
    #pragma unroll
    for (int im = 0; im < 4; ++im) {
        #pragma unroll
        for (int in = 0; in < 4; ++in) {
            const float* d = acc[im][in];
            const int n0 = nbase + in * 8;
            if (mode == 3) {
                const int m0 = mbase + im * 16;
                float2 v0, v1;
                v0.x = d[0] * alpha + biascol[n0];
                v0.y = d[1] * alpha + biascol[n0 + 1];
                v1.x = d[2] * alpha + biascol[n0];
                v1.y = d[3] * alpha + biascol[n0 + 1];
                *(float2*)(Cf + (size_t)m0 * Ntot + n0)       = v0;
                *(float2*)(Cf + (size_t)(m0 + 8) * Ntot + n0) = v1;
            } else {
                #pragma unroll
                for (int j = 0; j < 4; ++j) {
                    const int m = mbase + im * 16 + (j >> 1) * 8;
                    const int n = n0 + (j & 1);
                    float v = d[j] * alpha;
                    if (mode == 2) v += cA[m] * cB[n] + cC[m] * cD[n];
                    __nv_bfloat16 h = __float2bfloat16(v);
                    __nv_bfloat16 l = __float2bfloat16(v - __bfloat162float(h));
                    if (mode == 0) {
                        size_t o = (size_t)m * Ntot + n;
                        Ch[o] = h; Cl[o] = l;
                    } else if (mode == 1) {
                        size_t o1 = (size_t)m * Ntot + n;
                        size_t o2 = (size_t)n * Ntot + m;
                        Ch[o1] = h; Cl[o1] = l;
                        Ch[o2] = h; Cl[o2] = l;
                    } else {
                        size_t o = (size_t)n * Mtot + m;
                        Ch[o] = h; Cl[o] = l;
                    }
                }
            }
        }
    }
}

__device__ __forceinline__ void set_flags(int f0, int f1) {
    __threadfence();
    __syncthreads();
    if (threadIdx.x == 0) {
        atomicExch(g_flags + f0, 1);
        if (f1 >= 0) atomicExch(g_flags + f1, 1);
    }
}

// ---------------- MEGA: all 5 GEMMs, one launch, DAG via flags ----------------
// [0,136)    G  = xT xT^T (sym)                 -> flags [0,256)
// [136,392)  T1 = Wq^T Wk                       -> flags [256,512)
// [392,648)  T2 = T1 G      waits T1 row, G row -> flags [512,768)
// [648,904)  P  = s T2 Wv^T + rank2 (trans)     waits T2 row -> flags [768,1024)
// [904,1416) out = x P + 1 r^T (fp32)           waits P(kb, j)
__global__ void __launch_bounds__(256, 2) mega(
    const __nv_bfloat16* __restrict__ xTh, const __nv_bfloat16* __restrict__ xTl,
    __nv_bfloat16* __restrict__ gh, __nv_bfloat16* __restrict__ gl,
    const __nv_bfloat16* __restrict__ wqTh, const __nv_bfloat16* __restrict__ wqTl,
    const __nv_bfloat16* __restrict__ wkTh, const __nv_bfloat16* __restrict__ wkTl,
    __nv_bfloat16* __restrict__ t1h, __nv_bfloat16* __restrict__ t1l,
    __nv_bfloat16* __restrict__ t2h, __nv_bfloat16* __restrict__ t2l,
    const __nv_bfloat16* __restrict__ wvh, const __nv_bfloat16* __restrict__ wvl,
    __nv_bfloat16* __restrict__ pTh, __nv_bfloat16* __restrict__ pTl,
    const float* __restrict__ v1, const float* __restrict__ bv,
    const float* __restrict__ v2, const float* __restrict__ v3,
    const __nv_bfloat16* __restrict__ xh, const __nv_bfloat16* __restrict__ xl,
    float* __restrict__ outp, const float* __restrict__ r, float s)
{
    extern __shared__ char dyn[];
    const int bid = blockIdx.x;

    if (bid < 136) {                        // G (symmetric, 2-unit tiles)
        int idx = bid, by = 0;
        while (idx >= 16 - by) { idx -= 16 - by; ++by; }
        int bx = by + idx;
        gemm_body(xTh, xTl, xTh, xTl, gh, gl, nullptr,
                  nullptr, nullptr, nullptr, nullptr, nullptr,
                  by * 128, bx * 128, D_DIM, D_DIM, N_TOK, 1.0f, 1,
                  nullptr, nullptr, 1, dyn);
        set_flags(by * 16 + bx, bx * 16 + by);
    } else if (bid < 392) {                 // T1
        int idx = bid - 136;
        gemm_body(wqTh, wqTl, wkTh, wkTl, t1h, t1l, nullptr,
                  nullptr, nullptr, nullptr, nullptr, nullptr,
                  (idx >> 4) * 128, (idx & 15) * 128, D_DIM, D_DIM, D_DIM, 1.0f, 0,
                  nullptr, nullptr, 1, dyn);
        set_flags(256 + idx, -1);
    } else if (bid < 648) {                 // T2 = T1 G
        int idx = bid - 392;
        int m = idx >> 4, n = idx & 15;
        gemm_body(t1h, t1l, gh, gl, t2h, t2l, nullptr,
                  nullptr, nullptr, nullptr, nullptr, nullptr,
                  m * 128, n * 128, D_DIM, D_DIM, D_DIM, 1.0f, 0,
                  g_flags + 256 + m * 16, g_flags + n * 16, 1, dyn);
        set_flags(512 + idx, -1);
    } else if (bid < 904) {                 // P (trans store + rank-2)
        int idx = bid - 648;
        int a = idx >> 4, j = idx & 15;
        gemm_body(t2h, t2l, wvh, wvl, pTh, pTl, nullptr,
                  v1, bv, v2, v3, nullptr,
                  a * 128, j * 128, D_DIM, D_DIM, D_DIM, s, 2,
                  nullptr, g_flags + 512 + a * 16, 1, dyn);
        set_flags(768 + idx, -1);
    } else {                                // out
        int idx = bid - 904;
        int t = idx >> 4, j = idx & 15;
        gemm_body(xh, xl, pTh, pTl, nullptr, nullptr, outp,
                  nullptr, nullptr, nullptr, nullptr, r,
                  t * 128, j * 128, N_TOK, D_DIM, D_DIM, 1.0f, 3,
                  nullptr, g_flags + 768 + j, 16, dyn);
    }
}

__global__ void zero_flags() {
    for (int i = threadIdx.x; i < 1024; i += 256) g_flags[i] = 0;
}

// ---------------- preprocessing (one launch) ----------------
__global__ void prep_all(const float* __restrict__ x,
                         __nv_bfloat16* __restrict__ xh, __nv_bfloat16* __restrict__ xlo,
                         __nv_bfloat16* __restrict__ xth, __nv_bfloat16* __restrict__ xtl,
                         const float* __restrict__ Wq, __nv_bfloat16* __restrict__ wqTh, __nv_bfloat16* __restrict__ wqTl,
                         const float* __restrict__ Wk, __nv_bfloat16* __restrict__ wkTh, __nv_bfloat16* __restrict__ wkTl,
                         const float* __restrict__ Wv, __nv_bfloat16* __restrict__ wvh,  __nv_bfloat16* __restrict__ wvl)
{
    __shared__ float t[32][33];
    const int tx = threadIdx.x, ty = threadIdx.y;  // 32 x 8
    const int bid = blockIdx.x;
    if (bid < 8192) {
        int bx = (bid & 63) * 32, by = (bid >> 6) * 32;
        #pragma unroll
        for (int j = 0; j < 32; j += 8) {
            size_t gi = (size_t)(by + ty + j) * D_DIM + bx + tx;
            float v = x[gi];
            t[ty + j][tx] = v;
            __nv_bfloat16 h = __float2bfloat16(v);
            xh[gi] = h;
            xlo[gi] = __float2bfloat16(v - __bfloat162float(h));
        }
        __syncthreads();
        #pragma unroll
        for (int j = 0; j < 32; j += 8) {
            float v = t[tx][ty + j];
            size_t o = (size_t)(bx + ty + j) * N_TOK + by + tx;
            __nv_bfloat16 h = __float2bfloat16(v);
            xth[o] = h;
            xtl[o] = __float2bfloat16(v - __bfloat162float(h));
        }
        return;
    }
    const int w = bid - 8192;
    const int z = w >> 12;
    const int rem = w & 4095;
    const int bx = (rem & 63) * 32, by = (rem >> 6) * 32;
    const float* in = (z == 0) ? Wq : (z == 1) ? Wk : Wv;
    if (z == 2) {
        #pragma unroll
        for (int j = 0; j < 32; j += 8) {
            size_t gi = (size_t)(by + ty + j) * D_DIM + bx + tx;
            float v = in[gi];
            __nv_bfloat16 h = __float2bfloat16(v);
            wvh[gi] = h;
            wvl[gi] = __float2bfloat16(v - __bfloat162float(h));
        }
        return;
    }
    __nv_bfloat16* hi = (z == 0) ? wqTh : wkTh;
    __nv_bfloat16* lo = (z == 0) ? wqTl : wkTl;
    #pragma unroll
    for (int j = 0; j < 32; j += 8)
        t[ty + j][tx] = in[(size_t)(by + ty + j) * D_DIM + bx + tx];
    __syncthreads();
    #pragma unroll
    for (int j = 0; j < 32; j += 8) {
        float v = t[tx][ty + j];
        size_t o = (size_t)(bx + ty + j) * D_DIM + by + tx;
        __nv_bfloat16 h = __float2bfloat16(v);
        hi[o] = h;
        lo[o] = __float2bfloat16(v - __bfloat162float(h));
    }
}

// ---------------- exact fp32 vector chain (all pre-GEMM) ----------------
// pass 1 partials: z=0 u over x (vec=1), z=1 w1 over Wk (vec=bq), z=2 v2 over Wq (vec=bk)
__global__ void vec_part(const float* __restrict__ x,
                         const float* __restrict__ Wk, const float* __restrict__ bq,
                         const float* __restrict__ Wq, const float* __restrict__ bk,
                         float* __restrict__ part)
{
    const int d = blockIdx.x * 256 + threadIdx.x;
    const int c = blockIdx.y, z = blockIdx.z;
    const float* W = (z == 0) ? x : (z == 1) ? Wk : Wq;
    const float* v = (z == 0) ? nullptr : (z == 1) ? bq : bk;
    const int R = (z == 0) ? N_TOK : D_DIM;
    const int chunk = R / 16;
    float s = 0.0f;
    for (int r = c * chunk; r < (c + 1) * chunk; ++r)
        s = fmaf(v ? v[r] : 1.0f, W[(size_t)r * D_DIM + d], s);
    part[(size_t)(z * 16 + c) * D_DIM + d] = s;
}
__global__ void vec_reduce(const float* __restrict__ part,
                           float* __restrict__ u, float* __restrict__ w1,
                           float* __restrict__ v2, float sscale)
{
    const int d = blockIdx.x * 256 + threadIdx.x;
    const int z = blockIdx.y;
    float s = 0.0f;
    #pragma unroll
    for (int c = 0; c < 16; ++c) s += part[(size_t)(z * 16 + c) * D_DIM + d];
    if (z == 0) u[d] = s;
    else if (z == 1) w1[d] = s;
    else v2[d] = s * sscale;
}
// matvecs + dots: b<2 dots; [2,514) t=x w1 (4096 rows); [514,770) y=Wk u; [770,1026) v3=Wv u+N bv
__global__ void vec_mv(const float* __restrict__ x,  const float* __restrict__ w1, float* __restrict__ tvec,
                       const float* __restrict__ Wk, const float* __restrict__ u,  float* __restrict__ y,
                       const float* __restrict__ Wv, const float* __restrict__ bv, float* __restrict__ v3,
                       const float* __restrict__ bk, const float* __restrict__ bq, float* __restrict__ sc)
{
    const int b = blockIdx.x;
    if (b < 2) {
        __shared__ float red[256];
        int tid = threadIdx.x;
        float s = 0.0f;
        if (b == 0) for (int i = tid; i < D_DIM; i += 256) s = fmaf(u[i], w1[i], s);
        else        for (int i = tid; i < D_DIM; i += 256) s = fmaf(bk[i], bq[i], s);
        red[tid] = s;
        __syncthreads();
        for (int o = 128; o; o >>= 1) { if (tid < o) red[tid] += red[tid + o]; __syncthreads(); }
        if (tid == 0) sc[b] = red[0];
        return;
    }
    const int lane = threadIdx.x & 31;
    const float* W; const float* v; float* out; int rows0;
    if (b < 514)      { W = x;  v = w1; out = tvec; rows0 = (b - 2) * 8; }
    else if (b < 770) { W = Wk; v = u;  out = y;    rows0 = (b - 514) * 8; }
    else              { W = Wv; v = u;  out = v3;   rows0 = (b - 770) * 8; }
    const int i = rows0 + (threadIdx.x >> 5);
    float s = 0.0f;
    for (int j = lane; j < D_DIM; j += 32) s = fmaf(W[(size_t)i * D_DIM + j], v[j], s);
    #pragma unroll
    for (int o = 16; o; o >>= 1) s += __shfl_xor_sync(0xFFFFFFFFu, s, o);
    if (lane == 0) out[i] = (b < 770) ? s : s + (float)N_TOK * bv[i];
}
// pass 2 partials: z=0 w2 over x (vec=t, R=N_TOK), z=1 v1 over Wq (vec=y, R=D_DIM)
__global__ void vec_part2(const float* __restrict__ x, const float* __restrict__ tvec,
                          const float* __restrict__ Wq, const float* __restrict__ y,
                          float* __restrict__ part)
{
    const int d = blockIdx.x * 256 + threadIdx.x;
    const int c = blockIdx.y, z = blockIdx.z;
    const float* W = z ? Wq : x;
    const float* v = z ? y : tvec;
    const int R = z ? D_DIM : N_TOK;
    const int chunk = R / 16;
    float s = 0.0f;
    for (int r = c * chunk; r < (c + 1) * chunk; ++r)
        s = fmaf(v[r], W[(size_t)r * D_DIM + d], s);
    part[(size_t)(z * 16 + c) * D_DIM + d] = s;
}
__global__ void vec_reduce2(const float* __restrict__ part,
                            float* __restrict__ w2, float* __restrict__ v1, float sscale)
{
    const int d = blockIdx.x * 256 + threadIdx.x;
    const int z = blockIdx.y;
    float s = 0.0f;
    #pragma unroll
    for (int c = 0; c < 16; ++c) s += part[(size_t)(z * 16 + c) * D_DIM + d];
    if (z == 0) w2[d] = s;
    else v1[d] = s * sscale;
}
__global__ void r_kernel(const float* __restrict__ Wv, const float* __restrict__ w2,
                         const float* __restrict__ bv, const float* __restrict__ v3,
                         const float* __restrict__ sc, float* __restrict__ r, float s)
{
    const int i = (blockIdx.x * 256 + threadIdx.x) >> 5;
    const int lane = threadIdx.x & 31;
    if (i >= D_DIM) return;
    float acc = 0.0f;
    for (int j = lane; j < D_DIM; j += 32) acc = fmaf(Wv[(size_t)i * D_DIM + j], w2[j], acc);
    #pragma unroll
    for (int o = 16; o; o >>= 1) acc += __shfl_xor_sync(0xFFFFFFFFu, acc, o);
    if (lane == 0) r[i] = s * (acc + bv[i] * sc[0] + v3[i] * sc[1]);
}

// ---------------- launcher ----------------
extern "C" void kernel_launch(void* const* d_in, const int* in_sizes, int n_in,
                              void* d_out, int out_size)
{
    const float* x  = (const float*)d_in[0];
    const float* Wq = (const float*)d_in[1];
    const float* bq = (const float*)d_in[2];
    const float* Wk = (const float*)d_in[3];
    const float* bk = (const float*)d_in[4];
    const float* Wv = (const float*)d_in[5];
    const float* bv = (const float*)d_in[6];
    float* out = (float*)d_out;

    __nv_bfloat16 *xT_hi, *xT_lo, *x_hi, *x_lo, *wqT_hi, *wqT_lo, *wkT_hi, *wkT_lo;
    __nv_bfloat16 *wv_hi, *wv_lo, *gh, *gl, *t1h, *t1l, *t2h, *t2l, *pTh, *pTl;
    float *part, *u, *w1, *w2, *v1, *v2, *v3, *r, *sc, *tvec, *y;
    cudaGetSymbolAddress((void**)&xT_hi, g_xT_hi);  cudaGetSymbolAddress((void**)&xT_lo, g_xT_lo);
    cudaGetSymbolAddress((void**)&x_hi, g_x_hi);    cudaGetSymbolAddress((void**)&x_lo, g_x_lo);
    cudaGetSymbolAddress((void**)&wqT_hi, g_wqT_hi);cudaGetSymbolAddress((void**)&wqT_lo, g_wqT_lo);
    cudaGetSymbolAddress((void**)&wkT_hi, g_wkT_hi);cudaGetSymbolAddress((void**)&wkT_lo, g_wkT_lo);
    cudaGetSymbolAddress((void**)&wv_hi, g_wv_hi);  cudaGetSymbolAddress((void**)&wv_lo, g_wv_lo);
    cudaGetSymbolAddress((void**)&gh, g_g_hi);      cudaGetSymbolAddress((void**)&gl, g_g_lo);
    cudaGetSymbolAddress((void**)&t1h, g_t1_hi);    cudaGetSymbolAddress((void**)&t1l, g_t1_lo);
    cudaGetSymbolAddress((void**)&t2h, g_t2_hi);    cudaGetSymbolAddress((void**)&t2l, g_t2_lo);
    cudaGetSymbolAddress((void**)&pTh, g_pT_hi);    cudaGetSymbolAddress((void**)&pTl, g_pT_lo);
    cudaGetSymbolAddress((void**)&part, g_part);
    cudaGetSymbolAddress((void**)&u, g_u);   cudaGetSymbolAddress((void**)&w1, g_w1);
    cudaGetSymbolAddress((void**)&w2, g_w2); cudaGetSymbolAddress((void**)&v1, g_v1);
    cudaGetSymbolAddress((void**)&v2, g_v2); cudaGetSymbolAddress((void**)&v3, g_v3);
    cudaGetSymbolAddress((void**)&r, g_r);   cudaGetSymbolAddress((void**)&sc, g_sc);
    cudaGetSymbolAddress((void**)&tvec, g_t);cudaGetSymbolAddress((void**)&y, g_y);

    cudaFuncSetAttribute(mega, cudaFuncAttributeMaxDynamicSharedMemorySize, SMEM_DYN);

    const float s = 1.0f / sqrtf((float)D_DIM);

    zero_flags<<<1, 256>>>();
    prep_all<<<8192 + 3 * 4096, dim3(32, 8)>>>(x, x_hi, x_lo, xT_hi, xT_lo,
                                               Wq, wqT_hi, wqT_lo,
                                               Wk, wkT_hi, wkT_lo,
                                               Wv, wv_hi, wv_lo);
    // exact fp32 vector chain (no GEMM dependencies)
    vec_part<<<dim3(D_DIM / 256, 16, 3), 256>>>(x, Wk, bq, Wq, bk, part);
    vec_reduce<<<dim3(D_DIM / 256, 3), 256>>>(part, u, w1, v2, s);
    vec_mv<<<1026, 256>>>(x, w1, tvec, Wk, u, y, Wv, bv, v3, bk, bq, sc);
    vec_part2<<<dim3(D_DIM / 256, 16, 2), 256>>>(x, tvec, Wq, y, part);
    vec_reduce2<<<dim3(D_DIM / 256, 2), 256>>>(part, w2, v1, s);
    r_kernel<<<D_DIM / 8, 256>>>(Wv, w2, bv, v3, sc, r, s);

    // all GEMMs in one DAG launch
    mega<<<1416, 256, SMEM_DYN>>>(xT_hi, xT_lo, gh, gl,
                                  wqT_hi, wqT_lo, wkT_hi, wkT_lo,
                                  t1h, t1l, t2h, t2l,
                                  wv_hi, wv_lo, pTh, pTl,
                                  v1, bv, v2, v3,
                                  x_hi, x_lo, out, r, s);
}

// round 9
// speedup vs baseline: 1.1792x; 1.0560x over previous
#include <cuda_runtime.h>
#include <cuda_bf16.h>
#include <math.h>
#include <stdint.h>

#define D_DIM 2048
#define N_TOK 4096

// ---------------- device scratch (allocation-free rule) ----------------
__device__ __align__(128) __nv_bfloat16 g_xT_hi[(size_t)D_DIM * N_TOK];
__device__ __align__(128) __nv_bfloat16 g_xT_lo[(size_t)D_DIM * N_TOK];
__device__ __align__(128) __nv_bfloat16 g_x_hi [(size_t)N_TOK * D_DIM];
__device__ __align__(128) __nv_bfloat16 g_x_lo [(size_t)N_TOK * D_DIM];
__device__ __align__(128) __nv_bfloat16 g_wqT_hi[(size_t)D_DIM * D_DIM];
__device__ __align__(128) __nv_bfloat16 g_wqT_lo[(size_t)D_DIM * D_DIM];
__device__ __align__(128) __nv_bfloat16 g_wkT_hi[(size_t)D_DIM * D_DIM];
__device__ __align__(128) __nv_bfloat16 g_wkT_lo[(size_t)D_DIM * D_DIM];
__device__ __align__(128) __nv_bfloat16 g_wv_hi[(size_t)D_DIM * D_DIM];
__device__ __align__(128) __nv_bfloat16 g_wv_lo[(size_t)D_DIM * D_DIM];
__device__ __align__(128) __nv_bfloat16 g_g_hi [(size_t)D_DIM * D_DIM];
__device__ __align__(128) __nv_bfloat16 g_g_lo [(size_t)D_DIM * D_DIM];
__device__ __align__(128) __nv_bfloat16 g_t1_hi[(size_t)D_DIM * D_DIM];
__device__ __align__(128) __nv_bfloat16 g_t1_lo[(size_t)D_DIM * D_DIM];
__device__ __align__(128) __nv_bfloat16 g_t2_hi[(size_t)D_DIM * D_DIM];
__device__ __align__(128) __nv_bfloat16 g_t2_lo[(size_t)D_DIM * D_DIM];
__device__ __align__(128) __nv_bfloat16 g_pT_hi[(size_t)D_DIM * D_DIM];
__device__ __align__(128) __nv_bfloat16 g_pT_lo[(size_t)D_DIM * D_DIM];
__device__ float g_part[48 * D_DIM];
__device__ float g_u[D_DIM], g_w1[D_DIM], g_w2[D_DIM];
__device__ float g_v1[D_DIM], g_v2[D_DIM], g_v3[D_DIM], g_r[D_DIM];
__device__ float g_t[N_TOK], g_y[D_DIM];
__device__ float g_sc[2];
// tile flags: [0,256) G, [256,512) T1, [512,768) T2, [768,1024) P
__device__ int g_flags[1024];
// vec-stage counters: 0:A 1:B 2:C 3:D 4:E 5:F
__device__ int g_vcnt[8];

// ---------------- helpers ----------------
__device__ __forceinline__ uint32_t s2u(const void* p) {
    uint32_t a;
    asm("{ .reg .u64 t; cvta.to.shared.u64 t, %1; cvt.u32.u64 %0, t; }" : "=r"(a) : "l"(p));
    return a;
}
__device__ __forceinline__ void cp16(uint32_t dst, const void* src) {
    asm volatile("cp.async.cg.shared.global [%0], [%1], 16;" :: "r"(dst), "l"(src) : "memory");
}
__device__ __forceinline__ void cp_commit() {
    asm volatile("cp.async.commit_group;" ::: "memory");
}
template<int N>
__device__ __forceinline__ void cp_wait() {
    asm volatile("cp.async.wait_group %0;" :: "n"(N) : "memory");
}
__device__ __forceinline__ void ldsm4(uint32_t* r, uint32_t addr) {
    asm volatile("ldmatrix.sync.aligned.m8n8.x4.shared.b16 {%0,%1,%2,%3}, [%4];"
                 : "=r"(r[0]), "=r"(r[1]), "=r"(r[2]), "=r"(r[3]) : "r"(addr));
}
__device__ __forceinline__ void mma16816(float* d, const uint32_t* a, uint32_t b0, uint32_t b1) {
    asm volatile(
        "mma.sync.aligned.m16n8k16.row.col.f32.bf16.bf16.f32 "
        "{%0,%1,%2,%3}, {%4,%5,%6,%7}, {%8,%9}, {%0,%1,%2,%3};"
        : "+f"(d[0]), "+f"(d[1]), "+f"(d[2]), "+f"(d[3])
        : "r"(a[0]), "r"(a[1]), "r"(a[2]), "r"(a[3]), "r"(b0), "r"(b1));
}
__device__ __forceinline__ void wait_kblk(volatile int* wA, volatile int* wB, int sB,
                                          int kb, int tid) {
    if (tid == 0) {
        if (wA) while (wA[kb] == 0) __nanosleep(128);
        while (wB[kb * sB] == 0) __nanosleep(128);
        __threadfence();
    }
    __syncthreads();
}
__device__ __forceinline__ void vwait(volatile int* cnt, int target) {
    if (threadIdx.x == 0) {
        while (*cnt < target) __nanosleep(256);
        __threadfence();
    }
    __syncthreads();
}
__device__ __forceinline__ void vdone(int* cnt) {
    __threadfence();
    __syncthreads();
    if (threadIdx.x == 0) atomicAdd(cnt, 1);
}

// ---------------- split-bf16 HMMA GEMM body (runtime mode) ----------------
// C[m,n] = alpha * sum_k (Ah+Al)[m,k]*(Bh+Bl)[n,k]  (drops lo*lo)
// mode 0 NORM : Ch/Cl[m*Ntot+n] = split(val)
// mode 1 SYM  : NORM + mirror Ch/Cl[n*Ntot+m]
// mode 2 TRANS: Ch/Cl[n*Mtot+m] = split(val + cA[m]cB[n] + cC[m]cD[n])
// mode 3 FINAL: Cf[m*Ntot+n]    = val*alpha + biascol[n]   (fp32)
// wB != null => progressive waits per 128-wide K-block (wA optional, stride 1).
#define PLANE_B 10240
#define STAGE_B 40960
static const int SMEM_DYN = 2 * STAGE_B;

__device__ __forceinline__ void gemm_body(
    const __nv_bfloat16* __restrict__ Ah, const __nv_bfloat16* __restrict__ Al,
    const __nv_bfloat16* __restrict__ Bh, const __nv_bfloat16* __restrict__ Bl,
    __nv_bfloat16* Ch, __nv_bfloat16* Cl, float* Cf,
    const float* cA, const float* cB, const float* cC, const float* cD,
    const float* biascol,
    int bm0, int bn0, int Mtot, int Ntot, int Kd, float alpha, int mode,
    volatile int* wA, volatile int* wB, int sB,
    char* dyn)
{
    const uint32_t su = s2u(dyn);
    const int tid  = threadIdx.x;
    const int wid  = tid >> 5, lane = tid & 31;
    const int wm0  = (wid & 1) * 64;
    const int wn0  = (wid >> 1) * 32;

    const __nv_bfloat16* gsrc[8];
    uint32_t doff[8];
    #pragma unroll
    for (int i = 0; i < 8; ++i) {
        int idx   = i * 256 + tid;
        int plane = idx >> 9;
        int row   = (idx >> 2) & 127;
        int seg   = idx & 3;
        const __nv_bfloat16* base =
            (plane == 0) ? Ah : (plane == 1) ? Al : (plane == 2) ? Bh : Bl;
        int grow = (plane < 2 ? bm0 : bn0) + row;
        gsrc[i] = base + (size_t)grow * Kd + seg * 8;
        doff[i] = (uint32_t)(plane * PLANE_B + row * 80 + seg * 16);
    }

    const int NC = Kd / 32;
    if (wB) wait_kblk(wA, wB, sB, 0, tid);
    #pragma unroll
    for (int i = 0; i < 8; ++i) cp16(su + doff[i], gsrc[i]);
    cp_commit();

    float acc[4][4][4];
    #pragma unroll
    for (int im = 0; im < 4; ++im)
        #pragma unroll
        for (int in = 0; in < 4; ++in)
            #pragma unroll
            for (int j = 0; j < 4; ++j) acc[im][in][j] = 0.0f;

    const int a_rl = ((lane >> 3) & 1) * 8 + (lane & 7);
    const int a_ch = ((lane >> 4) & 1) * 16;
    const int b_rl = lane;

    for (int c = 0; c < NC; ++c) {
        cp_wait<0>();
        __syncthreads();
        if (c + 1 < NC) {
            if (wB && (((c + 1) & 3) == 0))
                wait_kblk(wA, wB, sB, (c + 1) >> 2, tid);
            const uint32_t sd = su + ((c + 1) & 1) * STAGE_B;
            const size_t koff = (size_t)(c + 1) * 32;
            #pragma unroll
            for (int i = 0; i < 8; ++i) cp16(sd + doff[i], gsrc[i] + koff);
            cp_commit();
        }
        const uint32_t sb = su + (c & 1) * STAGE_B;
        const uint32_t aBase = sb + (wm0 + a_rl) * 80 + a_ch;
        const uint32_t bBase = sb + (wn0 + b_rl) * 80;

        #pragma unroll
        for (int kk = 0; kk < 2; ++kk) {
            const uint32_t kO = kk * 32;
            uint32_t a[4][4], b0[4], b1[4];
            #pragma unroll
            for (int im = 0; im < 4; ++im)
                ldsm4(a[im], aBase + 0 * PLANE_B + im * (16 * 80) + kO);
            ldsm4(b0, bBase + 3 * PLANE_B + kO);
            ldsm4(b1, bBase + 3 * PLANE_B + kO + 16);
            #pragma unroll
            for (int im = 0; im < 4; ++im)
                #pragma unroll
                for (int in = 0; in < 4; ++in)
                    mma16816(acc[im][in], a[im], b0[in], b1[in]);
            ldsm4(b0, bBase + 2 * PLANE_B + kO);
            ldsm4(b1, bBase + 2 * PLANE_B + kO + 16);
            #pragma unroll
            for (int im = 0; im < 4; ++im)
                #pragma unroll
                for (int in = 0; in < 4; ++in)
                    mma16816(acc[im][in], a[im], b0[in], b1[in]);
            #pragma unroll
            for (int im = 0; im < 4; ++im)
                ldsm4(a[im], aBase + 1 * PLANE_B + im * (16 * 80) + kO);
            #pragma unroll
            for (int im = 0; im < 4; ++im)
                #pragma unroll
                for (int in = 0; in < 4; ++in)
                    mma16816(acc[im][in], a[im], b0[in], b1[in]);
        }
    }

    // ---- epilogue ----
    const int mbase = bm0 + wm0 + (lane >> 2);
    const int nbase = bn0 + wn0 + (lane & 3) * 2;
    #pragma unroll
    for (int im = 0; im < 4; ++im) {
        #pragma unroll
        for (int in = 0; in < 4; ++in) {
            const float* d = acc[im][in];
            const int n0 = nbase + in * 8;
            if (mode == 3) {
                const int m0 = mbase + im * 16;
                float2 v0, v1;
                v0.x = d[0] * alpha + biascol[n0];
                v0.y = d[1] * alpha + biascol[n0 + 1];
                v1.x = d[2] * alpha + biascol[n0];
                v1.y = d[3] * alpha + biascol[n0 + 1];
                *(float2*)(Cf + (size_t)m0 * Ntot + n0)       = v0;
                *(float2*)(Cf + (size_t)(m0 + 8) * Ntot + n0) = v1;
            } else {
                #pragma unroll
                for (int j = 0; j < 4; ++j) {
                    const int m = mbase + im * 16 + (j >> 1) * 8;
                    const int n = n0 + (j & 1);
                    float v = d[j] * alpha;
                    if (mode == 2) v += cA[m] * cB[n] + cC[m] * cD[n];
                    __nv_bfloat16 h = __float2bfloat16(v);
                    __nv_bfloat16 l = __float2bfloat16(v - __bfloat162float(h));
                    if (mode == 0) {
                        size_t o = (size_t)m * Ntot + n;
                        Ch[o] = h; Cl[o] = l;
                    } else if (mode == 1) {
                        size_t o1 = (size_t)m * Ntot + n;
                        size_t o2 = (size_t)n * Ntot + m;
                        Ch[o1] = h; Cl[o1] = l;
                        Ch[o2] = h; Cl[o2] = l;
                    } else {
                        size_t o = (size_t)n * Mtot + m;
                        Ch[o] = h; Cl[o] = l;
                    }
                }
            }
        }
    }
}

__device__ __forceinline__ void set_flags(int f0, int f1) {
    __threadfence();
    __syncthreads();
    if (threadIdx.x == 0) {
        atomicExch(g_flags + f0, 1);
        if (f1 >= 0) atomicExch(g_flags + f1, 1);
    }
}

// ---------------- vec chain inside mega: idx in [0,1002) ----------------
// A[0,384): partials (u over x | w1 over Wk,bq | v2 over Wq,bk)
// B[384,408): reduce -> u, w1, v2
// C[408,666): matvecs t=x w1 (128), y=Wk u (64), v3=Wv u + N bv (64); dots (2)
// D[666,922): partials (w2 over x,t | v1 over Wq,y)
// E[922,938): reduce -> w2, v1
// F[938,1002): r = s*(Wv w2 + bv sc0 + v3 sc1)
__device__ void vec_work(int idx,
                         const float* x, const float* Wq, const float* bq,
                         const float* Wk, const float* bk,
                         const float* Wv, const float* bv, float sscale)
{
    const int tid = threadIdx.x;
    if (idx < 384) {
        int dblk = idx & 7, c = (idx >> 3) & 15, z = idx >> 7;
        const float* W = (z == 0) ? x : (z == 1) ? Wk : Wq;
        const float* v = (z == 0) ? nullptr : (z == 1) ? bq : bk;
        const int R = (z == 0) ? N_TOK : D_DIM;
        const int chunk = R / 16;
        const int d = dblk * 256 + tid;
        float s = 0.0f;
        for (int r = c * chunk; r < (c + 1) * chunk; ++r)
            s = fmaf(v ? v[r] : 1.0f, W[(size_t)r * D_DIM + d], s);
        g_part[(size_t)(z * 16 + c) * D_DIM + d] = s;
        vdone(g_vcnt + 0);
    } else if (idx < 408) {
        vwait(g_vcnt + 0, 384);
        int i2 = idx - 384, dblk = i2 & 7, z = i2 >> 3;
        const int d = dblk * 256 + tid;
        float s = 0.0f;
        #pragma unroll
        for (int c = 0; c < 16; ++c) s += g_part[(size_t)(z * 16 + c) * D_DIM + d];
        if (z == 0) g_u[d] = s;
        else if (z == 1) g_w1[d] = s;
        else g_v2[d] = s * sscale;
        vdone(g_vcnt + 1);
    } else if (idx < 666) {
        vwait(g_vcnt + 1, 24);
        int i2 = idx - 408;
        if (i2 < 256) {
            const int lane = tid & 31, w = tid >> 5;
            const float* W; const float* v; float* outv; int rbase; bool addb = false;
            if (i2 < 128)      { W = x;  v = g_w1; outv = g_t;  rbase = i2 * 32; }
            else if (i2 < 192) { W = Wk; v = g_u;  outv = g_y;  rbase = (i2 - 128) * 32; }
            else               { W = Wv; v = g_u;  outv = g_v3; rbase = (i2 - 192) * 32; addb = true; }
            for (int rr = 0; rr < 4; ++rr) {
                const int i = rbase + w * 4 + rr;
                float s = 0.0f;
                for (int j = lane; j < D_DIM; j += 32)
                    s = fmaf(W[(size_t)i * D_DIM + j], v[j], s);
                #pragma unroll
                for (int o = 16; o; o >>= 1) s += __shfl_xor_sync(0xFFFFFFFFu, s, o);
                if (lane == 0) outv[i] = addb ? s + (float)N_TOK * bv[i] : s;
            }
        } else {
            __shared__ float red[256];
            float s = 0.0f;
            if (i2 == 256) for (int i = tid; i < D_DIM; i += 256) s = fmaf(g_u[i], g_w1[i], s);
            else           for (int i = tid; i < D_DIM; i += 256) s = fmaf(bk[i], bq[i], s);
            red[tid] = s;
            __syncthreads();
            for (int o = 128; o; o >>= 1) { if (tid < o) red[tid] += red[tid + o]; __syncthreads(); }
            if (tid == 0) g_sc[i2 - 256] = red[0];
        }
        vdone(g_vcnt + 2);
    } else if (idx < 922) {
        vwait(g_vcnt + 2, 258);
        int i2 = idx - 666, dblk = i2 & 7, c = (i2 >> 3) & 15, z = i2 >> 7;
        const float* W = z ? Wq : x;
        const float* v = z ? g_y : g_t;
        const int R = z ? D_DIM : N_TOK;
        const int chunk = R / 16;
        const int d = dblk * 256 + tid;
        float s = 0.0f;
        for (int r = c * chunk; r < (c + 1) * chunk; ++r)
            s = fmaf(v[r], W[(size_t)r * D_DIM + d], s);
        g_part[(size_t)(z * 16 + c) * D_DIM + d] = s;
        vdone(g_vcnt + 3);
    } else if (idx < 938) {
        vwait(g_vcnt + 3, 256);
        int i2 = idx - 922, dblk = i2 & 7, z = i2 >> 3;
        const int d = dblk * 256 + tid;
        float s = 0.0f;
        #pragma unroll
        for (int c = 0; c < 16; ++c) s += g_part[(size_t)(z * 16 + c) * D_DIM + d];
        if (z == 0) g_w2[d] = s;
        else g_v1[d] = s * sscale;
        vdone(g_vcnt + 4);
    } else {
        vwait(g_vcnt + 4, 16);
        int i2 = idx - 938;
        const int lane = tid & 31, w = tid >> 5;
        for (int rr = 0; rr < 4; ++rr) {
            const int i = i2 * 32 + w * 4 + rr;
            float acc = 0.0f;
            for (int j = lane; j < D_DIM; j += 32)
                acc = fmaf(Wv[(size_t)i * D_DIM + j], g_w2[j], acc);
            #pragma unroll
            for (int o = 16; o; o >>= 1) acc += __shfl_xor_sync(0xFFFFFFFFu, acc, o);
            if (lane == 0) g_r[i] = sscale * (acc + bv[i] * g_sc[0] + g_v3[i] * g_sc[1]);
        }
        vdone(g_vcnt + 5);
    }
}

// ---------------- MEGA: 5 GEMMs + vec chain, one launch ----------------
// [0,136)      G  = xT xT^T (sym)                    -> flags [0,256)
// [136,392)    T1 = Wq^T Wk                          -> flags [256,512)
// [392,1394)   vec chain (counters)
// [1394,1650)  T2 = T1 G       waits T1 row + G row  -> flags [512,768)
// [1650,1906)  P  = s T2 Wv^T + rank2 (trans)        waits T2 row + vecE -> flags [768,1024)
// [1906,2418)  out = x P + 1 r^T (fp32)              waits P(kb,j) + vecF
__global__ void __launch_bounds__(256, 2) mega(
    const float* __restrict__ x, const float* __restrict__ Wq, const float* __restrict__ bq,
    const float* __restrict__ Wk, const float* __restrict__ bk,
    const float* __restrict__ Wv, const float* __restrict__ bv,
    const __nv_bfloat16* __restrict__ xTh, const __nv_bfloat16* __restrict__ xTl,
    __nv_bfloat16* __restrict__ gh, __nv_bfloat16* __restrict__ gl,
    const __nv_bfloat16* __restrict__ wqTh, const __nv_bfloat16* __restrict__ wqTl,
    const __nv_bfloat16* __restrict__ wkTh, const __nv_bfloat16* __restrict__ wkTl,
    __nv_bfloat16* __restrict__ t1h, __nv_bfloat16* __restrict__ t1l,
    __nv_bfloat16* __restrict__ t2h, __nv_bfloat16* __restrict__ t2l,
    const __nv_bfloat16* __restrict__ wvh, const __nv_bfloat16* __restrict__ wvl,
    __nv_bfloat16* __restrict__ pTh, __nv_bfloat16* __restrict__ pTl,
    const float* v1, const float* v2, const float* v3,
    const __nv_bfloat16* __restrict__ xh, const __nv_bfloat16* __restrict__ xl,
    float* __restrict__ outp, const float* r, float s)
{
    extern __shared__ char dyn[];
    const int bid = blockIdx.x;

    if (bid < 136) {                        // G (symmetric, 2-unit tiles)
        int idx = bid, by = 0;
        while (idx >= 16 - by) { idx -= 16 - by; ++by; }
        int bx = by + idx;
        gemm_body(xTh, xTl, xTh, xTl, gh, gl, nullptr,
                  nullptr, nullptr, nullptr, nullptr, nullptr,
                  by * 128, bx * 128, D_DIM, D_DIM, N_TOK, 1.0f, 1,
                  nullptr, nullptr, 1, dyn);
        set_flags(by * 16 + bx, bx * 16 + by);
    } else if (bid < 392) {                 // T1
        int idx = bid - 136;
        gemm_body(wqTh, wqTl, wkTh, wkTl, t1h, t1l, nullptr,
                  nullptr, nullptr, nullptr, nullptr, nullptr,
                  (idx >> 4) * 128, (idx & 15) * 128, D_DIM, D_DIM, D_DIM, 1.0f, 0,
                  nullptr, nullptr, 1, dyn);
        set_flags(256 + idx, -1);
    } else if (bid < 1394) {                // vec chain
        vec_work(bid - 392, x, Wq, bq, Wk, bk, Wv, bv, s);
    } else if (bid < 1650) {                // T2 = T1 G
        int idx = bid - 1394;
        int m = idx >> 4, n = idx & 15;
        gemm_body(t1h, t1l, gh, gl, t2h, t2l, nullptr,
                  nullptr, nullptr, nullptr, nullptr, nullptr,
                  m * 128, n * 128, D_DIM, D_DIM, D_DIM, 1.0f, 0,
                  g_flags + 256 + m * 16, g_flags + n * 16, 1, dyn);
        set_flags(512 + idx, -1);
    } else if (bid < 1906) {                // P (trans store + rank-2)
        int idx = bid - 1650;
        int a = idx >> 4, j = idx & 15;
        vwait(g_vcnt + 4, 16);              // v1/v2/v3 ready (E implies B,C,D done)
        gemm_body(t2h, t2l, wvh, wvl, pTh, pTl, nullptr,
                  v1, bv, v2, v3, nullptr,
                  a * 128, j * 128, D_DIM, D_DIM, D_DIM, s, 2,
                  nullptr, g_flags + 512 + a * 16, 1, dyn);
        set_flags(768 + idx, -1);
    } else {                                // out
        int idx = bid - 1906;
        int t = idx >> 4, j = idx & 15;
        vwait(g_vcnt + 5, 64);              // r ready
        gemm_body(xh, xl, pTh, pTl, nullptr, nullptr, outp,
                  nullptr, nullptr, nullptr, nullptr, r,
                  t * 128, j * 128, N_TOK, D_DIM, D_DIM, 1.0f, 3,
                  nullptr, g_flags + 768 + j, 16, dyn);
    }
}

// ---------------- preprocessing (one launch; bid 0 also zeroes flags) ----------------
__global__ void prep_all(const float* __restrict__ x,
                         __nv_bfloat16* __restrict__ xh, __nv_bfloat16* __restrict__ xlo,
                         __nv_bfloat16* __restrict__ xth, __nv_bfloat16* __restrict__ xtl,
                         const float* __restrict__ Wq, __nv_bfloat16* __restrict__ wqTh, __nv_bfloat16* __restrict__ wqTl,
                         const float* __restrict__ Wk, __nv_bfloat16* __restrict__ wkTh, __nv_bfloat16* __restrict__ wkTl,
                         const float* __restrict__ Wv, __nv_bfloat16* __restrict__ wvh,  __nv_bfloat16* __restrict__ wvl)
{
    __shared__ float t[32][33];
    const int tx = threadIdx.x, ty = threadIdx.y;  // 32 x 8
    const int bid = blockIdx.x;
    const int tid = ty * 32 + tx;
    if (bid == 0) {
        for (int i = tid; i < 1024; i += 256) g_flags[i] = 0;
        if (tid < 8) g_vcnt[tid] = 0;
    }
    if (bid < 8192) {
        int bx = (bid & 63) * 32, by = (bid >> 6) * 32;
        #pragma unroll
        for (int j = 0; j < 32; j += 8) {
            size_t gi = (size_t)(by + ty + j) * D_DIM + bx + tx;
            float v = x[gi];
            t[ty + j][tx] = v;
            __nv_bfloat16 h = __float2bfloat16(v);
            xh[gi] = h;
            xlo[gi] = __float2bfloat16(v - __bfloat162float(h));
        }
        __syncthreads();
        #pragma unroll
        for (int j = 0; j < 32; j += 8) {
            float v = t[tx][ty + j];
            size_t o = (size_t)(bx + ty + j) * N_TOK + by + tx;
            __nv_bfloat16 h = __float2bfloat16(v);
            xth[o] = h;
            xtl[o] = __float2bfloat16(v - __bfloat162float(h));
        }
        return;
    }
    const int w = bid - 8192;
    const int z = w >> 12;
    const int rem = w & 4095;
    const int bx = (rem & 63) * 32, by = (rem >> 6) * 32;
    const float* in = (z == 0) ? Wq : (z == 1) ? Wk : Wv;
    if (z == 2) {
        #pragma unroll
        for (int j = 0; j < 32; j += 8) {
            size_t gi = (size_t)(by + ty + j) * D_DIM + bx + tx;
            float v = in[gi];
            __nv_bfloat16 h = __float2bfloat16(v);
            wvh[gi] = h;
            wvl[gi] = __float2bfloat16(v - __bfloat162float(h));
        }
        return;
    }
    __nv_bfloat16* hi = (z == 0) ? wqTh : wkTh;
    __nv_bfloat16* lo = (z == 0) ? wqTl : wkTl;
    #pragma unroll
    for (int j = 0; j < 32; j += 8)
        t[ty + j][tx] = in[(size_t)(by + ty + j) * D_DIM + bx + tx];
    __syncthreads();
    #pragma unroll
    for (int j = 0; j < 32; j += 8) {
        float v = t[tx][ty + j];
        size_t o = (size_t)(bx + ty + j) * D_DIM + by + tx;
        __nv_bfloat16 h = __float2bfloat16(v);
        hi[o] = h;
        lo[o] = __float2bfloat16(v - __bfloat162float(h));
    }
}

// ---------------- launcher ----------------
extern "C" void kernel_launch(void* const* d_in, const int* in_sizes, int n_in,
                              void* d_out, int out_size)
{
    const float* x  = (const float*)d_in[0];
    const float* Wq = (const float*)d_in[1];
    const float* bq = (const float*)d_in[2];
    const float* Wk = (const float*)d_in[3];
    const float* bk = (const float*)d_in[4];
    const float* Wv = (const float*)d_in[5];
    const float* bv = (const float*)d_in[6];
    float* out = (float*)d_out;

    __nv_bfloat16 *xT_hi, *xT_lo, *x_hi, *x_lo, *wqT_hi, *wqT_lo, *wkT_hi, *wkT_lo;
    __nv_bfloat16 *wv_hi, *wv_lo, *gh, *gl, *t1h, *t1l, *t2h, *t2l, *pTh, *pTl;
    float *v1, *v2, *v3, *r;
    cudaGetSymbolAddress((void**)&xT_hi, g_xT_hi);  cudaGetSymbolAddress((void**)&xT_lo, g_xT_lo);
    cudaGetSymbolAddress((void**)&x_hi, g_x_hi);    cudaGetSymbolAddress((void**)&x_lo, g_x_lo);
    cudaGetSymbolAddress((void**)&wqT_hi, g_wqT_hi);cudaGetSymbolAddress((void**)&wqT_lo, g_wqT_lo);
    cudaGetSymbolAddress((void**)&wkT_hi, g_wkT_hi);cudaGetSymbolAddress((void**)&wkT_lo, g_wkT_lo);
    cudaGetSymbolAddress((void**)&wv_hi, g_wv_hi);  cudaGetSymbolAddress((void**)&wv_lo, g_wv_lo);
    cudaGetSymbolAddress((void**)&gh, g_g_hi);      cudaGetSymbolAddress((void**)&gl, g_g_lo);
    cudaGetSymbolAddress((void**)&t1h, g_t1_hi);    cudaGetSymbolAddress((void**)&t1l, g_t1_lo);
    cudaGetSymbolAddress((void**)&t2h, g_t2_hi);    cudaGetSymbolAddress((void**)&t2l, g_t2_lo);
    cudaGetSymbolAddress((void**)&pTh, g_pT_hi);    cudaGetSymbolAddress((void**)&pTl, g_pT_lo);
    cudaGetSymbolAddress((void**)&v1, g_v1);        cudaGetSymbolAddress((void**)&v2, g_v2);
    cudaGetSymbolAddress((void**)&v3, g_v3);        cudaGetSymbolAddress((void**)&r, g_r);

    cudaFuncSetAttribute(mega, cudaFuncAttributeMaxDynamicSharedMemorySize, SMEM_DYN);

    const float s = 1.0f / sqrtf((float)D_DIM);

    // prep (bid 0 zeroes flags/counters)
    prep_all<<<8192 + 3 * 4096, dim3(32, 8)>>>(x, x_hi, x_lo, xT_hi, xT_lo,
                                               Wq, wqT_hi, wqT_lo,
                                               Wk, wkT_hi, wkT_lo,
                                               Wv, wv_hi, wv_lo);
    // everything else in one DAG launch
    mega<<<2418, 256, SMEM_DYN>>>(x, Wq, bq, Wk, bk, Wv, bv,
                                  xT_hi, xT_lo, gh, gl,
                                  wqT_hi, wqT_lo, wkT_hi, wkT_lo,
                                  t1h, t1l, t2h, t2l,
                                  wv_hi, wv_lo, pTh, pTl,
                                  v1, v2, v3,
                                  x_hi, x_lo, out, r, s);
}

// round 10
// speedup vs baseline: 1.6444x; 1.3945x over previous
#include <cuda_runtime.h>
#include <cuda_fp16.h>
#include <math.h>
#include <stdint.h>

#define D_DIM 2048
#define N_TOK 4096

// ---------------- device scratch (allocation-free rule) ----------------
__device__ __align__(128) __half g_xT_hi[(size_t)D_DIM * N_TOK];
__device__ __align__(128) __half g_xT_lo[(size_t)D_DIM * N_TOK];
__device__ __align__(128) __half g_x_hi [(size_t)N_TOK * D_DIM];
__device__ __align__(128) __half g_x_lo [(size_t)N_TOK * D_DIM];
__device__ __align__(128) __half g_wqT_hi[(size_t)D_DIM * D_DIM];
__device__ __align__(128) __half g_wqT_lo[(size_t)D_DIM * D_DIM];
__device__ __align__(128) __half g_wkT_hi[(size_t)D_DIM * D_DIM];
__device__ __align__(128) __half g_wv_hi[(size_t)D_DIM * D_DIM];
__device__ __align__(128) __half g_g_hi [(size_t)D_DIM * D_DIM];
__device__ __align__(128) __half g_t1_hi[(size_t)D_DIM * D_DIM];
__device__ __align__(128) __half g_t1_lo[(size_t)D_DIM * D_DIM];
__device__ __align__(128) __half g_t2_hi[(size_t)D_DIM * D_DIM];
__device__ __align__(128) __half g_t2_lo[(size_t)D_DIM * D_DIM];
__device__ __align__(128) __half g_pT_hi[(size_t)D_DIM * D_DIM];
__device__ float g_part[48 * D_DIM];
__device__ float g_u[D_DIM], g_w1[D_DIM], g_w2[D_DIM];
__device__ float g_v1[D_DIM], g_v2[D_DIM], g_v3[D_DIM], g_r[D_DIM];
__device__ float g_t[N_TOK], g_y[D_DIM];
__device__ float g_sc[2];
// tile flags: [0,256) G, [256,512) T1, [512,768) T2, [768,1024) P
__device__ int g_flags[1024];
// vec-stage counters: 0:A 1:B 2:C 3:D 4:E 5:F
__device__ int g_vcnt[8];

// ---------------- helpers ----------------
__device__ __forceinline__ uint32_t s2u(const void* p) {
    uint32_t a;
    asm("{ .reg .u64 t; cvta.to.shared.u64 t, %1; cvt.u32.u64 %0, t; }" : "=r"(a) : "l"(p));
    return a;
}
__device__ __forceinline__ void cp16(uint32_t dst, const void* src) {
    asm volatile("cp.async.cg.shared.global [%0], [%1], 16;" :: "r"(dst), "l"(src) : "memory");
}
__device__ __forceinline__ void cp_commit() {
    asm volatile("cp.async.commit_group;" ::: "memory");
}
template<int N>
__device__ __forceinline__ void cp_wait() {
    asm volatile("cp.async.wait_group %0;" :: "n"(N) : "memory");
}
__device__ __forceinline__ void ldsm4(uint32_t* r, uint32_t addr) {
    asm volatile("ldmatrix.sync.aligned.m8n8.x4.shared.b16 {%0,%1,%2,%3}, [%4];"
                 : "=r"(r[0]), "=r"(r[1]), "=r"(r[2]), "=r"(r[3]) : "r"(addr));
}
__device__ __forceinline__ void mma16816(float* d, const uint32_t* a, uint32_t b0, uint32_t b1) {
    asm volatile(
        "mma.sync.aligned.m16n8k16.row.col.f32.f16.f16.f32 "
        "{%0,%1,%2,%3}, {%4,%5,%6,%7}, {%8,%9}, {%0,%1,%2,%3};"
        : "+f"(d[0]), "+f"(d[1]), "+f"(d[2]), "+f"(d[3])
        : "r"(a[0]), "r"(a[1]), "r"(a[2]), "r"(a[3]), "r"(b0), "r"(b1));
}
__device__ __forceinline__ void wait_kblk(volatile int* wA, volatile int* wB, int sB,
                                          int kb, int tid) {
    if (tid == 0) {
        if (wA) while (wA[kb] == 0) __nanosleep(128);
        while (wB[kb * sB] == 0) __nanosleep(128);
        __threadfence();
    }
    __syncthreads();
}
__device__ __forceinline__ void vwait(volatile int* cnt, int target) {
    if (threadIdx.x == 0) {
        while (*cnt < target) __nanosleep(256);
        __threadfence();
    }
    __syncthreads();
}
__device__ __forceinline__ void vdone(int* cnt) {
    __threadfence();
    __syncthreads();
    if (threadIdx.x == 0) atomicAdd(cnt, 1);
}

// ---------------- fp16 single-split HMMA GEMM body ----------------
// C[m,n] = alpha * sum_k (Ah+Al)[m,k] * Bh[n,k]
// mode 0 NORM : Ch[m*Ntot+n]=hi, Cl[...]=lo   (both planes)
// mode 1 SYM  : hi only, both mirror positions
// mode 2 TRANS: Ch[n*Mtot+m] = hi(val + cA[m]cB[n] + cC[m]cD[n])  (hi only)
// mode 3 FINAL: Cf[m*Ntot+n] = val*alpha + biascol[n]   (fp32)
// wB != null => progressive waits per 128-wide K-block (wA optional, stride 1).
#define PLANE_B 10240
#define STAGE_B 30720
static const int SMEM_DYN = 2 * STAGE_B;

__device__ __forceinline__ void gemm_body(
    const __half* __restrict__ Ah, const __half* __restrict__ Al,
    const __half* __restrict__ Bh,
    __half* Ch, __half* Cl, float* Cf,
    const float* cA, const float* cB, const float* cC, const float* cD,
    const float* biascol,
    int bm0, int bn0, int Mtot, int Ntot, int Kd, float alpha, int mode,
    volatile int* wA, volatile int* wB, int sB,
    char* dyn)
{
    const uint32_t su = s2u(dyn);
    const int tid  = threadIdx.x;
    const int wid  = tid >> 5, lane = tid & 31;
    const int wm0  = (wid & 1) * 64;
    const int wn0  = (wid >> 1) * 32;

    // cp.async schedule: 1536 16B transfers / 256 threads = 6 each
    const __half* gsrc[6];
    uint32_t doff[6];
    #pragma unroll
    for (int i = 0; i < 6; ++i) {
        int idx   = i * 256 + tid;
        int plane = idx >> 9;            // 0:Ah 1:Al 2:Bh
        int row   = (idx >> 2) & 127;
        int seg   = idx & 3;
        const __half* base = (plane == 0) ? Ah : (plane == 1) ? Al : Bh;
        int grow = (plane < 2 ? bm0 : bn0) + row;
        gsrc[i] = base + (size_t)grow * Kd + seg * 8;
        doff[i] = (uint32_t)(plane * PLANE_B + row * 80 + seg * 16);
    }

    const int NC = Kd / 32;
    if (wB) wait_kblk(wA, wB, sB, 0, tid);
    #pragma unroll
    for (int i = 0; i < 6; ++i) cp16(su + doff[i], gsrc[i]);
    cp_commit();

    float acc[4][4][4];
    #pragma unroll
    for (int im = 0; im < 4; ++im)
        #pragma unroll
        for (int in = 0; in < 4; ++in)
            #pragma unroll
            for (int j = 0; j < 4; ++j) acc[im][in][j] = 0.0f;

    const int a_rl = ((lane >> 3) & 1) * 8 + (lane & 7);
    const int a_ch = ((lane >> 4) & 1) * 16;
    const int b_rl = lane;

    for (int c = 0; c < NC; ++c) {
        cp_wait<0>();
        __syncthreads();
        if (c + 1 < NC) {
            if (wB && (((c + 1) & 3) == 0))
                wait_kblk(wA, wB, sB, (c + 1) >> 2, tid);
            const uint32_t sd = su + ((c + 1) & 1) * STAGE_B;
            const size_t koff = (size_t)(c + 1) * 32;
            #pragma unroll
            for (int i = 0; i < 6; ++i) cp16(sd + doff[i], gsrc[i] + koff);
            cp_commit();
        }
        const uint32_t sb = su + (c & 1) * STAGE_B;
        const uint32_t aBase = sb + (wm0 + a_rl) * 80 + a_ch;
        const uint32_t bBase = sb + (wn0 + b_rl) * 80 + 2 * PLANE_B;

        #pragma unroll
        for (int kk = 0; kk < 2; ++kk) {
            const uint32_t kO = kk * 32;
            uint32_t a[4][4], b0[4], b1[4];
            // B fragments: loaded once, reused across both A passes
            ldsm4(b0, bBase + kO);
            ldsm4(b1, bBase + kO + 16);
            // pass 1: A_hi
            #pragma unroll
            for (int im = 0; im < 4; ++im)
                ldsm4(a[im], aBase + 0 * PLANE_B + im * (16 * 80) + kO);
            #pragma unroll
            for (int im = 0; im < 4; ++im)
                #pragma unroll
                for (int in = 0; in < 4; ++in)
                    mma16816(acc[im][in], a[im], b0[in], b1[in]);
            // pass 2: A_lo
            #pragma unroll
            for (int im = 0; im < 4; ++im)
                ldsm4(a[im], aBase + 1 * PLANE_B + im * (16 * 80) + kO);
            #pragma unroll
            for (int im = 0; im < 4; ++im)
                #pragma unroll
                for (int in = 0; in < 4; ++in)
                    mma16816(acc[im][in], a[im], b0[in], b1[in]);
        }
    }

    // ---- epilogue ----
    const int mbase = bm0 + wm0 + (lane >> 2);
    const int nbase = bn0 + wn0 + (lane & 3) * 2;
    #pragma unroll
    for (int im = 0; im < 4; ++im) {
        #pragma unroll
        for (int in = 0; in < 4; ++in) {
            const float* d = acc[im][in];
            const int n0 = nbase + in * 8;
            if (mode == 3) {
                const int m0 = mbase + im * 16;
                float2 v0, v1;
                v0.x = d[0] * alpha + biascol[n0];
                v0.y = d[1] * alpha + biascol[n0 + 1];
                v1.x = d[2] * alpha + biascol[n0];
                v1.y = d[3] * alpha + biascol[n0 + 1];
                *(float2*)(Cf + (size_t)m0 * Ntot + n0)       = v0;
                *(float2*)(Cf + (size_t)(m0 + 8) * Ntot + n0) = v1;
            } else {
                #pragma unroll
                for (int j = 0; j < 4; ++j) {
                    const int m = mbase + im * 16 + (j >> 1) * 8;
                    const int n = n0 + (j & 1);
                    float v = d[j] * alpha;
                    if (mode == 2) v += cA[m] * cB[n] + cC[m] * cD[n];
                    __half h = __float2half(v);
                    if (mode == 0) {
                        size_t o = (size_t)m * Ntot + n;
                        Ch[o] = h;
                        Cl[o] = __float2half(v - __half2float(h));
                    } else if (mode == 1) {
                        Ch[(size_t)m * Ntot + n] = h;
                        Ch[(size_t)n * Ntot + m] = h;
                    } else {
                        Ch[(size_t)n * Mtot + m] = h;
                    }
                }
            }
        }
    }
}

__device__ __forceinline__ void set_flags(int f0, int f1) {
    __threadfence();
    __syncthreads();
    if (threadIdx.x == 0) {
        atomicExch(g_flags + f0, 1);
        if (f1 >= 0) atomicExch(g_flags + f1, 1);
    }
}

// ---------------- vec chain inside mega: idx in [0,1002) ----------------
__device__ void vec_work(int idx,
                         const float* x, const float* Wq, const float* bq,
                         const float* Wk, const float* bk,
                         const float* Wv, const float* bv, float sscale)
{
    const int tid = threadIdx.x;
    if (idx < 384) {
        int dblk = idx & 7, c = (idx >> 3) & 15, z = idx >> 7;
        const float* W = (z == 0) ? x : (z == 1) ? Wk : Wq;
        const float* v = (z == 0) ? nullptr : (z == 1) ? bq : bk;
        const int R = (z == 0) ? N_TOK : D_DIM;
        const int chunk = R / 16;
        const int d = dblk * 256 + tid;
        float s = 0.0f;
        for (int r = c * chunk; r < (c + 1) * chunk; ++r)
            s = fmaf(v ? v[r] : 1.0f, W[(size_t)r * D_DIM + d], s);
        g_part[(size_t)(z * 16 + c) * D_DIM + d] = s;
        vdone(g_vcnt + 0);
    } else if (idx < 408) {
        vwait(g_vcnt + 0, 384);
        int i2 = idx - 384, dblk = i2 & 7, z = i2 >> 3;
        const int d = dblk * 256 + tid;
        float s = 0.0f;
        #pragma unroll
        for (int c = 0; c < 16; ++c) s += g_part[(size_t)(z * 16 + c) * D_DIM + d];
        if (z == 0) g_u[d] = s;
        else if (z == 1) g_w1[d] = s;
        else g_v2[d] = s * sscale;
        vdone(g_vcnt + 1);
    } else if (idx < 666) {
        vwait(g_vcnt + 1, 24);
        int i2 = idx - 408;
        if (i2 < 256) {
            const int lane = tid & 31, w = tid >> 5;
            const float* W; const float* v; float* outv; int rbase; bool addb = false;
            if (i2 < 128)      { W = x;  v = g_w1; outv = g_t;  rbase = i2 * 32; }
            else if (i2 < 192) { W = Wk; v = g_u;  outv = g_y;  rbase = (i2 - 128) * 32; }
            else               { W = Wv; v = g_u;  outv = g_v3; rbase = (i2 - 192) * 32; addb = true; }
            for (int rr = 0; rr < 4; ++rr) {
                const int i = rbase + w * 4 + rr;
                float s = 0.0f;
                for (int j = lane; j < D_DIM; j += 32)
                    s = fmaf(W[(size_t)i * D_DIM + j], v[j], s);
                #pragma unroll
                for (int o = 16; o; o >>= 1) s += __shfl_xor_sync(0xFFFFFFFFu, s, o);
                if (lane == 0) outv[i] = addb ? s + (float)N_TOK * bv[i] : s;
            }
        } else {
            __shared__ float red[256];
            float s = 0.0f;
            if (i2 == 256) for (int i = tid; i < D_DIM; i += 256) s = fmaf(g_u[i], g_w1[i], s);
            else           for (int i = tid; i < D_DIM; i += 256) s = fmaf(bk[i], bq[i], s);
            red[tid] = s;
            __syncthreads();
            for (int o = 128; o; o >>= 1) { if (tid < o) red[tid] += red[tid + o]; __syncthreads(); }
            if (tid == 0) g_sc[i2 - 256] = red[0];
        }
        vdone(g_vcnt + 2);
    } else if (idx < 922) {
        vwait(g_vcnt + 2, 258);
        int i2 = idx - 666, dblk = i2 & 7, c = (i2 >> 3) & 15, z = i2 >> 7;
        const float* W = z ? Wq : x;
        const float* v = z ? g_y : g_t;
        const int R = z ? D_DIM : N_TOK;
        const int chunk = R / 16;
        const int d = dblk * 256 + tid;
        float s = 0.0f;
        for (int r = c * chunk; r < (c + 1) * chunk; ++r)
            s = fmaf(v[r], W[(size_t)r * D_DIM + d], s);
        g_part[(size_t)(z * 16 + c) * D_DIM + d] = s;
        vdone(g_vcnt + 3);
    } else if (idx < 938) {
        vwait(g_vcnt + 3, 256);
        int i2 = idx - 922, dblk = i2 & 7, z = i2 >> 3;
        const int d = dblk * 256 + tid;
        float s = 0.0f;
        #pragma unroll
        for (int c = 0; c < 16; ++c) s += g_part[(size_t)(z * 16 + c) * D_DIM + d];
        if (z == 0) g_w2[d] = s;
        else g_v1[d] = s * sscale;
        vdone(g_vcnt + 4);
    } else {
        vwait(g_vcnt + 4, 16);
        int i2 = idx - 938;
        const int lane = tid & 31, w = tid >> 5;
        for (int rr = 0; rr < 4; ++rr) {
            const int i = i2 * 32 + w * 4 + rr;
            float acc = 0.0f;
            for (int j = lane; j < D_DIM; j += 32)
                acc = fmaf(Wv[(size_t)i * D_DIM + j], g_w2[j], acc);
            #pragma unroll
            for (int o = 16; o; o >>= 1) acc += __shfl_xor_sync(0xFFFFFFFFu, acc, o);
            if (lane == 0) g_r[i] = sscale * (acc + bv[i] * g_sc[0] + g_v3[i] * g_sc[1]);
        }
        vdone(g_vcnt + 5);
    }
}

// ---------------- MEGA: 5 GEMMs + vec chain, one launch ----------------
// [0,136)      G  = xT xT^T (sym, hi only)           -> flags [0,256)
// [136,392)    T1 = Wq^T Wk (hi+lo)                  -> flags [256,512)
// [392,1394)   vec chain (counters)
// [1394,1650)  T2 = T1 G  (hi+lo)  waits T1+G rows   -> flags [512,768)
// [1650,1906)  P  = s T2 Wv^T + rank2 (trans, hi)    waits T2 row + vecE -> flags [768,1024)
// [1906,2418)  out = x P + 1 r^T (fp32)              waits P(kb,j) + vecF
__global__ void __launch_bounds__(256, 2) mega(
    const float* __restrict__ x, const float* __restrict__ Wq, const float* __restrict__ bq,
    const float* __restrict__ Wk, const float* __restrict__ bk,
    const float* __restrict__ Wv, const float* __restrict__ bv,
    const __half* __restrict__ xTh, const __half* __restrict__ xTl,
    __half* __restrict__ gh,
    const __half* __restrict__ wqTh, const __half* __restrict__ wqTl,
    const __half* __restrict__ wkTh,
    __half* __restrict__ t1h, __half* __restrict__ t1l,
    __half* __restrict__ t2h, __half* __restrict__ t2l,
    const __half* __restrict__ wvh,
    __half* __restrict__ pTh,
    const float* v1, const float* v2, const float* v3,
    const __half* __restrict__ xh, const __half* __restrict__ xl,
    float* __restrict__ outp, const float* r, float s)
{
    extern __shared__ char dyn[];
    const int bid = blockIdx.x;

    if (bid < 136) {                        // G (symmetric)
        int idx = bid, by = 0;
        while (idx >= 16 - by) { idx -= 16 - by; ++by; }
        int bx = by + idx;
        gemm_body(xTh, xTl, xTh, gh, nullptr, nullptr,
                  nullptr, nullptr, nullptr, nullptr, nullptr,
                  by * 128, bx * 128, D_DIM, D_DIM, N_TOK, 1.0f, 1,
                  nullptr, nullptr, 1, dyn);
        set_flags(by * 16 + bx, bx * 16 + by);
    } else if (bid < 392) {                 // T1 (hi+lo)
        int idx = bid - 136;
        gemm_body(wqTh, wqTl, wkTh, t1h, t1l, nullptr,
                  nullptr, nullptr, nullptr, nullptr, nullptr,
                  (idx >> 4) * 128, (idx & 15) * 128, D_DIM, D_DIM, D_DIM, 1.0f, 0,
                  nullptr, nullptr, 1, dyn);
        set_flags(256 + idx, -1);
    } else if (bid < 1394) {                // vec chain
        vec_work(bid - 392, x, Wq, bq, Wk, bk, Wv, bv, s);
    } else if (bid < 1650) {                // T2 = T1 G (hi+lo)
        int idx = bid - 1394;
        int m = idx >> 4, n = idx & 15;
        gemm_body(t1h, t1l, gh, t2h, t2l, nullptr,
                  nullptr, nullptr, nullptr, nullptr, nullptr,
                  m * 128, n * 128, D_DIM, D_DIM, D_DIM, 1.0f, 0,
                  g_flags + 256 + m * 16, g_flags + n * 16, 1, dyn);
        set_flags(512 + idx, -1);
    } else if (bid < 1906) {                // P (trans, hi only, + rank2)
        int idx = bid - 1650;
        int a = idx >> 4, j = idx & 15;
        vwait(g_vcnt + 4, 16);              // v1/v2/v3 ready
        gemm_body(t2h, t2l, wvh, pTh, nullptr, nullptr,
                  v1, bv, v2, v3, nullptr,
                  a * 128, j * 128, D_DIM, D_DIM, D_DIM, s, 2,
                  nullptr, g_flags + 512 + a * 16, 1, dyn);
        set_flags(768 + idx, -1);
    } else {                                // out (fp32)
        int idx = bid - 1906;
        int t = idx >> 4, j = idx & 15;
        vwait(g_vcnt + 5, 64);              // r ready
        gemm_body(xh, xl, pTh, nullptr, nullptr, outp,
                  nullptr, nullptr, nullptr, nullptr, r,
                  t * 128, j * 128, N_TOK, D_DIM, D_DIM, 1.0f, 3,
                  nullptr, g_flags + 768 + j, 16, dyn);
    }
}

// ---------------- preprocessing (one launch; bid 0 also zeroes flags) ----------------
__global__ void prep_all(const float* __restrict__ x,
                         __half* __restrict__ xh, __half* __restrict__ xlo,
                         __half* __restrict__ xth, __half* __restrict__ xtl,
                         const float* __restrict__ Wq, __half* __restrict__ wqTh, __half* __restrict__ wqTl,
                         const float* __restrict__ Wk, __half* __restrict__ wkTh,
                         const float* __restrict__ Wv, __half* __restrict__ wvh)
{
    __shared__ float t[32][33];
    const int tx = threadIdx.x, ty = threadIdx.y;  // 32 x 8
    const int bid = blockIdx.x;
    const int tid = ty * 32 + tx;
    if (bid == 0) {
        for (int i = tid; i < 1024; i += 256) g_flags[i] = 0;
        if (tid < 8) g_vcnt[tid] = 0;
    }
    if (bid < 8192) {                       // x: split + transposed split (hi+lo both)
        int bx = (bid & 63) * 32, by = (bid >> 6) * 32;
        #pragma unroll
        for (int j = 0; j < 32; j += 8) {
            size_t gi = (size_t)(by + ty + j) * D_DIM + bx + tx;
            float v = x[gi];
            t[ty + j][tx] = v;
            __half h = __float2half(v);
            xh[gi] = h;
            xlo[gi] = __float2half(v - __half2float(h));
        }
        __syncthreads();
        #pragma unroll
        for (int j = 0; j < 32; j += 8) {
            float v = t[tx][ty + j];
            size_t o = (size_t)(bx + ty + j) * N_TOK + by + tx;
            __half h = __float2half(v);
            xth[o] = h;
            xtl[o] = __float2half(v - __half2float(h));
        }
        return;
    }
    const int w = bid - 8192;
    const int z = w >> 12;
    const int rem = w & 4095;
    const int bx = (rem & 63) * 32, by = (rem >> 6) * 32;
    const float* in = (z == 0) ? Wq : (z == 1) ? Wk : Wv;
    if (z == 2) {                           // Wv: straight split, hi only
        #pragma unroll
        for (int j = 0; j < 32; j += 8) {
            size_t gi = (size_t)(by + ty + j) * D_DIM + bx + tx;
            wvh[gi] = __float2half(in[gi]);
        }
        return;
    }
    #pragma unroll
    for (int j = 0; j < 32; j += 8)
        t[ty + j][tx] = in[(size_t)(by + ty + j) * D_DIM + bx + tx];
    __syncthreads();
    if (z == 0) {                           // WqT: hi+lo
        #pragma unroll
        for (int j = 0; j < 32; j += 8) {
            float v = t[tx][ty + j];
            size_t o = (size_t)(bx + ty + j) * D_DIM + by + tx;
            __half h = __float2half(v);
            wqTh[o] = h;
            wqTl[o] = __float2half(v - __half2float(h));
        }
    } else {                                // WkT: hi only
        #pragma unroll
        for (int j = 0; j < 32; j += 8) {
            size_t o = (size_t)(bx + ty + j) * D_DIM + by + tx;
            wkTh[o] = __float2half(t[tx][ty + j]);
        }
    }
}

// ---------------- launcher ----------------
extern "C" void kernel_launch(void* const* d_in, const int* in_sizes, int n_in,
                              void* d_out, int out_size)
{
    const float* x  = (const float*)d_in[0];
    const float* Wq = (const float*)d_in[1];
    const float* bq = (const float*)d_in[2];
    const float* Wk = (const float*)d_in[3];
    const float* bk = (const float*)d_in[4];
    const float* Wv = (const float*)d_in[5];
    const float* bv = (const float*)d_in[6];
    float* out = (float*)d_out;

    __half *xT_hi, *xT_lo, *x_hi, *x_lo, *wqT_hi, *wqT_lo, *wkT_hi, *wv_hi;
    __half *gh, *t1h, *t1l, *t2h, *t2l, *pTh;
    float *v1, *v2, *v3, *r;
    cudaGetSymbolAddress((void**)&xT_hi, g_xT_hi);  cudaGetSymbolAddress((void**)&xT_lo, g_xT_lo);
    cudaGetSymbolAddress((void**)&x_hi, g_x_hi);    cudaGetSymbolAddress((void**)&x_lo, g_x_lo);
    cudaGetSymbolAddress((void**)&wqT_hi, g_wqT_hi);cudaGetSymbolAddress((void**)&wqT_lo, g_wqT_lo);
    cudaGetSymbolAddress((void**)&wkT_hi, g_wkT_hi);
    cudaGetSymbolAddress((void**)&wv_hi, g_wv_hi);
    cudaGetSymbolAddress((void**)&gh, g_g_hi);
    cudaGetSymbolAddress((void**)&t1h, g_t1_hi);    cudaGetSymbolAddress((void**)&t1l, g_t1_lo);
    cudaGetSymbolAddress((void**)&t2h, g_t2_hi);    cudaGetSymbolAddress((void**)&t2l, g_t2_lo);
    cudaGetSymbolAddress((void**)&pTh, g_pT_hi);
    cudaGetSymbolAddress((void**)&v1, g_v1);        cudaGetSymbolAddress((void**)&v2, g_v2);
    cudaGetSymbolAddress((void**)&v3, g_v3);        cudaGetSymbolAddress((void**)&r, g_r);

    cudaFuncSetAttribute(mega, cudaFuncAttributeMaxDynamicSharedMemorySize, SMEM_DYN);

    const float s = 1.0f / sqrtf((float)D_DIM);

    // prep (bid 0 zeroes flags/counters)
    prep_all<<<8192 + 3 * 4096, dim3(32, 8)>>>(x, x_hi, x_lo, xT_hi, xT_lo,
                                               Wq, wqT_hi, wqT_lo,
                                               Wk, wkT_hi,
                                               Wv, wv_hi);
    // everything else in one DAG launch
    mega<<<2418, 256, SMEM_DYN>>>(x, Wq, bq, Wk, bk, Wv, bv,
                                  xT_hi, xT_lo, gh,
                                  wqT_hi, wqT_lo, wkT_hi,
                                  t1h, t1l, t2h, t2l,
                                  wv_hi, pTh,
                                  v1, v2, v3,
                                  x_hi, x_lo, out, r, s);
}

// round 11
// speedup vs baseline: 1.8854x; 1.1466x over previous
#include <cuda_runtime.h>
#include <cuda_fp16.h>
#include <math.h>
#include <stdint.h>

#define D_DIM 2048
#define N_TOK 4096

// ---------------- device scratch (allocation-free rule) ----------------
__device__ __align__(128) __half g_xT_hi[(size_t)D_DIM * N_TOK];
__device__ __align__(128) __half g_xT_lo[(size_t)D_DIM * N_TOK];
__device__ __align__(128) __half g_x_hi [(size_t)N_TOK * D_DIM];
__device__ __align__(128) __half g_wqT_hi[(size_t)D_DIM * D_DIM];
__device__ __align__(128) __half g_wqT_lo[(size_t)D_DIM * D_DIM];
__device__ __align__(128) __half g_wkT_hi[(size_t)D_DIM * D_DIM];
__device__ __align__(128) __half g_wv_hi[(size_t)D_DIM * D_DIM];
__device__ __align__(128) __half g_g_hi [(size_t)D_DIM * D_DIM];
__device__ __align__(128) __half g_t1_hi[(size_t)D_DIM * D_DIM];
__device__ __align__(128) __half g_t1_lo[(size_t)D_DIM * D_DIM];
__device__ __align__(128) __half g_t2_hi[(size_t)D_DIM * D_DIM];
__device__ __align__(128) __half g_t2_lo[(size_t)D_DIM * D_DIM];
__device__ __align__(128) __half g_pT_hi[(size_t)D_DIM * D_DIM];
__device__ float g_part[48 * D_DIM];
__device__ float g_u[D_DIM], g_w1[D_DIM], g_w2[D_DIM];
__device__ float g_v1[D_DIM], g_v2[D_DIM], g_v3[D_DIM], g_r[D_DIM];
__device__ float g_t[N_TOK], g_y[D_DIM];
__device__ float g_sc[2];
// tile flags: [0,256) G, [256,512) T1, [512,768) T2, [768,1024) P
__device__ int g_flags[1024];
// vec-stage counters: 0:A 1:B 2:C 3:D 4:E 5:F
__device__ int g_vcnt[8];

// ---------------- helpers ----------------
__device__ __forceinline__ uint32_t s2u(const void* p) {
    uint32_t a;
    asm("{ .reg .u64 t; cvta.to.shared.u64 t, %1; cvt.u32.u64 %0, t; }" : "=r"(a) : "l"(p));
    return a;
}
__device__ __forceinline__ void cp16(uint32_t dst, const void* src) {
    asm volatile("cp.async.cg.shared.global [%0], [%1], 16;" :: "r"(dst), "l"(src) : "memory");
}
__device__ __forceinline__ void cp_commit() {
    asm volatile("cp.async.commit_group;" ::: "memory");
}
template<int N>
__device__ __forceinline__ void cp_wait() {
    asm volatile("cp.async.wait_group %0;" :: "n"(N) : "memory");
}
__device__ __forceinline__ void ldsm4(uint32_t* r, uint32_t addr) {
    asm volatile("ldmatrix.sync.aligned.m8n8.x4.shared.b16 {%0,%1,%2,%3}, [%4];"
                 : "=r"(r[0]), "=r"(r[1]), "=r"(r[2]), "=r"(r[3]) : "r"(addr));
}
__device__ __forceinline__ void mma16816(float* d, const uint32_t* a, uint32_t b0, uint32_t b1) {
    asm volatile(
        "mma.sync.aligned.m16n8k16.row.col.f32.f16.f16.f32 "
        "{%0,%1,%2,%3}, {%4,%5,%6,%7}, {%8,%9}, {%0,%1,%2,%3};"
        : "+f"(d[0]), "+f"(d[1]), "+f"(d[2]), "+f"(d[3])
        : "r"(a[0]), "r"(a[1]), "r"(a[2]), "r"(a[3]), "r"(b0), "r"(b1));
}
__device__ __forceinline__ void wait_kblk(volatile int* wA, volatile int* wB, int sB,
                                          int kb, int tid) {
    if (tid == 0) {
        if (wA) while (wA[kb] == 0) __nanosleep(128);
        while (wB[kb * sB] == 0) __nanosleep(128);
        __threadfence();
    }
    __syncthreads();
}
__device__ __forceinline__ void vwait(volatile int* cnt, int target) {
    if (threadIdx.x == 0) {
        while (*cnt < target) __nanosleep(256);
        __threadfence();
    }
    __syncthreads();
}
__device__ __forceinline__ void vdone(int* cnt) {
    __threadfence();
    __syncthreads();
    if (threadIdx.x == 0) atomicAdd(cnt, 1);
}

// ---------------- fp16 single-split HMMA GEMM body ----------------
// C[m,n] = alpha * sum_k (Ah [+ Al])[m,k] * Bh[n,k]     (Al == nullptr => 1 pass)
// mode 0 NORM : Ch[m*Ntot+n]=hi, Cl[...]=lo   (both planes)
// mode 1 SYM  : hi only, both mirror positions
// mode 2 TRANS: Ch[n*Mtot+m] = hi(val + cA[m]cB[n] + cC[m]cD[n])  (hi only)
// mode 3 FINAL: Cf[m*Ntot+n] = val*alpha + biascol[n]   (fp32)
// wB != null => progressive waits per 128-wide K-block (wA optional, stride 1).
#define PLANE_B 10240
#define STAGE_B 30720
static const int SMEM_DYN = 2 * STAGE_B;

__device__ __forceinline__ void gemm_body(
    const __half* __restrict__ Ah, const __half* __restrict__ Al,
    const __half* __restrict__ Bh,
    __half* Ch, __half* Cl, float* Cf,
    const float* cA, const float* cB, const float* cC, const float* cD,
    const float* biascol,
    int bm0, int bn0, int Mtot, int Ntot, int Kd, float alpha, int mode,
    volatile int* wA, volatile int* wB, int sB,
    char* dyn)
{
    const uint32_t su = s2u(dyn);
    const int tid  = threadIdx.x;
    const int wid  = tid >> 5, lane = tid & 31;
    const int wm0  = (wid & 1) * 64;
    const int wn0  = (wid >> 1) * 32;
    const bool two_pass = (Al != nullptr);
    const int nslot = two_pass ? 6 : 4;     // 16B transfers per thread per stage

    // cp.async schedule: slots cover planes {0:Ah [,1:Al], last:Bh}
    const __half* gsrc[6];
    uint32_t doff[6];
    #pragma unroll
    for (int i = 0; i < 6; ++i) {
        if (i >= nslot) break;
        int idx   = i * 256 + tid;
        int pl    = idx >> 9;               // 0..nslot/2-1
        int plane = (pl == (nslot >> 1) - 1) ? 2 : pl;   // last slot -> B plane
        int row   = (idx >> 2) & 127;
        int seg   = idx & 3;
        const __half* base = (plane == 0) ? Ah : (plane == 1) ? Al : Bh;
        int grow = (plane < 2 ? bm0 : bn0) + row;
        gsrc[i] = base + (size_t)grow * Kd + seg * 8;
        doff[i] = (uint32_t)(plane * PLANE_B + row * 80 + seg * 16);
    }

    const int NC = Kd / 32;
    if (wB) wait_kblk(wA, wB, sB, 0, tid);
    #pragma unroll
    for (int i = 0; i < 6; ++i) { if (i >= nslot) break; cp16(su + doff[i], gsrc[i]); }
    cp_commit();

    float acc[4][4][4];
    #pragma unroll
    for (int im = 0; im < 4; ++im)
        #pragma unroll
        for (int in = 0; in < 4; ++in)
            #pragma unroll
            for (int j = 0; j < 4; ++j) acc[im][in][j] = 0.0f;

    const int a_rl = ((lane >> 3) & 1) * 8 + (lane & 7);
    const int a_ch = ((lane >> 4) & 1) * 16;
    const int b_rl = lane;

    for (int c = 0; c < NC; ++c) {
        cp_wait<0>();
        __syncthreads();
        if (c + 1 < NC) {
            if (wB && (((c + 1) & 3) == 0))
                wait_kblk(wA, wB, sB, (c + 1) >> 2, tid);
            const uint32_t sd = su + ((c + 1) & 1) * STAGE_B;
            const size_t koff = (size_t)(c + 1) * 32;
            #pragma unroll
            for (int i = 0; i < 6; ++i) { if (i >= nslot) break; cp16(sd + doff[i], gsrc[i] + koff); }
            cp_commit();
        }
        const uint32_t sb = su + (c & 1) * STAGE_B;
        const uint32_t aBase = sb + (wm0 + a_rl) * 80 + a_ch;
        const uint32_t bBase = sb + (wn0 + b_rl) * 80 + 2 * PLANE_B;

        #pragma unroll
        for (int kk = 0; kk < 2; ++kk) {
            const uint32_t kO = kk * 32;
            uint32_t a[4][4], b0[4], b1[4];
            // B fragments: loaded once, reused across passes
            ldsm4(b0, bBase + kO);
            ldsm4(b1, bBase + kO + 16);
            // pass 1: A_hi
            #pragma unroll
            for (int im = 0; im < 4; ++im)
                ldsm4(a[im], aBase + 0 * PLANE_B + im * (16 * 80) + kO);
            #pragma unroll
            for (int im = 0; im < 4; ++im)
                #pragma unroll
                for (int in = 0; in < 4; ++in)
                    mma16816(acc[im][in], a[im], b0[in], b1[in]);
            // pass 2: A_lo (optional)
            if (two_pass) {
                #pragma unroll
                for (int im = 0; im < 4; ++im)
                    ldsm4(a[im], aBase + 1 * PLANE_B + im * (16 * 80) + kO);
                #pragma unroll
                for (int im = 0; im < 4; ++im)
                    #pragma unroll
                    for (int in = 0; in < 4; ++in)
                        mma16816(acc[im][in], a[im], b0[in], b1[in]);
            }
        }
    }

    // ---- epilogue ----
    const int mbase = bm0 + wm0 + (lane >> 2);
    const int nbase = bn0 + wn0 + (lane & 3) * 2;
    #pragma unroll
    for (int im = 0; im < 4; ++im) {
        #pragma unroll
        for (int in = 0; in < 4; ++in) {
            const float* d = acc[im][in];
            const int n0 = nbase + in * 8;
            if (mode == 3) {
                const int m0 = mbase + im * 16;
                float2 v0, v1;
                v0.x = d[0] * alpha + biascol[n0];
                v0.y = d[1] * alpha + biascol[n0 + 1];
                v1.x = d[2] * alpha + biascol[n0];
                v1.y = d[3] * alpha + biascol[n0 + 1];
                *(float2*)(Cf + (size_t)m0 * Ntot + n0)       = v0;
                *(float2*)(Cf + (size_t)(m0 + 8) * Ntot + n0) = v1;
            } else {
                #pragma unroll
                for (int j = 0; j < 4; ++j) {
                    const int m = mbase + im * 16 + (j >> 1) * 8;
                    const int n = n0 + (j & 1);
                    float v = d[j] * alpha;
                    if (mode == 2) v += cA[m] * cB[n] + cC[m] * cD[n];
                    __half h = __float2half(v);
                    if (mode == 0) {
                        size_t o = (size_t)m * Ntot + n;
                        Ch[o] = h;
                        Cl[o] = __float2half(v - __half2float(h));
                    } else if (mode == 1) {
                        Ch[(size_t)m * Ntot + n] = h;
                        Ch[(size_t)n * Ntot + m] = h;
                    } else {
                        Ch[(size_t)n * Mtot + m] = h;
                    }
                }
            }
        }
    }
}

__device__ __forceinline__ void set_flags(int f0, int f1) {
    __threadfence();
    __syncthreads();
    if (threadIdx.x == 0) {
        atomicExch(g_flags + f0, 1);
        if (f1 >= 0) atomicExch(g_flags + f1, 1);
    }
}

// ---------------- vec chain inside mega: idx in [0,1002) ----------------
__device__ void vec_work(int idx,
                         const float* x, const float* Wq, const float* bq,
                         const float* Wk, const float* bk,
                         const float* Wv, const float* bv, float sscale)
{
    const int tid = threadIdx.x;
    if (idx < 384) {
        int dblk = idx & 7, c = (idx >> 3) & 15, z = idx >> 7;
        const float* W = (z == 0) ? x : (z == 1) ? Wk : Wq;
        const float* v = (z == 0) ? nullptr : (z == 1) ? bq : bk;
        const int R = (z == 0) ? N_TOK : D_DIM;
        const int chunk = R / 16;
        const int d = dblk * 256 + tid;
        float s = 0.0f;
        for (int r = c * chunk; r < (c + 1) * chunk; ++r)
            s = fmaf(v ? v[r] : 1.0f, W[(size_t)r * D_DIM + d], s);
        g_part[(size_t)(z * 16 + c) * D_DIM + d] = s;
        vdone(g_vcnt + 0);
    } else if (idx < 408) {
        vwait(g_vcnt + 0, 384);
        int i2 = idx - 384, dblk = i2 & 7, z = i2 >> 3;
        const int d = dblk * 256 + tid;
        float s = 0.0f;
        #pragma unroll
        for (int c = 0; c < 16; ++c) s += g_part[(size_t)(z * 16 + c) * D_DIM + d];
        if (z == 0) g_u[d] = s;
        else if (z == 1) g_w1[d] = s;
        else g_v2[d] = s * sscale;
        vdone(g_vcnt + 1);
    } else if (idx < 666) {
        vwait(g_vcnt + 1, 24);
        int i2 = idx - 408;
        if (i2 < 256) {
            const int lane = tid & 31, w = tid >> 5;
            const float* W; const float* v; float* outv; int rbase; bool addb = false;
            if (i2 < 128)      { W = x;  v = g_w1; outv = g_t;  rbase = i2 * 32; }
            else if (i2 < 192) { W = Wk; v = g_u;  outv = g_y;  rbase = (i2 - 128) * 32; }
            else               { W = Wv; v = g_u;  outv = g_v3; rbase = (i2 - 192) * 32; addb = true; }
            for (int rr = 0; rr < 4; ++rr) {
                const int i = rbase + w * 4 + rr;
                float s = 0.0f;
                for (int j = lane; j < D_DIM; j += 32)
                    s = fmaf(W[(size_t)i * D_DIM + j], v[j], s);
                #pragma unroll
                for (int o = 16; o; o >>= 1) s += __shfl_xor_sync(0xFFFFFFFFu, s, o);
                if (lane == 0) outv[i] = addb ? s + (float)N_TOK * bv[i] : s;
            }
        } else {
            __shared__ float red[256];
            float s = 0.0f;
            if (i2 == 256) for (int i = tid; i < D_DIM; i += 256) s = fmaf(g_u[i], g_w1[i], s);
            else           for (int i = tid; i < D_DIM; i += 256) s = fmaf(bk[i], bq[i], s);
            red[tid] = s;
            __syncthreads();
            for (int o = 128; o; o >>= 1) { if (tid < o) red[tid] += red[tid + o]; __syncthreads(); }
            if (tid == 0) g_sc[i2 - 256] = red[0];
        }
        vdone(g_vcnt + 2);
    } else if (idx < 922) {
        vwait(g_vcnt + 2, 258);
        int i2 = idx - 666, dblk = i2 & 7, c = (i2 >> 3) & 15, z = i2 >> 7;
        const float* W = z ? Wq : x;
        const float* v = z ? g_y : g_t;
        const int R = z ? D_DIM : N_TOK;
        const int chunk = R / 16;
        const int d = dblk * 256 + tid;
        float s = 0.0f;
        for (int r = c * chunk; r < (c + 1) * chunk; ++r)
            s = fmaf(v[r], W[(size_t)r * D_DIM + d], s);
        g_part[(size_t)(z * 16 + c) * D_DIM + d] = s;
        vdone(g_vcnt + 3);
    } else if (idx < 938) {
        vwait(g_vcnt + 3, 256);
        int i2 = idx - 922, dblk = i2 & 7, z = i2 >> 3;
        const int d = dblk * 256 + tid;
        float s = 0.0f;
        #pragma unroll
        for (int c = 0; c < 16; ++c) s += g_part[(size_t)(z * 16 + c) * D_DIM + d];
        if (z == 0) g_w2[d] = s;
        else g_v1[d] = s * sscale;
        vdone(g_vcnt + 4);
    } else {
        vwait(g_vcnt + 4, 16);
        int i2 = idx - 938;
        const int lane = tid & 31, w = tid >> 5;
        for (int rr = 0; rr < 4; ++rr) {
            const int i = i2 * 32 + w * 4 + rr;
            float acc = 0.0f;
            for (int j = lane; j < D_DIM; j += 32)
                acc = fmaf(Wv[(size_t)i * D_DIM + j], g_w2[j], acc);
            #pragma unroll
            for (int o = 16; o; o >>= 1) acc += __shfl_xor_sync(0xFFFFFFFFu, acc, o);
            if (lane == 0) g_r[i] = sscale * (acc + bv[i] * g_sc[0] + g_v3[i] * g_sc[1]);
        }
        vdone(g_vcnt + 5);
    }
}

// ---------------- MEGA: 5 GEMMs + vec chain, one launch ----------------
// [0,136)      G  = xT xT^T (sym, hi out, 2-pass A)  -> flags [0,256)
// [136,392)    T1 = Wq^T Wk (hi+lo out, 2-pass A)    -> flags [256,512)
// [392,1394)   vec chain (counters)
// [1394,1650)  T2 = T1 G  (hi+lo out, 2-pass A)  waits T1+G rows -> flags [512,768)
// [1650,1906)  P  = s T2 Wv^T + rank2 (trans, 2-pass A) waits T2 row + vecE -> flags [768,1024)
// [1906,2418)  out = x_hi P (fp32, 1-pass A)       waits P(kb,j) + vecF
__global__ void __launch_bounds__(256, 2) mega(
    const float* __restrict__ x, const float* __restrict__ Wq, const float* __restrict__ bq,
    const float* __restrict__ Wk, const float* __restrict__ bk,
    const float* __restrict__ Wv, const float* __restrict__ bv,
    const __half* __restrict__ xTh, const __half* __restrict__ xTl,
    __half* __restrict__ gh,
    const __half* __restrict__ wqTh, const __half* __restrict__ wqTl,
    const __half* __restrict__ wkTh,
    __half* __restrict__ t1h, __half* __restrict__ t1l,
    __half* __restrict__ t2h, __half* __restrict__ t2l,
    const __half* __restrict__ wvh,
    __half* __restrict__ pTh,
    const float* v1, const float* v2, const float* v3,
    const __half* __restrict__ xh,
    float* __restrict__ outp, const float* r, float s)
{
    extern __shared__ char dyn[];
    const int bid = blockIdx.x;

    if (bid < 136) {                        // G (symmetric)
        int idx = bid, by = 0;
        while (idx >= 16 - by) { idx -= 16 - by; ++by; }
        int bx = by + idx;
        gemm_body(xTh, xTl, xTh, gh, nullptr, nullptr,
                  nullptr, nullptr, nullptr, nullptr, nullptr,
                  by * 128, bx * 128, D_DIM, D_DIM, N_TOK, 1.0f, 1,
                  nullptr, nullptr, 1, dyn);
        set_flags(by * 16 + bx, bx * 16 + by);
    } else if (bid < 392) {                 // T1 (hi+lo)
        int idx = bid - 136;
        gemm_body(wqTh, wqTl, wkTh, t1h, t1l, nullptr,
                  nullptr, nullptr, nullptr, nullptr, nullptr,
                  (idx >> 4) * 128, (idx & 15) * 128, D_DIM, D_DIM, D_DIM, 1.0f, 0,
                  nullptr, nullptr, 1, dyn);
        set_flags(256 + idx, -1);
    } else if (bid < 1394) {                // vec chain
        vec_work(bid - 392, x, Wq, bq, Wk, bk, Wv, bv, s);
    } else if (bid < 1650) {                // T2 = T1 G (hi+lo)
        int idx = bid - 1394;
        int m = idx >> 4, n = idx & 15;
        gemm_body(t1h, t1l, gh, t2h, t2l, nullptr,
                  nullptr, nullptr, nullptr, nullptr, nullptr,
                  m * 128, n * 128, D_DIM, D_DIM, D_DIM, 1.0f, 0,
                  g_flags + 256 + m * 16, g_flags + n * 16, 1, dyn);
        set_flags(512 + idx, -1);
    } else if (bid < 1906) {                // P (trans, hi only, + rank2)
        int idx = bid - 1650;
        int a = idx >> 4, j = idx & 15;
        vwait(g_vcnt + 4, 16);              // v1/v2/v3 ready
        gemm_body(t2h, t2l, wvh, pTh, nullptr, nullptr,
                  v1, bv, v2, v3, nullptr,
                  a * 128, j * 128, D_DIM, D_DIM, D_DIM, s, 2,
                  nullptr, g_flags + 512 + a * 16, 1, dyn);
        set_flags(768 + idx, -1);
    } else {                                // out (fp32, SINGLE pass: x_hi only)
        int idx = bid - 1906;
        int t = idx >> 4, j = idx & 15;
        vwait(g_vcnt + 5, 64);              // r ready
        gemm_body(xh, nullptr, pTh, nullptr, nullptr, outp,
                  nullptr, nullptr, nullptr, nullptr, r,
                  t * 128, j * 128, N_TOK, D_DIM, D_DIM, 1.0f, 3,
                  nullptr, g_flags + 768 + j, 16, dyn);
    }
}

// ---------------- preprocessing (one launch; bid 0 also zeroes flags) ----------------
__global__ void prep_all(const float* __restrict__ x,
                         __half* __restrict__ xh,
                         __half* __restrict__ xth, __half* __restrict__ xtl,
                         const float* __restrict__ Wq, __half* __restrict__ wqTh, __half* __restrict__ wqTl,
                         const float* __restrict__ Wk, __half* __restrict__ wkTh,
                         const float* __restrict__ Wv, __half* __restrict__ wvh)
{
    __shared__ float t[32][33];
    const int tx = threadIdx.x, ty = threadIdx.y;  // 32 x 8
    const int bid = blockIdx.x;
    const int tid = ty * 32 + tx;
    if (bid == 0) {
        for (int i = tid; i < 1024; i += 256) g_flags[i] = 0;
        if (tid < 8) g_vcnt[tid] = 0;
    }
    if (bid < 8192) {                       // x: straight hi + transposed hi/lo
        int bx = (bid & 63) * 32, by = (bid >> 6) * 32;
        #pragma unroll
        for (int j = 0; j < 32; j += 8) {
            size_t gi = (size_t)(by + ty + j) * D_DIM + bx + tx;
            float v = x[gi];
            t[ty + j][tx] = v;
            xh[gi] = __float2half(v);
        }
        __syncthreads();
        #pragma unroll
        for (int j = 0; j < 32; j += 8) {
            float v = t[tx][ty + j];
            size_t o = (size_t)(bx + ty + j) * N_TOK + by + tx;
            __half h = __float2half(v);
            xth[o] = h;
            xtl[o] = __float2half(v - __half2float(h));
        }
        return;
    }
    const int w = bid - 8192;
    const int z = w >> 12;
    const int rem = w & 4095;
    const int bx = (rem & 63) * 32, by = (rem >> 6) * 32;
    const float* in = (z == 0) ? Wq : (z == 1) ? Wk : Wv;
    if (z == 2) {                           // Wv: hi only
        #pragma unroll
        for (int j = 0; j < 32; j += 8) {
            size_t gi = (size_t)(by + ty + j) * D_DIM + bx + tx;
            wvh[gi] = __float2half(in[gi]);
        }
        return;
    }
    #pragma unroll
    for (int j = 0; j < 32; j += 8)
        t[ty + j][tx] = in[(size_t)(by + ty + j) * D_DIM + bx + tx];
    __syncthreads();
    if (z == 0) {                           // WqT: hi+lo
        #pragma unroll
        for (int j = 0; j < 32; j += 8) {
            float v = t[tx][ty + j];
            size_t o = (size_t)(bx + ty + j) * D_DIM + by + tx;
            __half h = __float2half(v);
            wqTh[o] = h;
            wqTl[o] = __float2half(v - __half2float(h));
        }
    } else {                                // WkT: hi only
        #pragma unroll
        for (int j = 0; j < 32; j += 8) {
            size_t o = (size_t)(bx + ty + j) * D_DIM + by + tx;
            wkTh[o] = __float2half(t[tx][ty + j]);
        }
    }
}

// ---------------- launcher ----------------
extern "C" void kernel_launch(void* const* d_in, const int* in_sizes, int n_in,
                              void* d_out, int out_size)
{
    const float* x  = (const float*)d_in[0];
    const float* Wq = (const float*)d_in[1];
    const float* bq = (const float*)d_in[2];
    const float* Wk = (const float*)d_in[3];
    const float* bk = (const float*)d_in[4];
    const float* Wv = (const float*)d_in[5];
    const float* bv = (const float*)d_in[6];
    float* out = (float*)d_out;

    __half *xT_hi, *xT_lo, *x_hi, *wqT_hi, *wqT_lo, *wkT_hi, *wv_hi;
    __half *gh, *t1h, *t1l, *t2h, *t2l, *pTh;
    float *v1, *v2, *v3, *r;
    cudaGetSymbolAddress((void**)&xT_hi, g_xT_hi);  cudaGetSymbolAddress((void**)&xT_lo, g_xT_lo);
    cudaGetSymbolAddress((void**)&x_hi, g_x_hi);
    cudaGetSymbolAddress((void**)&wqT_hi, g_wqT_hi);cudaGetSymbolAddress((void**)&wqT_lo, g_wqT_lo);
    cudaGetSymbolAddress((void**)&wkT_hi, g_wkT_hi);
    cudaGetSymbolAddress((void**)&wv_hi, g_wv_hi);
    cudaGetSymbolAddress((void**)&gh, g_g_hi);
    cudaGetSymbolAddress((void**)&t1h, g_t1_hi);    cudaGetSymbolAddress((void**)&t1l, g_t1_lo);
    cudaGetSymbolAddress((void**)&t2h, g_t2_hi);    cudaGetSymbolAddress((void**)&t2l, g_t2_lo);
    cudaGetSymbolAddress((void**)&pTh, g_pT_hi);
    cudaGetSymbolAddress((void**)&v1, g_v1);        cudaGetSymbolAddress((void**)&v2, g_v2);
    cudaGetSymbolAddress((void**)&v3, g_v3);        cudaGetSymbolAddress((void**)&r, g_r);

    cudaFuncSetAttribute(mega, cudaFuncAttributeMaxDynamicSharedMemorySize, SMEM_DYN);

    const float s = 1.0f / sqrtf((float)D_DIM);

    // prep (bid 0 zeroes flags/counters)
    prep_all<<<8192 + 3 * 4096, dim3(32, 8)>>>(x, x_hi, xT_hi, xT_lo,
                                               Wq, wqT_hi, wqT_lo,
                                               Wk, wkT_hi,
                                               Wv, wv_hi);
    // everything else in one DAG launch
    mega<<<2418, 256, SMEM_DYN>>>(x, Wq, bq, Wk, bk, Wv, bv,
                                  xT_hi, xT_lo, gh,
                                  wqT_hi, wqT_lo, wkT_hi,
                                  t1h, t1l, t2h, t2l,
                                  wv_hi, pTh,
                                  v1, v2, v3,
                                  x_hi, out, r, s);
}

// round 12
// speedup vs baseline: 2.6315x; 1.3957x over previous
#include <cuda_runtime.h>
#include <cuda_fp16.h>
#include <math.h>
#include <stdint.h>

#define D_DIM 2048
#define N_TOK 4096

// ---------------- device scratch (allocation-free rule) ----------------
__device__ __align__(128) __half g_xT_hi[(size_t)D_DIM * N_TOK];
__device__ __align__(128) __half g_x_hi [(size_t)N_TOK * D_DIM];
__device__ __align__(128) __half g_wqT_hi[(size_t)D_DIM * D_DIM];
__device__ __align__(128) __half g_wkT_hi[(size_t)D_DIM * D_DIM];
__device__ __align__(128) __half g_wv_hi[(size_t)D_DIM * D_DIM];
__device__ __align__(128) __half g_g_hi [(size_t)D_DIM * D_DIM];
__device__ __align__(128) __half g_t1_hi[(size_t)D_DIM * D_DIM];
__device__ __align__(128) __half g_t2_hi[(size_t)D_DIM * D_DIM];
__device__ __align__(128) __half g_pT_hi[(size_t)D_DIM * D_DIM];
__device__ float g_part[48 * D_DIM];
__device__ float g_u[D_DIM], g_w1[D_DIM], g_w2[D_DIM];
__device__ float g_v1[D_DIM], g_v2[D_DIM], g_v3[D_DIM], g_r[D_DIM];
__device__ float g_t[N_TOK], g_y[D_DIM];
__device__ float g_sc[2];
// tile flags: [0,256) G, [256,512) T1, [512,768) T2, [768,1024) P
__device__ int g_flags[1024];
// vec-stage counters: 0:A 1:B 2:C 3:D 4:E 5:F
__device__ int g_vcnt[8];

// ---------------- helpers ----------------
__device__ __forceinline__ uint32_t s2u(const void* p) {
    uint32_t a;
    asm("{ .reg .u64 t; cvta.to.shared.u64 t, %1; cvt.u32.u64 %0, t; }" : "=r"(a) : "l"(p));
    return a;
}
__device__ __forceinline__ void cp16(uint32_t dst, const void* src) {
    asm volatile("cp.async.cg.shared.global [%0], [%1], 16;" :: "r"(dst), "l"(src) : "memory");
}
__device__ __forceinline__ void cp_commit() {
    asm volatile("cp.async.commit_group;" ::: "memory");
}
template<int N>
__device__ __forceinline__ void cp_wait() {
    asm volatile("cp.async.wait_group %0;" :: "n"(N) : "memory");
}
__device__ __forceinline__ void ldsm4(uint32_t* r, uint32_t addr) {
    asm volatile("ldmatrix.sync.aligned.m8n8.x4.shared.b16 {%0,%1,%2,%3}, [%4];"
                 : "=r"(r[0]), "=r"(r[1]), "=r"(r[2]), "=r"(r[3]) : "r"(addr));
}
__device__ __forceinline__ void mma16816(float* d, const uint32_t* a, uint32_t b0, uint32_t b1) {
    asm volatile(
        "mma.sync.aligned.m16n8k16.row.col.f32.f16.f16.f32 "
        "{%0,%1,%2,%3}, {%4,%5,%6,%7}, {%8,%9}, {%0,%1,%2,%3};"
        : "+f"(d[0]), "+f"(d[1]), "+f"(d[2]), "+f"(d[3])
        : "r"(a[0]), "r"(a[1]), "r"(a[2]), "r"(a[3]), "r"(b0), "r"(b1));
}
__device__ __forceinline__ void wait_kblk(volatile int* wA, volatile int* wB, int sB,
                                          int kb, int tid) {
    if (tid == 0) {
        if (wA) while (wA[kb] == 0) __nanosleep(128);
        while (wB[kb * sB] == 0) __nanosleep(128);
        __threadfence();
    }
    __syncthreads();
}
__device__ __forceinline__ void vwait(volatile int* cnt, int target) {
    if (threadIdx.x == 0) {
        while (*cnt < target) __nanosleep(256);
        __threadfence();
    }
    __syncthreads();
}
__device__ __forceinline__ void vdone(int* cnt) {
    __threadfence();
    __syncthreads();
    if (threadIdx.x == 0) atomicAdd(cnt, 1);
}

// ---------------- pure fp16 HMMA GEMM body (single pass) ----------------
// C[m,n] = alpha * sum_k Ah[m,k] * Bh[n,k]
// mode 0 NORM : Ch[m*Ntot+n] = hi
// mode 1 SYM  : hi, both mirror positions
// mode 2 TRANS: Ch[n*Mtot+m] = hi(val + cA[m]cB[n] + cC[m]cD[n])
// mode 3 FINAL: Cf[m*Ntot+n] = val*alpha + biascol[n]   (fp32)
// wB != null => progressive waits per 128-wide K-block (wA optional, stride 1).
#define PLANE_B 10240
#define STAGE_B 20480
static const int SMEM_DYN = 2 * STAGE_B;

__device__ __forceinline__ void gemm_body(
    const __half* __restrict__ Ah, const __half* __restrict__ Bh,
    __half* Ch, float* Cf,
    const float* cA, const float* cB, const float* cC, const float* cD,
    const float* biascol,
    int bm0, int bn0, int Mtot, int Ntot, int Kd, float alpha, int mode,
    volatile int* wA, volatile int* wB, int sB,
    char* dyn)
{
    const uint32_t su = s2u(dyn);
    const int tid  = threadIdx.x;
    const int wid  = tid >> 5, lane = tid & 31;
    const int wm0  = (wid & 1) * 64;
    const int wn0  = (wid >> 1) * 32;

    // cp.async schedule: 1024 16B transfers / 256 threads = 4 each (plane 0:A, 1:B)
    const __half* gsrc[4];
    uint32_t doff[4];
    #pragma unroll
    for (int i = 0; i < 4; ++i) {
        int idx   = i * 256 + tid;
        int plane = idx >> 9;
        int row   = (idx >> 2) & 127;
        int seg   = idx & 3;
        const __half* base = (plane == 0) ? Ah : Bh;
        int grow = (plane == 0 ? bm0 : bn0) + row;
        gsrc[i] = base + (size_t)grow * Kd + seg * 8;
        doff[i] = (uint32_t)(plane * PLANE_B + row * 80 + seg * 16);
    }

    const int NC = Kd / 32;
    if (wB) wait_kblk(wA, wB, sB, 0, tid);
    #pragma unroll
    for (int i = 0; i < 4; ++i) cp16(su + doff[i], gsrc[i]);
    cp_commit();

    float acc[4][4][4];
    #pragma unroll
    for (int im = 0; im < 4; ++im)
        #pragma unroll
        for (int in = 0; in < 4; ++in)
            #pragma unroll
            for (int j = 0; j < 4; ++j) acc[im][in][j] = 0.0f;

    const int a_rl = ((lane >> 3) & 1) * 8 + (lane & 7);
    const int a_ch = ((lane >> 4) & 1) * 16;
    const int b_rl = lane;

    for (int c = 0; c < NC; ++c) {
        cp_wait<0>();
        __syncthreads();
        if (c + 1 < NC) {
            if (wB && (((c + 1) & 3) == 0))
                wait_kblk(wA, wB, sB, (c + 1) >> 2, tid);
            const uint32_t sd = su + ((c + 1) & 1) * STAGE_B;
            const size_t koff = (size_t)(c + 1) * 32;
            #pragma unroll
            for (int i = 0; i < 4; ++i) cp16(sd + doff[i], gsrc[i] + koff);
            cp_commit();
        }
        const uint32_t sb = su + (c & 1) * STAGE_B;
        const uint32_t aBase = sb + (wm0 + a_rl) * 80 + a_ch;
        const uint32_t bBase = sb + (wn0 + b_rl) * 80 + PLANE_B;

        #pragma unroll
        for (int kk = 0; kk < 2; ++kk) {
            const uint32_t kO = kk * 32;
            uint32_t a[4][4], b0[4], b1[4];
            ldsm4(b0, bBase + kO);
            ldsm4(b1, bBase + kO + 16);
            #pragma unroll
            for (int im = 0; im < 4; ++im)
                ldsm4(a[im], aBase + im * (16 * 80) + kO);
            #pragma unroll
            for (int im = 0; im < 4; ++im)
                #pragma unroll
                for (int in = 0; in < 4; ++in)
                    mma16816(acc[im][in], a[im], b0[in], b1[in]);
        }
    }

    // ---- epilogue ----
    const int mbase = bm0 + wm0 + (lane >> 2);
    const int nbase = bn0 + wn0 + (lane & 3) * 2;
    #pragma unroll
    for (int im = 0; im < 4; ++im) {
        #pragma unroll
        for (int in = 0; in < 4; ++in) {
            const float* d = acc[im][in];
            const int n0 = nbase + in * 8;
            if (mode == 3) {
                const int m0 = mbase + im * 16;
                float2 v0, v1;
                v0.x = d[0] * alpha + biascol[n0];
                v0.y = d[1] * alpha + biascol[n0 + 1];
                v1.x = d[2] * alpha + biascol[n0];
                v1.y = d[3] * alpha + biascol[n0 + 1];
                *(float2*)(Cf + (size_t)m0 * Ntot + n0)       = v0;
                *(float2*)(Cf + (size_t)(m0 + 8) * Ntot + n0) = v1;
            } else {
                #pragma unroll
                for (int j = 0; j < 4; ++j) {
                    const int m = mbase + im * 16 + (j >> 1) * 8;
                    const int n = n0 + (j & 1);
                    float v = d[j] * alpha;
                    if (mode == 2) v += cA[m] * cB[n] + cC[m] * cD[n];
                    __half h = __float2half(v);
                    if (mode == 0) {
                        Ch[(size_t)m * Ntot + n] = h;
                    } else if (mode == 1) {
                        Ch[(size_t)m * Ntot + n] = h;
                        Ch[(size_t)n * Ntot + m] = h;
                    } else {
                        Ch[(size_t)n * Mtot + m] = h;
                    }
                }
            }
        }
    }
}

__device__ __forceinline__ void set_flags(int f0, int f1) {
    __threadfence();
    __syncthreads();
    if (threadIdx.x == 0) {
        atomicExch(g_flags + f0, 1);
        if (f1 >= 0) atomicExch(g_flags + f1, 1);
    }
}

// ---------------- vec chain inside mega: idx in [0,1002) ----------------
__device__ void vec_work(int idx,
                         const float* x, const float* Wq, const float* bq,
                         const float* Wk, const float* bk,
                         const float* Wv, const float* bv, float sscale)
{
    const int tid = threadIdx.x;
    if (idx < 384) {
        int dblk = idx & 7, c = (idx >> 3) & 15, z = idx >> 7;
        const float* W = (z == 0) ? x : (z == 1) ? Wk : Wq;
        const float* v = (z == 0) ? nullptr : (z == 1) ? bq : bk;
        const int R = (z == 0) ? N_TOK : D_DIM;
        const int chunk = R / 16;
        const int d = dblk * 256 + tid;
        float s = 0.0f;
        for (int r = c * chunk; r < (c + 1) * chunk; ++r)
            s = fmaf(v ? v[r] : 1.0f, W[(size_t)r * D_DIM + d], s);
        g_part[(size_t)(z * 16 + c) * D_DIM + d] = s;
        vdone(g_vcnt + 0);
    } else if (idx < 408) {
        vwait(g_vcnt + 0, 384);
        int i2 = idx - 384, dblk = i2 & 7, z = i2 >> 3;
        const int d = dblk * 256 + tid;
        float s = 0.0f;
        #pragma unroll
        for (int c = 0; c < 16; ++c) s += g_part[(size_t)(z * 16 + c) * D_DIM + d];
        if (z == 0) g_u[d] = s;
        else if (z == 1) g_w1[d] = s;
        else g_v2[d] = s * sscale;
        vdone(g_vcnt + 1);
    } else if (idx < 666) {
        vwait(g_vcnt + 1, 24);
        int i2 = idx - 408;
        if (i2 < 256) {
            const int lane = tid & 31, w = tid >> 5;
            const float* W; const float* v; float* outv; int rbase; bool addb = false;
            if (i2 < 128)      { W = x;  v = g_w1; outv = g_t;  rbase = i2 * 32; }
            else if (i2 < 192) { W = Wk; v = g_u;  outv = g_y;  rbase = (i2 - 128) * 32; }
            else               { W = Wv; v = g_u;  outv = g_v3; rbase = (i2 - 192) * 32; addb = true; }
            for (int rr = 0; rr < 4; ++rr) {
                const int i = rbase + w * 4 + rr;
                float s = 0.0f;
                for (int j = lane; j < D_DIM; j += 32)
                    s = fmaf(W[(size_t)i * D_DIM + j], v[j], s);
                #pragma unroll
                for (int o = 16; o; o >>= 1) s += __shfl_xor_sync(0xFFFFFFFFu, s, o);
                if (lane == 0) outv[i] = addb ? s + (float)N_TOK * bv[i] : s;
            }
        } else {
            __shared__ float red[256];
            float s = 0.0f;
            if (i2 == 256) for (int i = tid; i < D_DIM; i += 256) s = fmaf(g_u[i], g_w1[i], s);
            else           for (int i = tid; i < D_DIM; i += 256) s = fmaf(bk[i], bq[i], s);
            red[tid] = s;
            __syncthreads();
            for (int o = 128; o; o >>= 1) { if (tid < o) red[tid] += red[tid + o]; __syncthreads(); }
            if (tid == 0) g_sc[i2 - 256] = red[0];
        }
        vdone(g_vcnt + 2);
    } else if (idx < 922) {
        vwait(g_vcnt + 2, 258);
        int i2 = idx - 666, dblk = i2 & 7, c = (i2 >> 3) & 15, z = i2 >> 7;
        const float* W = z ? Wq : x;
        const float* v = z ? g_y : g_t;
        const int R = z ? D_DIM : N_TOK;
        const int chunk = R / 16;
        const int d = dblk * 256 + tid;
        float s = 0.0f;
        for (int r = c * chunk; r < (c + 1) * chunk; ++r)
            s = fmaf(v[r], W[(size_t)r * D_DIM + d], s);
        g_part[(size_t)(z * 16 + c) * D_DIM + d] = s;
        vdone(g_vcnt + 3);
    } else if (idx < 938) {
        vwait(g_vcnt + 3, 256);
        int i2 = idx - 922, dblk = i2 & 7, z = i2 >> 3;
        const int d = dblk * 256 + tid;
        float s = 0.0f;
        #pragma unroll
        for (int c = 0; c < 16; ++c) s += g_part[(size_t)(z * 16 + c) * D_DIM + d];
        if (z == 0) g_w2[d] = s;
        else g_v1[d] = s * sscale;
        vdone(g_vcnt + 4);
    } else {
        vwait(g_vcnt + 4, 16);
        int i2 = idx - 938;
        const int lane = tid & 31, w = tid >> 5;
        for (int rr = 0; rr < 4; ++rr) {
            const int i = i2 * 32 + w * 4 + rr;
            float acc = 0.0f;
            for (int j = lane; j < D_DIM; j += 32)
                acc = fmaf(Wv[(size_t)i * D_DIM + j], g_w2[j], acc);
            #pragma unroll
            for (int o = 16; o; o >>= 1) acc += __shfl_xor_sync(0xFFFFFFFFu, acc, o);
            if (lane == 0) g_r[i] = sscale * (acc + bv[i] * g_sc[0] + g_v3[i] * g_sc[1]);
        }
        vdone(g_vcnt + 5);
    }
}

// ---------------- MEGA: 5 GEMMs + vec chain, one launch ----------------
// [0,136)      G  = xT xT^T (sym)                 -> flags [0,256)
// [136,392)    T1 = Wq^T Wk                       -> flags [256,512)
// [392,1394)   vec chain (counters)
// [1394,1650)  T2 = T1 G    waits T1 row + G row  -> flags [512,768)
// [1650,1906)  P  = s T2 Wv^T + rank2 (trans)     waits T2 row + vecE -> flags [768,1024)
// [1906,2418)  out = x P + 1 r^T (fp32)           waits P(kb,j) + vecF
__global__ void __launch_bounds__(256, 2) mega(
    const float* __restrict__ x, const float* __restrict__ Wq, const float* __restrict__ bq,
    const float* __restrict__ Wk, const float* __restrict__ bk,
    const float* __restrict__ Wv, const float* __restrict__ bv,
    const __half* __restrict__ xTh,
    __half* __restrict__ gh,
    const __half* __restrict__ wqTh, const __half* __restrict__ wkTh,
    __half* __restrict__ t1h, __half* __restrict__ t2h,
    const __half* __restrict__ wvh,
    __half* __restrict__ pTh,
    const float* v1, const float* v2, const float* v3,
    const __half* __restrict__ xh,
    float* __restrict__ outp, const float* r, float s)
{
    extern __shared__ char dyn[];
    const int bid = blockIdx.x;

    if (bid < 136) {                        // G (symmetric)
        int idx = bid, by = 0;
        while (idx >= 16 - by) { idx -= 16 - by; ++by; }
        int bx = by + idx;
        gemm_body(xTh, xTh, gh, nullptr,
                  nullptr, nullptr, nullptr, nullptr, nullptr,
                  by * 128, bx * 128, D_DIM, D_DIM, N_TOK, 1.0f, 1,
                  nullptr, nullptr, 1, dyn);
        set_flags(by * 16 + bx, bx * 16 + by);
    } else if (bid < 392) {                 // T1
        int idx = bid - 136;
        gemm_body(wqTh, wkTh, t1h, nullptr,
                  nullptr, nullptr, nullptr, nullptr, nullptr,
                  (idx >> 4) * 128, (idx & 15) * 128, D_DIM, D_DIM, D_DIM, 1.0f, 0,
                  nullptr, nullptr, 1, dyn);
        set_flags(256 + idx, -1);
    } else if (bid < 1394) {                // vec chain
        vec_work(bid - 392, x, Wq, bq, Wk, bk, Wv, bv, s);
    } else if (bid < 1650) {                // T2 = T1 G
        int idx = bid - 1394;
        int m = idx >> 4, n = idx & 15;
        gemm_body(t1h, gh, t2h, nullptr,
                  nullptr, nullptr, nullptr, nullptr, nullptr,
                  m * 128, n * 128, D_DIM, D_DIM, D_DIM, 1.0f, 0,
                  g_flags + 256 + m * 16, g_flags + n * 16, 1, dyn);
        set_flags(512 + idx, -1);
    } else if (bid < 1906) {                // P (trans + rank2)
        int idx = bid - 1650;
        int a = idx >> 4, j = idx & 15;
        vwait(g_vcnt + 4, 16);              // v1/v2/v3 ready
        gemm_body(t2h, wvh, pTh, nullptr,
                  v1, bv, v2, v3, nullptr,
                  a * 128, j * 128, D_DIM, D_DIM, D_DIM, s, 2,
                  nullptr, g_flags + 512 + a * 16, 1, dyn);
        set_flags(768 + idx, -1);
    } else {                                // out (fp32)
        int idx = bid - 1906;
        int t = idx >> 4, j = idx & 15;
        vwait(g_vcnt + 5, 64);              // r ready
        gemm_body(xh, pTh, nullptr, outp,
                  nullptr, nullptr, nullptr, nullptr, r,
                  t * 128, j * 128, N_TOK, D_DIM, D_DIM, 1.0f, 3,
                  nullptr, g_flags + 768 + j, 16, dyn);
    }
}

// ---------------- preprocessing (one launch; bid 0 also zeroes flags) ----------------
__global__ void prep_all(const float* __restrict__ x,
                         __half* __restrict__ xh, __half* __restrict__ xth,
                         const float* __restrict__ Wq, __half* __restrict__ wqTh,
                         const float* __restrict__ Wk, __half* __restrict__ wkTh,
                         const float* __restrict__ Wv, __half* __restrict__ wvh)
{
    __shared__ float t[32][33];
    const int tx = threadIdx.x, ty = threadIdx.y;  // 32 x 8
    const int bid = blockIdx.x;
    const int tid = ty * 32 + tx;
    if (bid == 0) {
        for (int i = tid; i < 1024; i += 256) g_flags[i] = 0;
        if (tid < 8) g_vcnt[tid] = 0;
    }
    if (bid < 8192) {                       // x: straight hi + transposed hi
        int bx = (bid & 63) * 32, by = (bid >> 6) * 32;
        #pragma unroll
        for (int j = 0; j < 32; j += 8) {
            size_t gi = (size_t)(by + ty + j) * D_DIM + bx + tx;
            float v = x[gi];
            t[ty + j][tx] = v;
            xh[gi] = __float2half(v);
        }
        __syncthreads();
        #pragma unroll
        for (int j = 0; j < 32; j += 8) {
            size_t o = (size_t)(bx + ty + j) * N_TOK + by + tx;
            xth[o] = __float2half(t[tx][ty + j]);
        }
        return;
    }
    const int w = bid - 8192;
    const int z = w >> 12;
    const int rem = w & 4095;
    const int bx = (rem & 63) * 32, by = (rem >> 6) * 32;
    const float* in = (z == 0) ? Wq : (z == 1) ? Wk : Wv;
    if (z == 2) {                           // Wv: straight hi
        #pragma unroll
        for (int j = 0; j < 32; j += 8) {
            size_t gi = (size_t)(by + ty + j) * D_DIM + bx + tx;
            wvh[gi] = __float2half(in[gi]);
        }
        return;
    }
    __half* hi = (z == 0) ? wqTh : wkTh;    // transposed hi
    #pragma unroll
    for (int j = 0; j < 32; j += 8)
        t[ty + j][tx] = in[(size_t)(by + ty + j) * D_DIM + bx + tx];
    __syncthreads();
    #pragma unroll
    for (int j = 0; j < 32; j += 8) {
        size_t o = (size_t)(bx + ty + j) * D_DIM + by + tx;
        hi[o] = __float2half(t[tx][ty + j]);
    }
}

// ---------------- launcher ----------------
extern "C" void kernel_launch(void* const* d_in, const int* in_sizes, int n_in,
                              void* d_out, int out_size)
{
    const float* x  = (const float*)d_in[0];
    const float* Wq = (const float*)d_in[1];
    const float* bq = (const float*)d_in[2];
    const float* Wk = (const float*)d_in[3];
    const float* bk = (const float*)d_in[4];
    const float* Wv = (const float*)d_in[5];
    const float* bv = (const float*)d_in[6];
    float* out = (float*)d_out;

    __half *xT_hi, *x_hi, *wqT_hi, *wkT_hi, *wv_hi, *gh, *t1h, *t2h, *pTh;
    float *v1, *v2, *v3, *r;
    cudaGetSymbolAddress((void**)&xT_hi, g_xT_hi);
    cudaGetSymbolAddress((void**)&x_hi, g_x_hi);
    cudaGetSymbolAddress((void**)&wqT_hi, g_wqT_hi);
    cudaGetSymbolAddress((void**)&wkT_hi, g_wkT_hi);
    cudaGetSymbolAddress((void**)&wv_hi, g_wv_hi);
    cudaGetSymbolAddress((void**)&gh, g_g_hi);
    cudaGetSymbolAddress((void**)&t1h, g_t1_hi);
    cudaGetSymbolAddress((void**)&t2h, g_t2_hi);
    cudaGetSymbolAddress((void**)&pTh, g_pT_hi);
    cudaGetSymbolAddress((void**)&v1, g_v1);  cudaGetSymbolAddress((void**)&v2, g_v2);
    cudaGetSymbolAddress((void**)&v3, g_v3);  cudaGetSymbolAddress((void**)&r, g_r);

    cudaFuncSetAttribute(mega, cudaFuncAttributeMaxDynamicSharedMemorySize, SMEM_DYN);

    const float s = 1.0f / sqrtf((float)D_DIM);

    // prep (bid 0 zeroes flags/counters)
    prep_all<<<8192 + 3 * 4096, dim3(32, 8)>>>(x, x_hi, xT_hi,
                                               Wq, wqT_hi,
                                               Wk, wkT_hi,
                                               Wv, wv_hi);
    // everything else in one DAG launch
    mega<<<2418, 256, SMEM_DYN>>>(x, Wq, bq, Wk, bk, Wv, bv,
                                  xT_hi, gh,
                                  wqT_hi, wkT_hi,
                                  t1h, t2h,
                                  wv_hi, pTh,
                                  v1, v2, v3,
                                  x_hi, out, r, s);
}